// round 2
// baseline (speedup 1.0000x reference)
#include <cuda_runtime.h>
#include <cuda_bf16.h>
#include <math.h>

#define NN 100000
#define EE 1600000

// ---------------- static scratch (no allocations allowed) ----------------
__device__ float g_bufA[(size_t)NN * 256];
__device__ float g_bufB[(size_t)NN * 256];
__device__ float g_bufC[(size_t)NN * 256];
__device__ float g_sout[NN];
__device__ float g_sin[NN];
__device__ int   g_cnt_out[NN];
__device__ int   g_cnt_in[NN];
__device__ int   g_cursor[NN];
__device__ int   g_row_ptr[NN + 1];
__device__ int   g_csr[EE];

// ---------------- graph preprocessing ----------------
__global__ void k_zero_counts() {
    int i = blockIdx.x * blockDim.x + threadIdx.x;
    if (i < NN) { g_cnt_out[i] = 0; g_cnt_in[i] = 0; g_cursor[i] = 0; }
}

__global__ void k_hist(const int* __restrict__ src, const int* __restrict__ dst) {
    int stride = gridDim.x * blockDim.x;
    for (int i = blockIdx.x * blockDim.x + threadIdx.x; i < EE; i += stride) {
        atomicAdd(&g_cnt_out[src[i]], 1);
        atomicAdd(&g_cnt_in[dst[i]], 1);
    }
}

// single-block chunked inclusive scan of g_cnt_in -> g_row_ptr
__global__ void k_scan() {
    __shared__ int sh[1024];
    __shared__ int carry;
    int t = threadIdx.x;
    if (t == 0) carry = 0;
    __syncthreads();
    for (int base = 0; base < NN; base += 1024) {
        int idx = base + t;
        int v = (idx < NN) ? g_cnt_in[idx] : 0;
        sh[t] = v;
        __syncthreads();
        for (int off = 1; off < 1024; off <<= 1) {
            int add = (t >= off) ? sh[t - off] : 0;
            __syncthreads();
            sh[t] += add;
            __syncthreads();
        }
        if (idx < NN) g_row_ptr[idx + 1] = carry + sh[t];
        int total = sh[1023];
        __syncthreads();
        if (t == 0) carry += total;
        __syncthreads();
    }
    if (t == 0) g_row_ptr[0] = 0;
}

__global__ void k_fill(const int* __restrict__ src, const int* __restrict__ dst) {
    int stride = gridDim.x * blockDim.x;
    for (int i = blockIdx.x * blockDim.x + threadIdx.x; i < EE; i += stride) {
        int d = dst[i];
        int pos = g_row_ptr[d] + atomicAdd(&g_cursor[d], 1);
        g_csr[pos] = src[i];
    }
}

__global__ void k_scales() {
    int i = blockIdx.x * blockDim.x + threadIdx.x;
    if (i < NN) {
        g_sout[i] = rsqrtf(fmaxf((float)g_cnt_out[i], 1.f));
        g_sin[i]  = rsqrtf(fmaxf((float)g_cnt_in[i], 1.f));
    }
}

// ---------------- aggregation: out[n] = sum_{e in CSR(n)} x[src_e] * (sscale[src_e] | 1) ----------------
template <int D>
__global__ void k_agg(const float* __restrict__ x, const float* __restrict__ sscale,
                      float* __restrict__ out) {
    int warp = (blockIdx.x * blockDim.x + threadIdx.x) >> 5;
    int lane = threadIdx.x & 31;
    if (warp >= NN) return;
    constexpr int V = D / 128;  // float4's per lane
    float4 acc[V];
#pragma unroll
    for (int v = 0; v < V; v++) acc[v] = make_float4(0.f, 0.f, 0.f, 0.f);
    int s0 = g_row_ptr[warp], s1 = g_row_ptr[warp + 1];
    const float4* xb = (const float4*)x;
    for (int e = s0; e < s1; e++) {
        int s = g_csr[e];
        float w = sscale ? sscale[s] : 1.f;
        const float4* xp = xb + (size_t)s * (D / 4);
#pragma unroll
        for (int v = 0; v < V; v++) {
            float4 t = xp[lane + 32 * v];
            acc[v].x += t.x * w; acc[v].y += t.y * w;
            acc[v].z += t.z * w; acc[v].w += t.w * w;
        }
    }
    float4* ob = (float4*)out + (size_t)warp * (D / 4);
#pragma unroll
    for (int v = 0; v < V; v++) ob[lane + 32 * v] = acc[v];
}

// ---------------- SGEMM: C = act(A[M,K] @ W[K,Nn] * rowscale[m] + bias[n]) ----------------
// BM=128, BN=64, BK=16, 256 threads, 8x4 per thread
template <int ACT>  // 0 = none, 1 = tanh
__global__ __launch_bounds__(256)
void k_gemm(const float* __restrict__ A, const float* __restrict__ W,
            float* __restrict__ C, int M, int K, int Nn,
            const float* __restrict__ rowscale, const float* __restrict__ bias) {
    constexpr int BM = 128, BN = 64, BK = 16;
    __shared__ float As[BK][BM];
    __shared__ float Bs[BK][BN];
    int tid = threadIdx.x;
    int tx = tid & 15, ty = tid >> 4;
    int bm = blockIdx.x * BM, bn = blockIdx.y * BN;
    float acc[8][4];
#pragma unroll
    for (int i = 0; i < 8; i++)
#pragma unroll
        for (int j = 0; j < 4; j++) acc[i][j] = 0.f;

    for (int kt = 0; kt < K; kt += BK) {
        // load A tile (128x16) -> As transposed
#pragma unroll
        for (int i = 0; i < 2; i++) {
            int fid = tid + i * 256;
            int row = fid >> 2, c4 = (fid & 3) * 4;
            int gm = bm + row;
            float4 v = make_float4(0.f, 0.f, 0.f, 0.f);
            if (gm < M) v = *(const float4*)&A[(size_t)gm * K + kt + c4];
            As[c4 + 0][row] = v.x; As[c4 + 1][row] = v.y;
            As[c4 + 2][row] = v.z; As[c4 + 3][row] = v.w;
        }
        // load W tile (16x64)
        {
            int row = tid >> 4, c4 = (tid & 15) * 4;
            *(float4*)&Bs[row][c4] = *(const float4*)&W[(size_t)(kt + row) * Nn + bn + c4];
        }
        __syncthreads();
#pragma unroll
        for (int kk = 0; kk < BK; kk++) {
            float4 b4 = *(float4*)&Bs[kk][tx * 4];
            float4 a0 = *(float4*)&As[kk][ty * 8];
            float4 a1 = *(float4*)&As[kk][ty * 8 + 4];
            float a[8] = {a0.x, a0.y, a0.z, a0.w, a1.x, a1.y, a1.z, a1.w};
            float b[4] = {b4.x, b4.y, b4.z, b4.w};
#pragma unroll
            for (int i = 0; i < 8; i++)
#pragma unroll
                for (int j = 0; j < 4; j++) acc[i][j] += a[i] * b[j];
        }
        __syncthreads();
    }

    float bb[4] = {0.f, 0.f, 0.f, 0.f};
    if (bias) {
        float4 t = *(const float4*)&bias[bn + tx * 4];
        bb[0] = t.x; bb[1] = t.y; bb[2] = t.z; bb[3] = t.w;
    }
#pragma unroll
    for (int i = 0; i < 8; i++) {
        int gm = bm + ty * 8 + i;
        if (gm >= M) break;
        float rs = rowscale ? rowscale[gm] : 1.f;
        float4 o;
        o.x = acc[i][0] * rs + bb[0];
        o.y = acc[i][1] * rs + bb[1];
        o.z = acc[i][2] * rs + bb[2];
        o.w = acc[i][3] * rs + bb[3];
        if (ACT == 1) { o.x = tanhf(o.x); o.y = tanhf(o.y); o.z = tanhf(o.z); o.w = tanhf(o.w); }
        *(float4*)&C[(size_t)gm * Nn + bn + tx * 4] = o;
    }
}

// ---------------- row softmax over D=128, optional rowscale+bias before ----------------
__global__ void k_softmax128(const float* __restrict__ in, float* __restrict__ out,
                             const float* __restrict__ rowscale, const float* __restrict__ bias) {
    int warp = (blockIdx.x * blockDim.x + threadIdx.x) >> 5;
    int lane = threadIdx.x & 31;
    if (warp >= NN) return;
    float4 v = ((const float4*)in)[(size_t)warp * 32 + lane];
    float rs = rowscale ? rowscale[warp] : 1.f;
    float4 b = make_float4(0.f, 0.f, 0.f, 0.f);
    if (bias) b = ((const float4*)bias)[lane];
    v.x = v.x * rs + b.x; v.y = v.y * rs + b.y;
    v.z = v.z * rs + b.z; v.w = v.w * rs + b.w;
    float m = fmaxf(fmaxf(v.x, v.y), fmaxf(v.z, v.w));
#pragma unroll
    for (int off = 16; off > 0; off >>= 1) m = fmaxf(m, __shfl_xor_sync(0xffffffffu, m, off));
    v.x = expf(v.x - m); v.y = expf(v.y - m);
    v.z = expf(v.z - m); v.w = expf(v.w - m);
    float s = v.x + v.y + v.z + v.w;
#pragma unroll
    for (int off = 16; off > 0; off >>= 1) s += __shfl_xor_sync(0xffffffffu, s, off);
    float inv = 1.f / s;
    v.x *= inv; v.y *= inv; v.z *= inv; v.w *= inv;
    ((float4*)out)[(size_t)warp * 32 + lane] = v;
}

// ---------------- launcher ----------------
extern "C" void kernel_launch(void* const* d_in, const int* in_sizes, int n_in,
                              void* d_out, int out_size) {
    const float* in_feat = (const float*)d_in[0];
    const int*   src     = (const int*)d_in[1];
    const int*   dst     = (const int*)d_in[2];
    const float* Wc0 = (const float*)d_in[3];
    const float* bc0 = (const float*)d_in[4];
    const float* Wc1 = (const float*)d_in[5];
    const float* bc1 = (const float*)d_in[6];
    const float* Wc2 = (const float*)d_in[7];
    const float* bc2 = (const float*)d_in[8];
    const float* Wr0 = (const float*)d_in[9];
    const float* br0 = (const float*)d_in[10];
    const float* Wr1 = (const float*)d_in[11];
    const float* br1 = (const float*)d_in[12];
    const float* Wr2 = (const float*)d_in[13];
    const float* br2 = (const float*)d_in[14];
    float* out = (float*)d_out;

    float *bufA, *bufB, *bufC, *sout, *sin;
    cudaGetSymbolAddress((void**)&bufA, g_bufA);
    cudaGetSymbolAddress((void**)&bufB, g_bufB);
    cudaGetSymbolAddress((void**)&bufC, g_bufC);
    cudaGetSymbolAddress((void**)&sout, g_sout);
    cudaGetSymbolAddress((void**)&sin,  g_sin);

    const int M = NN;
    dim3 g_n((NN + 255) / 256);
    dim3 g_e(4096);
    dim3 g_w((NN * 32 + 255) / 256);         // one warp per node, 256-thread blocks
    dim3 gg((M + 127) / 128, 0);

    // graph preprocessing
    k_zero_counts<<<g_n, 256>>>();
    k_hist<<<g_e, 256>>>(src, dst);
    k_scan<<<1, 1024>>>();
    k_fill<<<g_e, 256>>>(src, dst);
    k_scales<<<g_n, 256>>>();

    // conv1: aggregate(in_feat * s_out) -> GEMM 128->256, *s_in + bc0, tanh
    k_agg<128><<<g_w, 256>>>(in_feat, sout, bufA);
    k_gemm<1><<<dim3((M + 127) / 128, 4), 256>>>(bufA, Wc0, bufB, M, 128, 256, sin, bc0);

    // conv2: aggregate(h1 * s_out) -> GEMM 256->256, *s_in + bc1, tanh
    k_agg<256><<<g_w, 256>>>(bufB, sout, bufC);
    k_gemm<1><<<dim3((M + 127) / 128, 4), 256>>>(bufC, Wc1, bufA, M, 256, 256, sin, bc1);

    // conv3: GEMM 256->128 with rowscale s_out (transform first), aggregate, softmax(*s_in + bc2)
    k_gemm<0><<<dim3((M + 127) / 128, 2), 256>>>(bufA, Wc2, bufB, M, 256, 128, sout, nullptr);
    k_agg<128><<<g_w, 256>>>(bufB, nullptr, bufC);
    k_softmax128<<<g_w, 256>>>(bufC, out, sin, bc2);

    // MLP on h (h lives in out[0 : N*128])
    k_gemm<1><<<dim3((M + 127) / 128, 4), 256>>>(out, Wr0, bufA, M, 128, 256, nullptr, br0);
    k_gemm<1><<<dim3((M + 127) / 128, 4), 256>>>(bufA, Wr1, bufB, M, 256, 256, nullptr, br1);
    k_gemm<0><<<dim3((M + 127) / 128, 2), 256>>>(bufB, Wr2, bufC, M, 256, 128, nullptr, br2);
    k_softmax128<<<g_w, 256>>>(bufC, out + (size_t)M * 128, nullptr, nullptr);
}

// round 5
// speedup vs baseline: 1.6219x; 1.6219x over previous
#include <cuda_runtime.h>
#include <cuda_bf16.h>
#include <math.h>
#include <stdint.h>

#define NN 100000
#define EE 1600000

// ---------------- static scratch ----------------
__device__ float g_bufA[(size_t)NN * 256];
__device__ float g_bufB[(size_t)NN * 256];
__device__ float g_bufC[(size_t)NN * 256];
__device__ float g_sout[NN];
__device__ float g_sin[NN];
__device__ int   g_cnt_out[NN];
__device__ int   g_cnt_in[NN];
__device__ int   g_cursor[NN];
__device__ int   g_row_ptr[NN + 1];
__device__ int   g_csr[EE];
__device__ float g_wt[6][65536];   // transposed weights [N,K] row-major

// ---------------- graph preprocessing ----------------
__global__ void k_zero_counts() {
    int i = blockIdx.x * blockDim.x + threadIdx.x;
    if (i < NN) { g_cnt_out[i] = 0; g_cnt_in[i] = 0; g_cursor[i] = 0; }
}
__global__ void k_hist(const int* __restrict__ src, const int* __restrict__ dst) {
    int stride = gridDim.x * blockDim.x;
    for (int i = blockIdx.x * blockDim.x + threadIdx.x; i < EE; i += stride) {
        atomicAdd(&g_cnt_out[src[i]], 1);
        atomicAdd(&g_cnt_in[dst[i]], 1);
    }
}
__global__ void k_scan() {
    __shared__ int sh[1024];
    __shared__ int carry;
    int t = threadIdx.x;
    if (t == 0) carry = 0;
    __syncthreads();
    for (int base = 0; base < NN; base += 1024) {
        int idx = base + t;
        int v = (idx < NN) ? g_cnt_in[idx] : 0;
        sh[t] = v;
        __syncthreads();
        for (int off = 1; off < 1024; off <<= 1) {
            int add = (t >= off) ? sh[t - off] : 0;
            __syncthreads();
            sh[t] += add;
            __syncthreads();
        }
        if (idx < NN) g_row_ptr[idx + 1] = carry + sh[t];
        int total = sh[1023];
        __syncthreads();
        if (t == 0) carry += total;
        __syncthreads();
    }
    if (t == 0) g_row_ptr[0] = 0;
}
__global__ void k_fill(const int* __restrict__ src, const int* __restrict__ dst) {
    int stride = gridDim.x * blockDim.x;
    for (int i = blockIdx.x * blockDim.x + threadIdx.x; i < EE; i += stride) {
        int d = dst[i];
        int pos = g_row_ptr[d] + atomicAdd(&g_cursor[d], 1);
        g_csr[pos] = src[i];
    }
}
__global__ void k_scales() {
    int i = blockIdx.x * blockDim.x + threadIdx.x;
    if (i < NN) {
        g_sout[i] = rsqrtf(fmaxf((float)g_cnt_out[i], 1.f));
        g_sin[i]  = rsqrtf(fmaxf((float)g_cnt_in[i], 1.f));
    }
}

// weight transpose: WT[n*K+k] = W[k*N+n]
__global__ void k_transpose(const float* __restrict__ W, float* __restrict__ WT, int K, int N) {
    __shared__ float t[32][33];
    int k0 = blockIdx.x * 32, n0 = blockIdx.y * 32;
    int x = threadIdx.x, y = threadIdx.y;
    for (int i = 0; i < 32; i += 8) {
        int k = k0 + y + i, n = n0 + x;
        t[y + i][x] = (k < K && n < N) ? W[(size_t)k * N + n] : 0.f;
    }
    __syncthreads();
    for (int i = 0; i < 32; i += 8) {
        int n = n0 + y + i, k = k0 + x;
        if (n < N && k < K) WT[(size_t)n * K + k] = t[x][y + i];
    }
}

// ---------------- aggregation ----------------
template <int D>
__global__ void k_agg(const float* __restrict__ x, const float* __restrict__ sscale,
                      float* __restrict__ out) {
    int warp = (blockIdx.x * blockDim.x + threadIdx.x) >> 5;
    int lane = threadIdx.x & 31;
    if (warp >= NN) return;
    constexpr int V = D / 128;
    float4 acc[V];
#pragma unroll
    for (int v = 0; v < V; v++) acc[v] = make_float4(0.f, 0.f, 0.f, 0.f);
    int s0 = g_row_ptr[warp], s1 = g_row_ptr[warp + 1];
    const float4* xb = (const float4*)x;
    for (int e = s0; e < s1; e++) {
        int s = g_csr[e];
        float w = sscale ? sscale[s] : 1.f;
        const float4* xp = xb + (size_t)s * (D / 4);
#pragma unroll
        for (int v = 0; v < V; v++) {
            float4 t = xp[lane + 32 * v];
            acc[v].x += t.x * w; acc[v].y += t.y * w;
            acc[v].z += t.z * w; acc[v].w += t.w * w;
        }
    }
    float4* ob = (float4*)out + (size_t)warp * (D / 4);
#pragma unroll
    for (int v = 0; v < V; v++) ob[lane + 32 * v] = acc[v];
}

// ---------------- tf32 tensor-core GEMM via mma.sync ----------------
__device__ __forceinline__ float tf32r(float x) {
    uint32_t u;
    asm("cvt.rna.tf32.f32 %0, %1;" : "=r"(u) : "f"(x));
    return __uint_as_float(u);
}
__device__ __forceinline__ void mma_tf32(float* d, const uint32_t* a, const uint32_t* b) {
    asm volatile(
        "mma.sync.aligned.m16n8k8.row.col.f32.tf32.tf32.f32 "
        "{%0,%1,%2,%3}, {%4,%5,%6,%7}, {%8,%9}, {%0,%1,%2,%3};"
        : "+f"(d[0]), "+f"(d[1]), "+f"(d[2]), "+f"(d[3])
        : "r"(a[0]), "r"(a[1]), "r"(a[2]), "r"(a[3]), "r"(b[0]), "r"(b[1]));
}

// C[M,N] = act( (A[M,K] @ WT[N,K]^T) * rowscale[m] + bias[n] )
// CTA tile 128x64, BK=32, 256 threads (8 warps, 4x2), warp tile 32x32.
template <int ACT>
__global__ void __launch_bounds__(256)
k_gemm_mma(const float* __restrict__ A, const float* __restrict__ WT,
           float* __restrict__ C, int M, int K, int N,
           const float* __restrict__ rowscale, const float* __restrict__ bias) {
    __shared__ float As[128 * 36];   // stride 36: conflict-free fragment loads
    __shared__ float Bs[64 * 36];
    int tid = threadIdx.x;
    int warp = tid >> 5, lane = tid & 31;
    int g = lane >> 2, t = lane & 3;          // groupID / threadID-in-group
    int wm = warp >> 1, wn = warp & 1;
    int bm = blockIdx.x * 128, bn = blockIdx.y * 64;

    float acc[2][4][4];
#pragma unroll
    for (int mt = 0; mt < 2; mt++)
#pragma unroll
        for (int nt = 0; nt < 4; nt++)
#pragma unroll
            for (int j = 0; j < 4; j++) acc[mt][nt][j] = 0.f;

    for (int kt = 0; kt < K; kt += 32) {
        // A tile: 128 rows x 32 k = 1024 float4, 4 per thread
#pragma unroll
        for (int i = 0; i < 4; i++) {
            int s = tid + i * 256;
            int row = s >> 3, q = s & 7;
            int gm = bm + row;
            float4 v = make_float4(0.f, 0.f, 0.f, 0.f);
            if (gm < M) v = *(const float4*)(A + (size_t)gm * K + kt + q * 4);
            v.x = tf32r(v.x); v.y = tf32r(v.y); v.z = tf32r(v.z); v.w = tf32r(v.w);
            *(float4*)(As + row * 36 + q * 4) = v;
        }
        // B tile: 64 n-rows x 32 k = 512 float4, 2 per thread
#pragma unroll
        for (int i = 0; i < 2; i++) {
            int s = tid + i * 256;
            int row = s >> 3, q = s & 7;
            float4 v = *(const float4*)(WT + (size_t)(bn + row) * K + kt + q * 4);
            v.x = tf32r(v.x); v.y = tf32r(v.y); v.z = tf32r(v.z); v.w = tf32r(v.w);
            *(float4*)(Bs + row * 36 + q * 4) = v;
        }
        __syncthreads();

        const uint32_t* Asu = (const uint32_t*)As;
        const uint32_t* Bsu = (const uint32_t*)Bs;
#pragma unroll
        for (int k8 = 0; k8 < 4; k8++) {
            int kc = k8 * 8;
            uint32_t a[2][4];
#pragma unroll
            for (int mt = 0; mt < 2; mt++) {
                int r0 = (wm * 32 + mt * 16 + g) * 36 + kc + t;
                a[mt][0] = Asu[r0];
                a[mt][1] = Asu[r0 + 8 * 36];
                a[mt][2] = Asu[r0 + 4];
                a[mt][3] = Asu[r0 + 8 * 36 + 4];
            }
            uint32_t b[4][2];
#pragma unroll
            for (int nt = 0; nt < 4; nt++) {
                int r0 = (wn * 32 + nt * 8 + g) * 36 + kc + t;
                b[nt][0] = Bsu[r0];
                b[nt][1] = Bsu[r0 + 4];
            }
#pragma unroll
            for (int mt = 0; mt < 2; mt++)
#pragma unroll
                for (int nt = 0; nt < 4; nt++)
                    mma_tf32(acc[mt][nt], a[mt], b[nt]);
        }
        __syncthreads();
    }

    // epilogue
    float2 bv[4];
#pragma unroll
    for (int nt = 0; nt < 4; nt++) {
        if (bias) bv[nt] = *(const float2*)(bias + bn + wn * 32 + nt * 8 + 2 * t);
        else bv[nt] = make_float2(0.f, 0.f);
    }
#pragma unroll
    for (int mt = 0; mt < 2; mt++) {
#pragma unroll
        for (int h = 0; h < 2; h++) {
            int gm = bm + wm * 32 + mt * 16 + h * 8 + g;
            if (gm >= M) continue;
            float rs = rowscale ? rowscale[gm] : 1.f;
#pragma unroll
            for (int nt = 0; nt < 4; nt++) {
                float2 o;
                o.x = acc[mt][nt][2 * h]     * rs + bv[nt].x;
                o.y = acc[mt][nt][2 * h + 1] * rs + bv[nt].y;
                if (ACT == 1) { o.x = tanhf(o.x); o.y = tanhf(o.y); }
                *(float2*)(C + (size_t)gm * N + bn + wn * 32 + nt * 8 + 2 * t) = o;
            }
        }
    }
}

// ---------------- row softmax over D=128 ----------------
__global__ void k_softmax128(const float* __restrict__ in, float* __restrict__ out,
                             const float* __restrict__ rowscale, const float* __restrict__ bias) {
    int warp = (blockIdx.x * blockDim.x + threadIdx.x) >> 5;
    int lane = threadIdx.x & 31;
    if (warp >= NN) return;
    float4 v = ((const float4*)in)[(size_t)warp * 32 + lane];
    float rs = rowscale ? rowscale[warp] : 1.f;
    float4 b = make_float4(0.f, 0.f, 0.f, 0.f);
    if (bias) b = ((const float4*)bias)[lane];
    v.x = v.x * rs + b.x; v.y = v.y * rs + b.y;
    v.z = v.z * rs + b.z; v.w = v.w * rs + b.w;
    float m = fmaxf(fmaxf(v.x, v.y), fmaxf(v.z, v.w));
#pragma unroll
    for (int off = 16; off > 0; off >>= 1) m = fmaxf(m, __shfl_xor_sync(0xffffffffu, m, off));
    v.x = expf(v.x - m); v.y = expf(v.y - m);
    v.z = expf(v.z - m); v.w = expf(v.w - m);
    float s = v.x + v.y + v.z + v.w;
#pragma unroll
    for (int off = 16; off > 0; off >>= 1) s += __shfl_xor_sync(0xffffffffu, s, off);
    float inv = 1.f / s;
    v.x *= inv; v.y *= inv; v.z *= inv; v.w *= inv;
    ((float4*)out)[(size_t)warp * 32 + lane] = v;
}

// ---------------- launcher ----------------
extern "C" void kernel_launch(void* const* d_in, const int* in_sizes, int n_in,
                              void* d_out, int out_size) {
    const float* in_feat = (const float*)d_in[0];
    const int*   src     = (const int*)d_in[1];
    const int*   dst     = (const int*)d_in[2];
    const float* Wc0 = (const float*)d_in[3];
    const float* bc0 = (const float*)d_in[4];
    const float* Wc1 = (const float*)d_in[5];
    const float* bc1 = (const float*)d_in[6];
    const float* Wc2 = (const float*)d_in[7];
    const float* bc2 = (const float*)d_in[8];
    const float* Wr0 = (const float*)d_in[9];
    const float* br0 = (const float*)d_in[10];
    const float* Wr1 = (const float*)d_in[11];
    const float* br1 = (const float*)d_in[12];
    const float* Wr2 = (const float*)d_in[13];
    const float* br2 = (const float*)d_in[14];
    float* out = (float*)d_out;

    float *bufA, *bufB, *bufC, *sout, *sin, *wt;
    cudaGetSymbolAddress((void**)&bufA, g_bufA);
    cudaGetSymbolAddress((void**)&bufB, g_bufB);
    cudaGetSymbolAddress((void**)&bufC, g_bufC);
    cudaGetSymbolAddress((void**)&sout, g_sout);
    cudaGetSymbolAddress((void**)&sin,  g_sin);
    cudaGetSymbolAddress((void**)&wt,   g_wt);
    float* WTc0 = wt + 0 * 65536;
    float* WTc1 = wt + 1 * 65536;
    float* WTc2 = wt + 2 * 65536;
    float* WTr0 = wt + 3 * 65536;
    float* WTr1 = wt + 4 * 65536;
    float* WTr2 = wt + 5 * 65536;

    const int M = NN;
    dim3 g_n((NN + 255) / 256);
    dim3 g_e(4096);
    dim3 g_w((NN * 32 + 255) / 256);
    const int GT = (M + 127) / 128;

    // graph preprocessing
    k_zero_counts<<<g_n, 256>>>();
    k_hist<<<g_e, 256>>>(src, dst);
    k_scan<<<1, 1024>>>();
    k_fill<<<g_e, 256>>>(src, dst);
    k_scales<<<g_n, 256>>>();

    // transpose all weights -> [N,K]
    k_transpose<<<dim3(4, 8), dim3(32, 8)>>>(Wc0, WTc0, 128, 256);
    k_transpose<<<dim3(8, 8), dim3(32, 8)>>>(Wc1, WTc1, 256, 256);
    k_transpose<<<dim3(8, 4), dim3(32, 8)>>>(Wc2, WTc2, 256, 128);
    k_transpose<<<dim3(4, 8), dim3(32, 8)>>>(Wr0, WTr0, 128, 256);
    k_transpose<<<dim3(8, 8), dim3(32, 8)>>>(Wr1, WTr1, 256, 256);
    k_transpose<<<dim3(8, 4), dim3(32, 8)>>>(Wr2, WTr2, 256, 128);

    // conv1: aggregate(in_feat * s_out) -> GEMM 128->256, *s_in + bc0, tanh
    k_agg<128><<<g_w, 256>>>(in_feat, sout, bufA);
    k_gemm_mma<1><<<dim3(GT, 4), 256>>>(bufA, WTc0, bufB, M, 128, 256, sin, bc0);

    // conv2: aggregate(h1 * s_out) -> GEMM 256->256, *s_in + bc1, tanh
    k_agg<256><<<g_w, 256>>>(bufB, sout, bufC);
    k_gemm_mma<1><<<dim3(GT, 4), 256>>>(bufC, WTc1, bufA, M, 256, 256, sin, bc1);

    // conv3: GEMM 256->128 (rowscale s_out), aggregate, softmax(*s_in + bc2)
    k_gemm_mma<0><<<dim3(GT, 2), 256>>>(bufA, WTc2, bufB, M, 256, 128, sout, nullptr);
    k_agg<128><<<g_w, 256>>>(bufB, nullptr, bufC);
    k_softmax128<<<g_w, 256>>>(bufC, out, sin, bc2);

    // MLP on h (h lives in out[0 : N*128])
    k_gemm_mma<1><<<dim3(GT, 4), 256>>>(out, WTr0, bufA, M, 128, 256, nullptr, br0);
    k_gemm_mma<1><<<dim3(GT, 4), 256>>>(bufA, WTr1, bufB, M, 256, 256, nullptr, br1);
    k_gemm_mma<0><<<dim3(GT, 2), 256>>>(bufB, WTr2, bufC, M, 256, 128, nullptr, br2);
    k_softmax128<<<g_w, 256>>>(bufC, out + (size_t)M * 128, nullptr, nullptr);
}

// round 6
// speedup vs baseline: 1.6858x; 1.0394x over previous
#include <cuda_runtime.h>
#include <cuda_bf16.h>
#include <math.h>
#include <stdint.h>

#define NN 100000
#define EE 1600000

// ---------------- static scratch ----------------
__device__ float g_bufA[(size_t)NN * 256];
__device__ float g_bufB[(size_t)NN * 256];
__device__ float g_bufC[(size_t)NN * 256];
__device__ float g_sout[NN];
__device__ float g_sin[NN];
__device__ int   g_cnt_out[NN];
__device__ int   g_cnt_in[NN];
__device__ int   g_cursor[NN];
__device__ int   g_row_ptr[NN + 1];
__device__ int   g_csr[EE];
__device__ float g_wt[6][65536];   // holds bf16 transposed weights (cast)

// ---------------- graph preprocessing ----------------
__global__ void k_zero_counts() {
    int i = blockIdx.x * blockDim.x + threadIdx.x;
    if (i < NN) { g_cnt_out[i] = 0; g_cnt_in[i] = 0; g_cursor[i] = 0; }
}
__global__ void k_hist(const int* __restrict__ src, const int* __restrict__ dst) {
    int stride = gridDim.x * blockDim.x;
    for (int i = blockIdx.x * blockDim.x + threadIdx.x; i < EE; i += stride) {
        atomicAdd(&g_cnt_out[src[i]], 1);
        atomicAdd(&g_cnt_in[dst[i]], 1);
    }
}
__global__ void k_scan() {
    __shared__ int sh[1024];
    __shared__ int carry;
    int t = threadIdx.x;
    if (t == 0) carry = 0;
    __syncthreads();
    for (int base = 0; base < NN; base += 1024) {
        int idx = base + t;
        int v = (idx < NN) ? g_cnt_in[idx] : 0;
        sh[t] = v;
        __syncthreads();
        for (int off = 1; off < 1024; off <<= 1) {
            int add = (t >= off) ? sh[t - off] : 0;
            __syncthreads();
            sh[t] += add;
            __syncthreads();
        }
        if (idx < NN) g_row_ptr[idx + 1] = carry + sh[t];
        int total = sh[1023];
        __syncthreads();
        if (t == 0) carry += total;
        __syncthreads();
    }
    if (t == 0) g_row_ptr[0] = 0;
}
__global__ void k_fill(const int* __restrict__ src, const int* __restrict__ dst) {
    int stride = gridDim.x * blockDim.x;
    for (int i = blockIdx.x * blockDim.x + threadIdx.x; i < EE; i += stride) {
        int d = dst[i];
        int pos = g_row_ptr[d] + atomicAdd(&g_cursor[d], 1);
        g_csr[pos] = src[i];
    }
}
__global__ void k_scales() {
    int i = blockIdx.x * blockDim.x + threadIdx.x;
    if (i < NN) {
        g_sout[i] = rsqrtf(fmaxf((float)g_cnt_out[i], 1.f));
        g_sin[i]  = rsqrtf(fmaxf((float)g_cnt_in[i], 1.f));
    }
}

// weight transpose + bf16 convert: WT[n*K+k] = bf16(W[k*N+n])
__global__ void k_transpose_b16(const float* __restrict__ W, __nv_bfloat16* __restrict__ WT,
                                int K, int N) {
    __shared__ float t[32][33];
    int k0 = blockIdx.x * 32, n0 = blockIdx.y * 32;
    int x = threadIdx.x, y = threadIdx.y;
    for (int i = 0; i < 32; i += 8) {
        int k = k0 + y + i, n = n0 + x;
        t[y + i][x] = (k < K && n < N) ? W[(size_t)k * N + n] : 0.f;
    }
    __syncthreads();
    for (int i = 0; i < 32; i += 8) {
        int n = n0 + y + i, k = k0 + x;
        if (n < N && k < K) WT[(size_t)n * K + k] = __float2bfloat16(t[x][y + i]);
    }
}

// prescale in_feat by sout and convert to bf16
__global__ void k_prescale(const float* __restrict__ x, __nv_bfloat16* __restrict__ o) {
    int i = blockIdx.x * blockDim.x + threadIdx.x;     // one float4 each
    if (i >= NN * 32) return;
    int m = i >> 5;
    float s = g_sout[m];
    float4 v = ((const float4*)x)[i];
    uint2 r;
    __nv_bfloat162 p0 = __float22bfloat162_rn(make_float2(v.x * s, v.y * s));
    __nv_bfloat162 p1 = __float22bfloat162_rn(make_float2(v.z * s, v.w * s));
    r.x = *(uint32_t*)&p0; r.y = *(uint32_t*)&p1;
    ((uint2*)o)[i] = r;
}

// ---------------- aggregation (bf16 gather, fp32 accumulate) ----------------
// OUTB: 1 -> bf16 output, 0 -> fp32 output
template <int D, int OUTB>
__global__ void k_agg_b16(const __nv_bfloat16* __restrict__ x, void* __restrict__ out) {
    int warp = (blockIdx.x * blockDim.x + threadIdx.x) >> 5;
    int lane = threadIdx.x & 31;
    if (warp >= NN) return;
    int s0 = g_row_ptr[warp], s1 = g_row_ptr[warp + 1];

    if (D == 128) {
        float4 acc = make_float4(0.f, 0.f, 0.f, 0.f);
        for (int e = s0; e < s1; e++) {
            int s = g_csr[e];
            uint2 v = ((const uint2*)(x + (size_t)s * 128))[lane];
            __nv_bfloat162 p0 = *(__nv_bfloat162*)&v.x;
            __nv_bfloat162 p1 = *(__nv_bfloat162*)&v.y;
            acc.x += __low2float(p0); acc.y += __high2float(p0);
            acc.z += __low2float(p1); acc.w += __high2float(p1);
        }
        if (OUTB) {
            uint2 r;
            __nv_bfloat162 p0 = __float22bfloat162_rn(make_float2(acc.x, acc.y));
            __nv_bfloat162 p1 = __float22bfloat162_rn(make_float2(acc.z, acc.w));
            r.x = *(uint32_t*)&p0; r.y = *(uint32_t*)&p1;
            ((uint2*)out)[(size_t)warp * 32 + lane] = r;
        } else {
            ((float4*)out)[(size_t)warp * 32 + lane] = acc;
        }
    } else {  // D == 256
        float acc[8];
#pragma unroll
        for (int j = 0; j < 8; j++) acc[j] = 0.f;
        for (int e = s0; e < s1; e++) {
            int s = g_csr[e];
            uint4 v = ((const uint4*)(x + (size_t)s * 256))[lane];
            __nv_bfloat162 p0 = *(__nv_bfloat162*)&v.x;
            __nv_bfloat162 p1 = *(__nv_bfloat162*)&v.y;
            __nv_bfloat162 p2 = *(__nv_bfloat162*)&v.z;
            __nv_bfloat162 p3 = *(__nv_bfloat162*)&v.w;
            acc[0] += __low2float(p0); acc[1] += __high2float(p0);
            acc[2] += __low2float(p1); acc[3] += __high2float(p1);
            acc[4] += __low2float(p2); acc[5] += __high2float(p2);
            acc[6] += __low2float(p3); acc[7] += __high2float(p3);
        }
        uint4 r;
        __nv_bfloat162 q0 = __float22bfloat162_rn(make_float2(acc[0], acc[1]));
        __nv_bfloat162 q1 = __float22bfloat162_rn(make_float2(acc[2], acc[3]));
        __nv_bfloat162 q2 = __float22bfloat162_rn(make_float2(acc[4], acc[5]));
        __nv_bfloat162 q3 = __float22bfloat162_rn(make_float2(acc[6], acc[7]));
        r.x = *(uint32_t*)&q0; r.y = *(uint32_t*)&q1;
        r.z = *(uint32_t*)&q2; r.w = *(uint32_t*)&q3;
        ((uint4*)out)[(size_t)warp * 32 + lane] = r;
    }
}

// ---------------- bf16 tensor-core GEMM via mma.sync m16n8k16 ----------------
__device__ __forceinline__ void mma_bf16(float* d, const uint32_t* a, const uint32_t* b) {
    asm volatile(
        "mma.sync.aligned.m16n8k16.row.col.f32.bf16.bf16.f32 "
        "{%0,%1,%2,%3}, {%4,%5,%6,%7}, {%8,%9}, {%0,%1,%2,%3};"
        : "+f"(d[0]), "+f"(d[1]), "+f"(d[2]), "+f"(d[3])
        : "r"(a[0]), "r"(a[1]), "r"(a[2]), "r"(a[3]), "r"(b[0]), "r"(b[1]));
}

// C[M,N] = post[m] * act( (A@WT^T)*pre[m] + bias[n] ), A bf16 [M,K], WT bf16 [N,K]
// CTA tile 128x64, BK=64, 256 threads (8 warps 4x2), warp tile 32x32.
template <int ACT, int OUTB>
__global__ void __launch_bounds__(256)
k_gemm_bf16(const __nv_bfloat16* __restrict__ A, const __nv_bfloat16* __restrict__ WT,
            void* __restrict__ Cout, int M, int K, int N,
            const float* __restrict__ prescale, const float* __restrict__ bias,
            const float* __restrict__ postscale) {
    __shared__ __nv_bfloat16 As[128 * 72];   // stride 72 bf16 = 36 words: conflict-free
    __shared__ __nv_bfloat16 Bs[64 * 72];
    int tid = threadIdx.x;
    int warp = tid >> 5, lane = tid & 31;
    int g = lane >> 2, t = lane & 3;
    int wm = warp >> 1, wn = warp & 1;
    int bm = blockIdx.x * 128, bn = blockIdx.y * 64;

    float acc[2][4][4];
#pragma unroll
    for (int mt = 0; mt < 2; mt++)
#pragma unroll
        for (int nt = 0; nt < 4; nt++)
#pragma unroll
            for (int j = 0; j < 4; j++) acc[mt][nt][j] = 0.f;

    for (int kt = 0; kt < K; kt += 64) {
        // A tile: 128 rows x 64 bf16, uint4 = 8 bf16; 1024 loads / 256 thr = 4
#pragma unroll
        for (int i = 0; i < 4; i++) {
            int s = tid + i * 256;
            int row = s >> 3, q = s & 7;
            int gm = bm + row;
            uint4 v = make_uint4(0u, 0u, 0u, 0u);
            if (gm < M) v = *(const uint4*)(A + (size_t)gm * K + kt + q * 8);
            *(uint4*)(As + row * 72 + q * 8) = v;
        }
        // B tile: 64 rows x 64 bf16; 512 / 256 = 2
#pragma unroll
        for (int i = 0; i < 2; i++) {
            int s = tid + i * 256;
            int row = s >> 3, q = s & 7;
            uint4 v = *(const uint4*)(WT + (size_t)(bn + row) * K + kt + q * 8);
            *(uint4*)(Bs + row * 72 + q * 8) = v;
        }
        __syncthreads();

        const uint32_t* Asu = (const uint32_t*)As;   // 36 words per row
        const uint32_t* Bsu = (const uint32_t*)Bs;
#pragma unroll
        for (int k16 = 0; k16 < 4; k16++) {
            int kw = k16 * 8;       // word offset = (k16*16)/2
            uint32_t a[2][4];
#pragma unroll
            for (int mt = 0; mt < 2; mt++) {
                int r0 = (wm * 32 + mt * 16 + g) * 36 + kw + t;
                a[mt][0] = Asu[r0];
                a[mt][1] = Asu[r0 + 8 * 36];
                a[mt][2] = Asu[r0 + 4];
                a[mt][3] = Asu[r0 + 8 * 36 + 4];
            }
            uint32_t b[4][2];
#pragma unroll
            for (int nt = 0; nt < 4; nt++) {
                int r0 = (wn * 32 + nt * 8 + g) * 36 + kw + t;
                b[nt][0] = Bsu[r0];
                b[nt][1] = Bsu[r0 + 4];
            }
#pragma unroll
            for (int mt = 0; mt < 2; mt++)
#pragma unroll
                for (int nt = 0; nt < 4; nt++)
                    mma_bf16(acc[mt][nt], a[mt], b[nt]);
        }
        __syncthreads();
    }

    // epilogue
    float2 bv[4];
#pragma unroll
    for (int nt = 0; nt < 4; nt++) {
        if (bias) bv[nt] = *(const float2*)(bias + bn + wn * 32 + nt * 8 + 2 * t);
        else bv[nt] = make_float2(0.f, 0.f);
    }
#pragma unroll
    for (int mt = 0; mt < 2; mt++) {
#pragma unroll
        for (int h = 0; h < 2; h++) {
            int gm = bm + wm * 32 + mt * 16 + h * 8 + g;
            if (gm >= M) continue;
            float pre = prescale ? prescale[gm] : 1.f;
            float post = postscale ? postscale[gm] : 1.f;
#pragma unroll
            for (int nt = 0; nt < 4; nt++) {
                float ox = acc[mt][nt][2 * h]     * pre + bv[nt].x;
                float oy = acc[mt][nt][2 * h + 1] * pre + bv[nt].y;
                if (ACT == 1) { ox = tanhf(ox); oy = tanhf(oy); }
                ox *= post; oy *= post;
                size_t off = (size_t)gm * N + bn + wn * 32 + nt * 8 + 2 * t;
                if (OUTB) {
                    __nv_bfloat162 p = __float22bfloat162_rn(make_float2(ox, oy));
                    *(uint32_t*)((__nv_bfloat16*)Cout + off) = *(uint32_t*)&p;
                } else {
                    *(float2*)((float*)Cout + off) = make_float2(ox, oy);
                }
            }
        }
    }
}

// ---------------- row softmax over D=128, fp32 in, fp32 out + optional bf16 out ----------------
__global__ void k_softmax128(const float* __restrict__ in, float* __restrict__ out,
                             __nv_bfloat16* __restrict__ outb,
                             const float* __restrict__ rowscale, const float* __restrict__ bias) {
    int warp = (blockIdx.x * blockDim.x + threadIdx.x) >> 5;
    int lane = threadIdx.x & 31;
    if (warp >= NN) return;
    float4 v = ((const float4*)in)[(size_t)warp * 32 + lane];
    float rs = rowscale ? rowscale[warp] : 1.f;
    float4 b = make_float4(0.f, 0.f, 0.f, 0.f);
    if (bias) b = ((const float4*)bias)[lane];
    v.x = v.x * rs + b.x; v.y = v.y * rs + b.y;
    v.z = v.z * rs + b.z; v.w = v.w * rs + b.w;
    float m = fmaxf(fmaxf(v.x, v.y), fmaxf(v.z, v.w));
#pragma unroll
    for (int off = 16; off > 0; off >>= 1) m = fmaxf(m, __shfl_xor_sync(0xffffffffu, m, off));
    v.x = expf(v.x - m); v.y = expf(v.y - m);
    v.z = expf(v.z - m); v.w = expf(v.w - m);
    float s = v.x + v.y + v.z + v.w;
#pragma unroll
    for (int off = 16; off > 0; off >>= 1) s += __shfl_xor_sync(0xffffffffu, s, off);
    float inv = 1.f / s;
    v.x *= inv; v.y *= inv; v.z *= inv; v.w *= inv;
    ((float4*)out)[(size_t)warp * 32 + lane] = v;
    if (outb) {
        uint2 r;
        __nv_bfloat162 p0 = __float22bfloat162_rn(make_float2(v.x, v.y));
        __nv_bfloat162 p1 = __float22bfloat162_rn(make_float2(v.z, v.w));
        r.x = *(uint32_t*)&p0; r.y = *(uint32_t*)&p1;
        ((uint2*)outb)[(size_t)warp * 32 + lane] = r;
    }
}

// ---------------- launcher ----------------
extern "C" void kernel_launch(void* const* d_in, const int* in_sizes, int n_in,
                              void* d_out, int out_size) {
    const float* in_feat = (const float*)d_in[0];
    const int*   src     = (const int*)d_in[1];
    const int*   dst     = (const int*)d_in[2];
    const float* Wc0 = (const float*)d_in[3];
    const float* bc0 = (const float*)d_in[4];
    const float* Wc1 = (const float*)d_in[5];
    const float* bc1 = (const float*)d_in[6];
    const float* Wc2 = (const float*)d_in[7];
    const float* bc2 = (const float*)d_in[8];
    const float* Wr0 = (const float*)d_in[9];
    const float* br0 = (const float*)d_in[10];
    const float* Wr1 = (const float*)d_in[11];
    const float* br1 = (const float*)d_in[12];
    const float* Wr2 = (const float*)d_in[13];
    const float* br2 = (const float*)d_in[14];
    float* out = (float*)d_out;

    float *bufA, *bufB, *bufC, *sout, *sin, *wt;
    cudaGetSymbolAddress((void**)&bufA, g_bufA);
    cudaGetSymbolAddress((void**)&bufB, g_bufB);
    cudaGetSymbolAddress((void**)&bufC, g_bufC);
    cudaGetSymbolAddress((void**)&sout, g_sout);
    cudaGetSymbolAddress((void**)&sin,  g_sin);
    cudaGetSymbolAddress((void**)&wt,   g_wt);

    __nv_bfloat16* bA16 = (__nv_bfloat16*)bufA;
    __nv_bfloat16* bB16 = (__nv_bfloat16*)bufB;
    __nv_bfloat16* WTc0 = (__nv_bfloat16*)(wt + 0 * 65536);
    __nv_bfloat16* WTc1 = (__nv_bfloat16*)(wt + 1 * 65536);
    __nv_bfloat16* WTc2 = (__nv_bfloat16*)(wt + 2 * 65536);
    __nv_bfloat16* WTr0 = (__nv_bfloat16*)(wt + 3 * 65536);
    __nv_bfloat16* WTr1 = (__nv_bfloat16*)(wt + 4 * 65536);
    __nv_bfloat16* WTr2 = (__nv_bfloat16*)(wt + 5 * 65536);

    const int M = NN;
    dim3 g_n((NN + 255) / 256);
    dim3 g_e(4096);
    dim3 g_w((NN * 32 + 255) / 256);       // one warp per node
    dim3 g_p((NN * 32 + 255) / 256);       // prescale: one float4 per thread
    const int GT = (M + 127) / 128;

    // graph preprocessing
    k_zero_counts<<<g_n, 256>>>();
    k_hist<<<g_e, 256>>>(src, dst);
    k_scan<<<1, 1024>>>();
    k_fill<<<g_e, 256>>>(src, dst);
    k_scales<<<g_n, 256>>>();

    // weight transpose + bf16
    k_transpose_b16<<<dim3(4, 8), dim3(32, 8)>>>(Wc0, WTc0, 128, 256);
    k_transpose_b16<<<dim3(8, 8), dim3(32, 8)>>>(Wc1, WTc1, 256, 256);
    k_transpose_b16<<<dim3(8, 4), dim3(32, 8)>>>(Wc2, WTc2, 256, 128);
    k_transpose_b16<<<dim3(4, 8), dim3(32, 8)>>>(Wr0, WTr0, 128, 256);
    k_transpose_b16<<<dim3(8, 8), dim3(32, 8)>>>(Wr1, WTr1, 256, 256);
    k_transpose_b16<<<dim3(8, 4), dim3(32, 8)>>>(Wr2, WTr2, 256, 128);

    // x_b16 = bf16(in_feat * sout)   (into bufA region)
    k_prescale<<<g_p, 256>>>(in_feat, bA16);

    // conv1: agg(x_b16) -> GEMM 128->256: tanh(acc*sin + bc0) * sout -> bf16
    k_agg_b16<128, 1><<<g_w, 256>>>(bA16, bB16);
    k_gemm_bf16<1, 1><<<dim3(GT, 4), 256>>>(bB16, WTc0, bA16, M, 128, 256, sin, bc0, sout);

    // conv2: agg -> GEMM 256->256: tanh(acc*sin + bc1) * sout -> bf16
    k_agg_b16<256, 1><<<g_w, 256>>>(bA16, bB16);
    k_gemm_bf16<1, 1><<<dim3(GT, 4), 256>>>(bB16, WTc1, bA16, M, 256, 256, sin, bc1, sout);

    // conv3: GEMM 256->128 plain -> bf16, agg -> fp32, softmax(*sin + bc2) -> out + bf16
    k_gemm_bf16<0, 1><<<dim3(GT, 2), 256>>>(bA16, WTc2, bB16, M, 256, 128, nullptr, nullptr, nullptr);
    k_agg_b16<128, 0><<<g_w, 256>>>(bB16, bufC);
    k_softmax128<<<g_w, 256>>>(bufC, out, bA16, sin, bc2);

    // MLP on h (bf16 copy in bA16)
    k_gemm_bf16<1, 1><<<dim3(GT, 4), 256>>>(bA16, WTr0, bB16, M, 128, 256, nullptr, br0, nullptr);
    k_gemm_bf16<1, 1><<<dim3(GT, 4), 256>>>(bB16, WTr1, bA16, M, 256, 256, nullptr, br1, nullptr);
    k_gemm_bf16<0, 0><<<dim3(GT, 2), 256>>>(bA16, WTr2, bufC, M, 256, 128, nullptr, br2, nullptr);
    k_softmax128<<<g_w, 256>>>(bufC, out + (size_t)M * 128, nullptr, nullptr, nullptr);
}

// round 8
// speedup vs baseline: 2.6863x; 1.5935x over previous
#include <cuda_runtime.h>
#include <cuda_bf16.h>
#include <math.h>
#include <stdint.h>

#define NN 100000
#define EE 1600000

// ---------------- static scratch ----------------
__device__ float g_bufA[(size_t)NN * 256];
__device__ float g_bufB[(size_t)NN * 256];
__device__ float g_bufC[(size_t)NN * 256];
__device__ float g_sout[NN];
__device__ float g_sin[NN];
__device__ int   g_cnt_out[NN];
__device__ int   g_cnt_in[NN];
__device__ int   g_cursor[NN];
__device__ int   g_row_ptr[NN + 1];
__device__ int   g_csr[EE];
__device__ float g_wt[6][65536];   // holds bf16 transposed weights (cast)

// ---------------- graph preprocessing ----------------
__global__ void k_zero_counts() {
    int i = blockIdx.x * blockDim.x + threadIdx.x;
    if (i < NN) { g_cnt_out[i] = 0; g_cnt_in[i] = 0; g_cursor[i] = 0; }
}
__global__ void k_hist(const int* __restrict__ src, const int* __restrict__ dst) {
    int stride = gridDim.x * blockDim.x;
    for (int i = blockIdx.x * blockDim.x + threadIdx.x; i < EE; i += stride) {
        atomicAdd(&g_cnt_out[src[i]], 1);
        atomicAdd(&g_cnt_in[dst[i]], 1);
    }
}
// shfl-based chunked inclusive scan of g_cnt_in -> g_row_ptr
__global__ void k_scan() {
    __shared__ int wsum[32];
    __shared__ int carry_s;
    int t = threadIdx.x, lane = t & 31, w = t >> 5;
    if (t == 0) carry_s = 0;
    __syncthreads();
    for (int base = 0; base < NN; base += 1024) {
        int idx = base + t;
        int x = (idx < NN) ? g_cnt_in[idx] : 0;
#pragma unroll
        for (int off = 1; off < 32; off <<= 1) {
            int y = __shfl_up_sync(0xffffffffu, x, off);
            if (lane >= off) x += y;
        }
        if (lane == 31) wsum[w] = x;
        __syncthreads();
        if (w == 0) {
            int s = wsum[lane];
#pragma unroll
            for (int off = 1; off < 32; off <<= 1) {
                int y = __shfl_up_sync(0xffffffffu, s, off);
                if (lane >= off) s += y;
            }
            wsum[lane] = s;
        }
        __syncthreads();
        int res = carry_s + ((w > 0) ? wsum[w - 1] : 0) + x;
        if (idx < NN) g_row_ptr[idx + 1] = res;
        __syncthreads();
        if (t == 1023) carry_s = res;
        __syncthreads();
    }
    if (t == 0) g_row_ptr[0] = 0;
}
__global__ void k_fill(const int* __restrict__ src, const int* __restrict__ dst) {
    int stride = gridDim.x * blockDim.x;
    for (int i = blockIdx.x * blockDim.x + threadIdx.x; i < EE; i += stride) {
        int d = dst[i];
        int pos = g_row_ptr[d] + atomicAdd(&g_cursor[d], 1);
        g_csr[pos] = src[i];
    }
}
__global__ void k_scales() {
    int i = blockIdx.x * blockDim.x + threadIdx.x;
    if (i < NN) {
        g_sout[i] = rsqrtf(fmaxf((float)g_cnt_out[i], 1.f));
        g_sin[i]  = rsqrtf(fmaxf((float)g_cnt_in[i], 1.f));
    }
}

// weight transpose + bf16 convert: WT[n*K+k] = bf16(W[k*N+n])
__global__ void k_transpose_b16(const float* __restrict__ W, __nv_bfloat16* __restrict__ WT,
                                int K, int N) {
    __shared__ float t[32][33];
    int k0 = blockIdx.x * 32, n0 = blockIdx.y * 32;
    int x = threadIdx.x, y = threadIdx.y;
    for (int i = 0; i < 32; i += 8) {
        int k = k0 + y + i, n = n0 + x;
        t[y + i][x] = (k < K && n < N) ? W[(size_t)k * N + n] : 0.f;
    }
    __syncthreads();
    for (int i = 0; i < 32; i += 8) {
        int n = n0 + y + i, k = k0 + x;
        if (n < N && k < K) WT[(size_t)n * K + k] = __float2bfloat16(t[x][y + i]);
    }
}

// prescale in_feat by sout and convert to bf16
__global__ void k_prescale(const float* __restrict__ x, __nv_bfloat16* __restrict__ o) {
    int i = blockIdx.x * blockDim.x + threadIdx.x;
    if (i >= NN * 32) return;
    int m = i >> 5;
    float s = g_sout[m];
    float4 v = ((const float4*)x)[i];
    uint2 r;
    __nv_bfloat162 p0 = __float22bfloat162_rn(make_float2(v.x * s, v.y * s));
    __nv_bfloat162 p1 = __float22bfloat162_rn(make_float2(v.z * s, v.w * s));
    r.x = *(uint32_t*)&p0; r.y = *(uint32_t*)&p1;
    ((uint2*)o)[i] = r;
}

// ---------------- aggregation (bf16 gather, fp32 accumulate) ----------------
// Index preload per 32-edge chunk + shfl broadcast + 2-way unrolled gathers.
template <int D, int OUTB>
__global__ void k_agg_b16(const __nv_bfloat16* __restrict__ x, void* __restrict__ out) {
    int warp = (blockIdx.x * blockDim.x + threadIdx.x) >> 5;
    int lane = threadIdx.x & 31;
    if (warp >= NN) return;
    int s0 = g_row_ptr[warp], s1 = g_row_ptr[warp + 1];

    if (D == 128) {
        float4 a0 = make_float4(0.f, 0.f, 0.f, 0.f);
        float4 a1 = make_float4(0.f, 0.f, 0.f, 0.f);
        for (int base = s0; base < s1; base += 32) {
            int cnt = min(32, s1 - base);
            int myidx = (lane < cnt) ? g_csr[base + lane] : 0;
            int e = 0;
            for (; e + 2 <= cnt; e += 2) {
                int sa = __shfl_sync(0xffffffffu, myidx, e);
                int sb = __shfl_sync(0xffffffffu, myidx, e + 1);
                uint2 va = ((const uint2*)(x + (size_t)sa * 128))[lane];
                uint2 vb = ((const uint2*)(x + (size_t)sb * 128))[lane];
                __nv_bfloat162 p0 = *(__nv_bfloat162*)&va.x;
                __nv_bfloat162 p1 = *(__nv_bfloat162*)&va.y;
                a0.x += __low2float(p0); a0.y += __high2float(p0);
                a0.z += __low2float(p1); a0.w += __high2float(p1);
                __nv_bfloat162 q0 = *(__nv_bfloat162*)&vb.x;
                __nv_bfloat162 q1 = *(__nv_bfloat162*)&vb.y;
                a1.x += __low2float(q0); a1.y += __high2float(q0);
                a1.z += __low2float(q1); a1.w += __high2float(q1);
            }
            if (e < cnt) {
                int sa = __shfl_sync(0xffffffffu, myidx, e);
                uint2 va = ((const uint2*)(x + (size_t)sa * 128))[lane];
                __nv_bfloat162 p0 = *(__nv_bfloat162*)&va.x;
                __nv_bfloat162 p1 = *(__nv_bfloat162*)&va.y;
                a0.x += __low2float(p0); a0.y += __high2float(p0);
                a0.z += __low2float(p1); a0.w += __high2float(p1);
            }
        }
        float4 acc = make_float4(a0.x + a1.x, a0.y + a1.y, a0.z + a1.z, a0.w + a1.w);
        if (OUTB) {
            uint2 r;
            __nv_bfloat162 p0 = __float22bfloat162_rn(make_float2(acc.x, acc.y));
            __nv_bfloat162 p1 = __float22bfloat162_rn(make_float2(acc.z, acc.w));
            r.x = *(uint32_t*)&p0; r.y = *(uint32_t*)&p1;
            ((uint2*)out)[(size_t)warp * 32 + lane] = r;
        } else {
            ((float4*)out)[(size_t)warp * 32 + lane] = acc;
        }
    } else {  // D == 256
        float a0[8], a1[8];
#pragma unroll
        for (int j = 0; j < 8; j++) { a0[j] = 0.f; a1[j] = 0.f; }
        for (int base = s0; base < s1; base += 32) {
            int cnt = min(32, s1 - base);
            int myidx = (lane < cnt) ? g_csr[base + lane] : 0;
            int e = 0;
            for (; e + 2 <= cnt; e += 2) {
                int sa = __shfl_sync(0xffffffffu, myidx, e);
                int sb = __shfl_sync(0xffffffffu, myidx, e + 1);
                uint4 va = ((const uint4*)(x + (size_t)sa * 256))[lane];
                uint4 vb = ((const uint4*)(x + (size_t)sb * 256))[lane];
                {
                    __nv_bfloat162 p0 = *(__nv_bfloat162*)&va.x, p1 = *(__nv_bfloat162*)&va.y;
                    __nv_bfloat162 p2 = *(__nv_bfloat162*)&va.z, p3 = *(__nv_bfloat162*)&va.w;
                    a0[0] += __low2float(p0); a0[1] += __high2float(p0);
                    a0[2] += __low2float(p1); a0[3] += __high2float(p1);
                    a0[4] += __low2float(p2); a0[5] += __high2float(p2);
                    a0[6] += __low2float(p3); a0[7] += __high2float(p3);
                }
                {
                    __nv_bfloat162 p0 = *(__nv_bfloat162*)&vb.x, p1 = *(__nv_bfloat162*)&vb.y;
                    __nv_bfloat162 p2 = *(__nv_bfloat162*)&vb.z, p3 = *(__nv_bfloat162*)&vb.w;
                    a1[0] += __low2float(p0); a1[1] += __high2float(p0);
                    a1[2] += __low2float(p1); a1[3] += __high2float(p1);
                    a1[4] += __low2float(p2); a1[5] += __high2float(p2);
                    a1[6] += __low2float(p3); a1[7] += __high2float(p3);
                }
            }
            if (e < cnt) {
                int sa = __shfl_sync(0xffffffffu, myidx, e);
                uint4 va = ((const uint4*)(x + (size_t)sa * 256))[lane];
                __nv_bfloat162 p0 = *(__nv_bfloat162*)&va.x, p1 = *(__nv_bfloat162*)&va.y;
                __nv_bfloat162 p2 = *(__nv_bfloat162*)&va.z, p3 = *(__nv_bfloat162*)&va.w;
                a0[0] += __low2float(p0); a0[1] += __high2float(p0);
                a0[2] += __low2float(p1); a0[3] += __high2float(p1);
                a0[4] += __low2float(p2); a0[5] += __high2float(p2);
                a0[6] += __low2float(p3); a0[7] += __high2float(p3);
            }
        }
        uint4 r;
        __nv_bfloat162 q0 = __float22bfloat162_rn(make_float2(a0[0] + a1[0], a0[1] + a1[1]));
        __nv_bfloat162 q1 = __float22bfloat162_rn(make_float2(a0[2] + a1[2], a0[3] + a1[3]));
        __nv_bfloat162 q2 = __float22bfloat162_rn(make_float2(a0[4] + a1[4], a0[5] + a1[5]));
        __nv_bfloat162 q3 = __float22bfloat162_rn(make_float2(a0[6] + a1[6], a0[7] + a1[7]));
        r.x = *(uint32_t*)&q0; r.y = *(uint32_t*)&q1;
        r.z = *(uint32_t*)&q2; r.w = *(uint32_t*)&q3;
        ((uint4*)out)[(size_t)warp * 32 + lane] = r;
    }
}

// ---------------- bf16 tensor-core GEMM, cp.async 2-stage pipeline ----------------
__device__ __forceinline__ void mma_bf16(float* d, const uint32_t* a, const uint32_t* b) {
    asm volatile(
        "mma.sync.aligned.m16n8k16.row.col.f32.bf16.bf16.f32 "
        "{%0,%1,%2,%3}, {%4,%5,%6,%7}, {%8,%9}, {%0,%1,%2,%3};"
        : "+f"(d[0]), "+f"(d[1]), "+f"(d[2]), "+f"(d[3])
        : "r"(a[0]), "r"(a[1]), "r"(a[2]), "r"(a[3]), "r"(b[0]), "r"(b[1]));
}
__device__ __forceinline__ void cp16(uint32_t dst, const void* src, int sz) {
    asm volatile("cp.async.cg.shared.global [%0], [%1], 16, %2;" :: "r"(dst), "l"(src), "r"(sz) : "memory");
}
#define CP_COMMIT() asm volatile("cp.async.commit_group;" ::: "memory")

// C[M,N] = post[m] * act( (A@WT^T)*pre[m] + bias[n] )
// CTA 128x64, BK=64, 256 threads (8 warps 4x2), 2-stage cp.async pipeline.
template <int ACT, int OUTB>
__global__ void __launch_bounds__(256)
k_gemm_bf16(const __nv_bfloat16* __restrict__ A, const __nv_bfloat16* __restrict__ WT,
            void* __restrict__ Cout, int M, int K, int N,
            const float* __restrict__ prescale, const float* __restrict__ bias,
            const float* __restrict__ postscale) {
    extern __shared__ __nv_bfloat16 sm[];
    constexpr int AW = 128 * 72;   // bf16 elements per A stage
    constexpr int BW = 64 * 72;
    __nv_bfloat16* As = sm;                 // [2][AW]
    __nv_bfloat16* Bs = sm + 2 * AW;        // [2][BW]
    uint32_t sA = (uint32_t)__cvta_generic_to_shared(As);
    uint32_t sB = (uint32_t)__cvta_generic_to_shared(Bs);

    int tid = threadIdx.x;
    int warp = tid >> 5, lane = tid & 31;
    int g = lane >> 2, t = lane & 3;
    int wm = warp >> 1, wn = warp & 1;
    int bm = blockIdx.x * 128, bn = blockIdx.y * 64;

    int lrow = tid >> 3, lq = tid & 7;      // load coords: 32 rows x 8 qcols per 256-thr pass

    float acc[2][4][4];
#pragma unroll
    for (int mt = 0; mt < 2; mt++)
#pragma unroll
        for (int nt = 0; nt < 4; nt++)
#pragma unroll
            for (int j = 0; j < 4; j++) acc[mt][nt][j] = 0.f;

    const int T = K >> 6;

    auto load_tile = [&](int stage, int kt) {
#pragma unroll
        for (int i = 0; i < 4; i++) {
            int row = lrow + i * 32;
            int gm = bm + row;
            cp16(sA + (uint32_t)(stage * AW + row * 72 + lq * 8) * 2,
                 A + (size_t)gm * K + kt + lq * 8, (gm < M) ? 16 : 0);
        }
#pragma unroll
        for (int i = 0; i < 2; i++) {
            int row = lrow + i * 32;
            cp16(sB + (uint32_t)(stage * BW + row * 72 + lq * 8) * 2,
                 WT + (size_t)(bn + row) * K + kt + lq * 8, 16);
        }
    };

    load_tile(0, 0);
    CP_COMMIT();

    for (int ti = 0; ti < T; ti++) {
        if (ti + 1 < T) {
            load_tile((ti + 1) & 1, (ti + 1) * 64);
            CP_COMMIT();
            asm volatile("cp.async.wait_group 1;" ::: "memory");
        } else {
            asm volatile("cp.async.wait_group 0;" ::: "memory");
        }
        __syncthreads();

        const uint32_t* Asu = (const uint32_t*)(As + (ti & 1) * AW);
        const uint32_t* Bsu = (const uint32_t*)(Bs + (ti & 1) * BW);
#pragma unroll
        for (int k16 = 0; k16 < 4; k16++) {
            int kw = k16 * 8;
            uint32_t a[2][4];
#pragma unroll
            for (int mt = 0; mt < 2; mt++) {
                int r0 = (wm * 32 + mt * 16 + g) * 36 + kw + t;
                a[mt][0] = Asu[r0];
                a[mt][1] = Asu[r0 + 8 * 36];
                a[mt][2] = Asu[r0 + 4];
                a[mt][3] = Asu[r0 + 8 * 36 + 4];
            }
            uint32_t b[4][2];
#pragma unroll
            for (int nt = 0; nt < 4; nt++) {
                int r0 = (wn * 32 + nt * 8 + g) * 36 + kw + t;
                b[nt][0] = Bsu[r0];
                b[nt][1] = Bsu[r0 + 4];
            }
#pragma unroll
            for (int mt = 0; mt < 2; mt++)
#pragma unroll
                for (int nt = 0; nt < 4; nt++)
                    mma_bf16(acc[mt][nt], a[mt], b[nt]);
        }
        __syncthreads();
    }

    // epilogue
    float2 bv[4];
#pragma unroll
    for (int nt = 0; nt < 4; nt++) {
        if (bias) bv[nt] = *(const float2*)(bias + bn + wn * 32 + nt * 8 + 2 * t);
        else bv[nt] = make_float2(0.f, 0.f);
    }
#pragma unroll
    for (int mt = 0; mt < 2; mt++) {
#pragma unroll
        for (int h = 0; h < 2; h++) {
            int gm = bm + wm * 32 + mt * 16 + h * 8 + g;
            if (gm >= M) continue;
            float pre = prescale ? prescale[gm] : 1.f;
            float post = postscale ? postscale[gm] : 1.f;
#pragma unroll
            for (int nt = 0; nt < 4; nt++) {
                float ox = acc[mt][nt][2 * h]     * pre + bv[nt].x;
                float oy = acc[mt][nt][2 * h + 1] * pre + bv[nt].y;
                if (ACT == 1) { ox = tanhf(ox); oy = tanhf(oy); }
                ox *= post; oy *= post;
                size_t off = (size_t)gm * N + bn + wn * 32 + nt * 8 + 2 * t;
                if (OUTB) {
                    __nv_bfloat162 p = __float22bfloat162_rn(make_float2(ox, oy));
                    *(uint32_t*)((__nv_bfloat16*)Cout + off) = *(uint32_t*)&p;
                } else {
                    *(float2*)((float*)Cout + off) = make_float2(ox, oy);
                }
            }
        }
    }
}

// ---------------- row softmax over D=128, fp32 in, fp32 out + optional bf16 out ----------------
__global__ void k_softmax128(const float* __restrict__ in, float* __restrict__ out,
                             __nv_bfloat16* __restrict__ outb,
                             const float* __restrict__ rowscale, const float* __restrict__ bias) {
    int warp = (blockIdx.x * blockDim.x + threadIdx.x) >> 5;
    int lane = threadIdx.x & 31;
    if (warp >= NN) return;
    float4 v = ((const float4*)in)[(size_t)warp * 32 + lane];
    float rs = rowscale ? rowscale[warp] : 1.f;
    float4 b = make_float4(0.f, 0.f, 0.f, 0.f);
    if (bias) b = ((const float4*)bias)[lane];
    v.x = v.x * rs + b.x; v.y = v.y * rs + b.y;
    v.z = v.z * rs + b.z; v.w = v.w * rs + b.w;
    float m = fmaxf(fmaxf(v.x, v.y), fmaxf(v.z, v.w));
#pragma unroll
    for (int off = 16; off > 0; off >>= 1) m = fmaxf(m, __shfl_xor_sync(0xffffffffu, m, off));
    v.x = expf(v.x - m); v.y = expf(v.y - m);
    v.z = expf(v.z - m); v.w = expf(v.w - m);
    float s = v.x + v.y + v.z + v.w;
#pragma unroll
    for (int off = 16; off > 0; off >>= 1) s += __shfl_xor_sync(0xffffffffu, s, off);
    float inv = 1.f / s;
    v.x *= inv; v.y *= inv; v.z *= inv; v.w *= inv;
    ((float4*)out)[(size_t)warp * 32 + lane] = v;
    if (outb) {
        uint2 r;
        __nv_bfloat162 p0 = __float22bfloat162_rn(make_float2(v.x, v.y));
        __nv_bfloat162 p1 = __float22bfloat162_rn(make_float2(v.z, v.w));
        r.x = *(uint32_t*)&p0; r.y = *(uint32_t*)&p1;
        ((uint2*)outb)[(size_t)warp * 32 + lane] = r;
    }
}

// ---------------- launcher ----------------
extern "C" void kernel_launch(void* const* d_in, const int* in_sizes, int n_in,
                              void* d_out, int out_size) {
    const float* in_feat = (const float*)d_in[0];
    const int*   src     = (const int*)d_in[1];
    const int*   dst     = (const int*)d_in[2];
    const float* Wc0 = (const float*)d_in[3];
    const float* bc0 = (const float*)d_in[4];
    const float* Wc1 = (const float*)d_in[5];
    const float* bc1 = (const float*)d_in[6];
    const float* Wc2 = (const float*)d_in[7];
    const float* bc2 = (const float*)d_in[8];
    const float* Wr0 = (const float*)d_in[9];
    const float* br0 = (const float*)d_in[10];
    const float* Wr1 = (const float*)d_in[11];
    const float* br1 = (const float*)d_in[12];
    const float* Wr2 = (const float*)d_in[13];
    const float* br2 = (const float*)d_in[14];
    float* out = (float*)d_out;

    float *bufA, *bufB, *bufC, *sout, *sin, *wt;
    cudaGetSymbolAddress((void**)&bufA, g_bufA);
    cudaGetSymbolAddress((void**)&bufB, g_bufB);
    cudaGetSymbolAddress((void**)&bufC, g_bufC);
    cudaGetSymbolAddress((void**)&sout, g_sout);
    cudaGetSymbolAddress((void**)&sin,  g_sin);
    cudaGetSymbolAddress((void**)&wt,   g_wt);

    __nv_bfloat16* bA16 = (__nv_bfloat16*)bufA;
    __nv_bfloat16* bB16 = (__nv_bfloat16*)bufB;
    __nv_bfloat16* WTc0 = (__nv_bfloat16*)(wt + 0 * 65536);
    __nv_bfloat16* WTc1 = (__nv_bfloat16*)(wt + 1 * 65536);
    __nv_bfloat16* WTc2 = (__nv_bfloat16*)(wt + 2 * 65536);
    __nv_bfloat16* WTr0 = (__nv_bfloat16*)(wt + 3 * 65536);
    __nv_bfloat16* WTr1 = (__nv_bfloat16*)(wt + 4 * 65536);
    __nv_bfloat16* WTr2 = (__nv_bfloat16*)(wt + 5 * 65536);

    const int M = NN;
    dim3 g_n((NN + 255) / 256);
    dim3 g_e(4096);
    dim3 g_w((NN * 32 + 255) / 256);
    dim3 g_p((NN * 32 + 255) / 256);
    const int GT = (M + 127) / 128;

    const int SMEM_GEMM = (2 * 128 * 72 + 2 * 64 * 72) * 2;   // 55296 B
    static int attr_done = 0;
    if (!attr_done) {
        cudaFuncSetAttribute(k_gemm_bf16<1, 1>, cudaFuncAttributeMaxDynamicSharedMemorySize, SMEM_GEMM);
        cudaFuncSetAttribute(k_gemm_bf16<0, 1>, cudaFuncAttributeMaxDynamicSharedMemorySize, SMEM_GEMM);
        cudaFuncSetAttribute(k_gemm_bf16<0, 0>, cudaFuncAttributeMaxDynamicSharedMemorySize, SMEM_GEMM);
        attr_done = 1;
    }

    // graph preprocessing
    k_zero_counts<<<g_n, 256>>>();
    k_hist<<<g_e, 256>>>(src, dst);
    k_scan<<<1, 1024>>>();
    k_fill<<<g_e, 256>>>(src, dst);
    k_scales<<<g_n, 256>>>();

    // weight transpose + bf16
    k_transpose_b16<<<dim3(4, 8), dim3(32, 8)>>>(Wc0, WTc0, 128, 256);
    k_transpose_b16<<<dim3(8, 8), dim3(32, 8)>>>(Wc1, WTc1, 256, 256);
    k_transpose_b16<<<dim3(8, 4), dim3(32, 8)>>>(Wc2, WTc2, 256, 128);
    k_transpose_b16<<<dim3(4, 8), dim3(32, 8)>>>(Wr0, WTr0, 128, 256);
    k_transpose_b16<<<dim3(8, 8), dim3(32, 8)>>>(Wr1, WTr1, 256, 256);
    k_transpose_b16<<<dim3(8, 4), dim3(32, 8)>>>(Wr2, WTr2, 256, 128);

    // x_b16 = bf16(in_feat * sout)
    k_prescale<<<g_p, 256>>>(in_feat, bA16);

    // conv1
    k_agg_b16<128, 1><<<g_w, 256>>>(bA16, bB16);
    k_gemm_bf16<1, 1><<<dim3(GT, 4), 256, SMEM_GEMM>>>(bB16, WTc0, bA16, M, 128, 256, sin, bc0, sout);

    // conv2
    k_agg_b16<256, 1><<<g_w, 256>>>(bA16, bB16);
    k_gemm_bf16<1, 1><<<dim3(GT, 4), 256, SMEM_GEMM>>>(bB16, WTc1, bA16, M, 256, 256, sin, bc1, sout);

    // conv3
    k_gemm_bf16<0, 1><<<dim3(GT, 2), 256, SMEM_GEMM>>>(bA16, WTc2, bB16, M, 256, 128, nullptr, nullptr, nullptr);
    k_agg_b16<128, 0><<<g_w, 256>>>(bB16, bufC);
    k_softmax128<<<g_w, 256>>>(bufC, out, bA16, sin, bc2);

    // MLP on h (bf16 copy in bA16)
    k_gemm_bf16<1, 1><<<dim3(GT, 4), 256, SMEM_GEMM>>>(bA16, WTr0, bB16, M, 128, 256, nullptr, br0, nullptr);
    k_gemm_bf16<1, 1><<<dim3(GT, 4), 256, SMEM_GEMM>>>(bB16, WTr1, bA16, M, 256, 256, nullptr, br1, nullptr);
    k_gemm_bf16<0, 0><<<dim3(GT, 2), 256, SMEM_GEMM>>>(bA16, WTr2, bufC, M, 256, 128, nullptr, br2, nullptr);
    k_softmax128<<<g_w, 256>>>(bufC, out + (size_t)M * 128, nullptr, nullptr, nullptr);
}

// round 9
// speedup vs baseline: 2.9215x; 1.0876x over previous
#include <cuda_runtime.h>
#include <cuda_bf16.h>
#include <math.h>
#include <stdint.h>

#define NN 100000
#define EE 1600000

// ---------------- static scratch ----------------
__device__ float g_bufA[(size_t)NN * 256];
__device__ float g_bufB[(size_t)NN * 256];
__device__ float g_bufC[(size_t)NN * 256];
__device__ float g_sout[NN];
__device__ float g_sin[NN];
__device__ int   g_cnt_out[NN];
__device__ int   g_cnt_in[NN];
__device__ int   g_cursor[NN];
__device__ int   g_row_ptr[NN + 1];
__device__ int   g_csr[EE];
__device__ float g_wt[6][65536];

// ---------------- graph preprocessing ----------------
__global__ void k_zero_counts() {
    int i = blockIdx.x * blockDim.x + threadIdx.x;
    if (i < NN) { g_cnt_out[i] = 0; g_cnt_in[i] = 0; g_cursor[i] = 0; }
}
__global__ void k_hist(const int* __restrict__ src, const int* __restrict__ dst) {
    int stride = gridDim.x * blockDim.x;
    for (int i = blockIdx.x * blockDim.x + threadIdx.x; i < EE; i += stride) {
        atomicAdd(&g_cnt_out[src[i]], 1);
        atomicAdd(&g_cnt_in[dst[i]], 1);
    }
}
__global__ void k_scan() {
    __shared__ int wsum[32];
    __shared__ int carry_s;
    int t = threadIdx.x, lane = t & 31, w = t >> 5;
    if (t == 0) carry_s = 0;
    __syncthreads();
    for (int base = 0; base < NN; base += 1024) {
        int idx = base + t;
        int x = (idx < NN) ? g_cnt_in[idx] : 0;
#pragma unroll
        for (int off = 1; off < 32; off <<= 1) {
            int y = __shfl_up_sync(0xffffffffu, x, off);
            if (lane >= off) x += y;
        }
        if (lane == 31) wsum[w] = x;
        __syncthreads();
        if (w == 0) {
            int s = wsum[lane];
#pragma unroll
            for (int off = 1; off < 32; off <<= 1) {
                int y = __shfl_up_sync(0xffffffffu, s, off);
                if (lane >= off) s += y;
            }
            wsum[lane] = s;
        }
        __syncthreads();
        int res = carry_s + ((w > 0) ? wsum[w - 1] : 0) + x;
        if (idx < NN) g_row_ptr[idx + 1] = res;
        __syncthreads();
        if (t == 1023) carry_s = res;
        __syncthreads();
    }
    if (t == 0) g_row_ptr[0] = 0;
}
__global__ void k_fill(const int* __restrict__ src, const int* __restrict__ dst) {
    int stride = gridDim.x * blockDim.x;
    for (int i = blockIdx.x * blockDim.x + threadIdx.x; i < EE; i += stride) {
        int d = dst[i];
        int pos = g_row_ptr[d] + atomicAdd(&g_cursor[d], 1);
        g_csr[pos] = src[i];
    }
}
__global__ void k_scales() {
    int i = blockIdx.x * blockDim.x + threadIdx.x;
    if (i < NN) {
        g_sout[i] = rsqrtf(fmaxf((float)g_cnt_out[i], 1.f));
        g_sin[i]  = rsqrtf(fmaxf((float)g_cnt_in[i], 1.f));
    }
}

// all 6 weight transposes in one launch (blockIdx.z selects weight)
__global__ void k_transpose_all(
    const float* W0, const float* W1, const float* W2,
    const float* W3, const float* W4, const float* W5,
    __nv_bfloat16* T0, __nv_bfloat16* T1, __nv_bfloat16* T2,
    __nv_bfloat16* T3, __nv_bfloat16* T4, __nv_bfloat16* T5) {
    __shared__ float t[32][33];
    const float* W; __nv_bfloat16* WT; int K, N;
    switch (blockIdx.z) {
        case 0: W = W0; WT = T0; K = 128; N = 256; break;
        case 1: W = W1; WT = T1; K = 256; N = 256; break;
        case 2: W = W2; WT = T2; K = 256; N = 128; break;
        case 3: W = W3; WT = T3; K = 128; N = 256; break;
        case 4: W = W4; WT = T4; K = 256; N = 256; break;
        default: W = W5; WT = T5; K = 256; N = 128; break;
    }
    int k0 = blockIdx.x * 32, n0 = blockIdx.y * 32;
    if (k0 >= K || n0 >= N) return;
    int x = threadIdx.x, y = threadIdx.y;
    for (int i = 0; i < 32; i += 8) {
        int k = k0 + y + i, n = n0 + x;
        t[y + i][x] = (k < K && n < N) ? W[(size_t)k * N + n] : 0.f;
    }
    __syncthreads();
    for (int i = 0; i < 32; i += 8) {
        int n = n0 + y + i, k = k0 + x;
        if (n < N && k < K) WT[(size_t)n * K + k] = __float2bfloat16(t[x][y + i]);
    }
}

// prescale in_feat by sout -> bf16
__global__ void k_prescale(const float* __restrict__ x, __nv_bfloat16* __restrict__ o) {
    int i = blockIdx.x * blockDim.x + threadIdx.x;
    if (i >= NN * 32) return;
    int m = i >> 5;
    float s = g_sout[m];
    float4 v = ((const float4*)x)[i];
    uint2 r;
    __nv_bfloat162 p0 = __float22bfloat162_rn(make_float2(v.x * s, v.y * s));
    __nv_bfloat162 p1 = __float22bfloat162_rn(make_float2(v.z * s, v.w * s));
    r.x = *(uint32_t*)&p0; r.y = *(uint32_t*)&p1;
    ((uint2*)o)[i] = r;
}

// ---------------- aggregation (bf16 gather, fp32 accumulate) ----------------
template <int D, int OUTB>
__global__ void k_agg_b16(const __nv_bfloat16* __restrict__ x, void* __restrict__ out) {
    int warp = (blockIdx.x * blockDim.x + threadIdx.x) >> 5;
    int lane = threadIdx.x & 31;
    if (warp >= NN) return;
    int s0 = g_row_ptr[warp], s1 = g_row_ptr[warp + 1];

    if (D == 128) {
        float4 a0 = make_float4(0.f, 0.f, 0.f, 0.f);
        float4 a1 = make_float4(0.f, 0.f, 0.f, 0.f);
        for (int base = s0; base < s1; base += 32) {
            int cnt = min(32, s1 - base);
            int myidx = (lane < cnt) ? g_csr[base + lane] : 0;
            int e = 0;
            for (; e + 2 <= cnt; e += 2) {
                int sa = __shfl_sync(0xffffffffu, myidx, e);
                int sb = __shfl_sync(0xffffffffu, myidx, e + 1);
                uint2 va = ((const uint2*)(x + (size_t)sa * 128))[lane];
                uint2 vb = ((const uint2*)(x + (size_t)sb * 128))[lane];
                __nv_bfloat162 p0 = *(__nv_bfloat162*)&va.x;
                __nv_bfloat162 p1 = *(__nv_bfloat162*)&va.y;
                a0.x += __low2float(p0); a0.y += __high2float(p0);
                a0.z += __low2float(p1); a0.w += __high2float(p1);
                __nv_bfloat162 q0 = *(__nv_bfloat162*)&vb.x;
                __nv_bfloat162 q1 = *(__nv_bfloat162*)&vb.y;
                a1.x += __low2float(q0); a1.y += __high2float(q0);
                a1.z += __low2float(q1); a1.w += __high2float(q1);
            }
            if (e < cnt) {
                int sa = __shfl_sync(0xffffffffu, myidx, e);
                uint2 va = ((const uint2*)(x + (size_t)sa * 128))[lane];
                __nv_bfloat162 p0 = *(__nv_bfloat162*)&va.x;
                __nv_bfloat162 p1 = *(__nv_bfloat162*)&va.y;
                a0.x += __low2float(p0); a0.y += __high2float(p0);
                a0.z += __low2float(p1); a0.w += __high2float(p1);
            }
        }
        float4 acc = make_float4(a0.x + a1.x, a0.y + a1.y, a0.z + a1.z, a0.w + a1.w);
        if (OUTB) {
            uint2 r;
            __nv_bfloat162 p0 = __float22bfloat162_rn(make_float2(acc.x, acc.y));
            __nv_bfloat162 p1 = __float22bfloat162_rn(make_float2(acc.z, acc.w));
            r.x = *(uint32_t*)&p0; r.y = *(uint32_t*)&p1;
            ((uint2*)out)[(size_t)warp * 32 + lane] = r;
        } else {
            ((float4*)out)[(size_t)warp * 32 + lane] = acc;
        }
    } else {  // D == 256
        float a0[8], a1[8];
#pragma unroll
        for (int j = 0; j < 8; j++) { a0[j] = 0.f; a1[j] = 0.f; }
        for (int base = s0; base < s1; base += 32) {
            int cnt = min(32, s1 - base);
            int myidx = (lane < cnt) ? g_csr[base + lane] : 0;
            int e = 0;
            for (; e + 2 <= cnt; e += 2) {
                int sa = __shfl_sync(0xffffffffu, myidx, e);
                int sb = __shfl_sync(0xffffffffu, myidx, e + 1);
                uint4 va = ((const uint4*)(x + (size_t)sa * 256))[lane];
                uint4 vb = ((const uint4*)(x + (size_t)sb * 256))[lane];
                {
                    __nv_bfloat162 p0 = *(__nv_bfloat162*)&va.x, p1 = *(__nv_bfloat162*)&va.y;
                    __nv_bfloat162 p2 = *(__nv_bfloat162*)&va.z, p3 = *(__nv_bfloat162*)&va.w;
                    a0[0] += __low2float(p0); a0[1] += __high2float(p0);
                    a0[2] += __low2float(p1); a0[3] += __high2float(p1);
                    a0[4] += __low2float(p2); a0[5] += __high2float(p2);
                    a0[6] += __low2float(p3); a0[7] += __high2float(p3);
                }
                {
                    __nv_bfloat162 p0 = *(__nv_bfloat162*)&vb.x, p1 = *(__nv_bfloat162*)&vb.y;
                    __nv_bfloat162 p2 = *(__nv_bfloat162*)&vb.z, p3 = *(__nv_bfloat162*)&vb.w;
                    a1[0] += __low2float(p0); a1[1] += __high2float(p0);
                    a1[2] += __low2float(p1); a1[3] += __high2float(p1);
                    a1[4] += __low2float(p2); a1[5] += __high2float(p2);
                    a1[6] += __low2float(p3); a1[7] += __high2float(p3);
                }
            }
            if (e < cnt) {
                int sa = __shfl_sync(0xffffffffu, myidx, e);
                uint4 va = ((const uint4*)(x + (size_t)sa * 256))[lane];
                __nv_bfloat162 p0 = *(__nv_bfloat162*)&va.x, p1 = *(__nv_bfloat162*)&va.y;
                __nv_bfloat162 p2 = *(__nv_bfloat162*)&va.z, p3 = *(__nv_bfloat162*)&va.w;
                a0[0] += __low2float(p0); a0[1] += __high2float(p0);
                a0[2] += __low2float(p1); a0[3] += __high2float(p1);
                a0[4] += __low2float(p2); a0[5] += __high2float(p2);
                a0[6] += __low2float(p3); a0[7] += __high2float(p3);
            }
        }
        uint4 r;
        __nv_bfloat162 q0 = __float22bfloat162_rn(make_float2(a0[0] + a1[0], a0[1] + a1[1]));
        __nv_bfloat162 q1 = __float22bfloat162_rn(make_float2(a0[2] + a1[2], a0[3] + a1[3]));
        __nv_bfloat162 q2 = __float22bfloat162_rn(make_float2(a0[4] + a1[4], a0[5] + a1[5]));
        __nv_bfloat162 q3 = __float22bfloat162_rn(make_float2(a0[6] + a1[6], a0[7] + a1[7]));
        r.x = *(uint32_t*)&q0; r.y = *(uint32_t*)&q1;
        r.z = *(uint32_t*)&q2; r.w = *(uint32_t*)&q3;
        ((uint4*)out)[(size_t)warp * 32 + lane] = r;
    }
}

// conv3: aggregate(D=128) then fused scale+bias+softmax, dual fp32 + bf16 output
__global__ void k_agg_smax128(const __nv_bfloat16* __restrict__ x,
                              float* __restrict__ out, __nv_bfloat16* __restrict__ outb,
                              const float* __restrict__ rowscale, const float* __restrict__ bias) {
    int warp = (blockIdx.x * blockDim.x + threadIdx.x) >> 5;
    int lane = threadIdx.x & 31;
    if (warp >= NN) return;
    int s0 = g_row_ptr[warp], s1 = g_row_ptr[warp + 1];
    float4 a0 = make_float4(0.f, 0.f, 0.f, 0.f);
    float4 a1 = make_float4(0.f, 0.f, 0.f, 0.f);
    for (int base = s0; base < s1; base += 32) {
        int cnt = min(32, s1 - base);
        int myidx = (lane < cnt) ? g_csr[base + lane] : 0;
        int e = 0;
        for (; e + 2 <= cnt; e += 2) {
            int sa = __shfl_sync(0xffffffffu, myidx, e);
            int sb = __shfl_sync(0xffffffffu, myidx, e + 1);
            uint2 va = ((const uint2*)(x + (size_t)sa * 128))[lane];
            uint2 vb = ((const uint2*)(x + (size_t)sb * 128))[lane];
            __nv_bfloat162 p0 = *(__nv_bfloat162*)&va.x;
            __nv_bfloat162 p1 = *(__nv_bfloat162*)&va.y;
            a0.x += __low2float(p0); a0.y += __high2float(p0);
            a0.z += __low2float(p1); a0.w += __high2float(p1);
            __nv_bfloat162 q0 = *(__nv_bfloat162*)&vb.x;
            __nv_bfloat162 q1 = *(__nv_bfloat162*)&vb.y;
            a1.x += __low2float(q0); a1.y += __high2float(q0);
            a1.z += __low2float(q1); a1.w += __high2float(q1);
        }
        if (e < cnt) {
            int sa = __shfl_sync(0xffffffffu, myidx, e);
            uint2 va = ((const uint2*)(x + (size_t)sa * 128))[lane];
            __nv_bfloat162 p0 = *(__nv_bfloat162*)&va.x;
            __nv_bfloat162 p1 = *(__nv_bfloat162*)&va.y;
            a0.x += __low2float(p0); a0.y += __high2float(p0);
            a0.z += __low2float(p1); a0.w += __high2float(p1);
        }
    }
    float4 v = make_float4(a0.x + a1.x, a0.y + a1.y, a0.z + a1.z, a0.w + a1.w);
    float rs = rowscale[warp];
    float4 b = ((const float4*)bias)[lane];
    v.x = v.x * rs + b.x; v.y = v.y * rs + b.y;
    v.z = v.z * rs + b.z; v.w = v.w * rs + b.w;
    float m = fmaxf(fmaxf(v.x, v.y), fmaxf(v.z, v.w));
#pragma unroll
    for (int off = 16; off > 0; off >>= 1) m = fmaxf(m, __shfl_xor_sync(0xffffffffu, m, off));
    v.x = expf(v.x - m); v.y = expf(v.y - m);
    v.z = expf(v.z - m); v.w = expf(v.w - m);
    float s = v.x + v.y + v.z + v.w;
#pragma unroll
    for (int off = 16; off > 0; off >>= 1) s += __shfl_xor_sync(0xffffffffu, s, off);
    float inv = 1.f / s;
    v.x *= inv; v.y *= inv; v.z *= inv; v.w *= inv;
    ((float4*)out)[(size_t)warp * 32 + lane] = v;
    uint2 r;
    __nv_bfloat162 p0 = __float22bfloat162_rn(make_float2(v.x, v.y));
    __nv_bfloat162 p1 = __float22bfloat162_rn(make_float2(v.z, v.w));
    r.x = *(uint32_t*)&p0; r.y = *(uint32_t*)&p1;
    ((uint2*)outb)[(size_t)warp * 32 + lane] = r;
}

// ---------------- bf16 tensor-core GEMM, BN=128, cp.async 2-stage ----------------
__device__ __forceinline__ void mma_bf16(float* d, const uint32_t* a, const uint32_t* b) {
    asm volatile(
        "mma.sync.aligned.m16n8k16.row.col.f32.bf16.bf16.f32 "
        "{%0,%1,%2,%3}, {%4,%5,%6,%7}, {%8,%9}, {%0,%1,%2,%3};"
        : "+f"(d[0]), "+f"(d[1]), "+f"(d[2]), "+f"(d[3])
        : "r"(a[0]), "r"(a[1]), "r"(a[2]), "r"(a[3]), "r"(b[0]), "r"(b[1]));
}
__device__ __forceinline__ void cp16(uint32_t dst, const void* src, int sz) {
    asm volatile("cp.async.cg.shared.global [%0], [%1], 16, %2;" :: "r"(dst), "l"(src), "r"(sz) : "memory");
}
#define CP_COMMIT() asm volatile("cp.async.commit_group;" ::: "memory")

// CTA tile 128x128; 8 warps (4 wm x 2 wn); warp tile 32x64.
// ACT: 0 none, 1 tanh, 2 row-softmax (requires N==128, gridDim.y==1, OUTB=0)
template <int ACT, int OUTB>
__global__ void __launch_bounds__(256)
k_gemm_bf16(const __nv_bfloat16* __restrict__ A, const __nv_bfloat16* __restrict__ WT,
            void* __restrict__ Cout, int M, int K, int N,
            const float* __restrict__ prescale, const float* __restrict__ bias,
            const float* __restrict__ postscale) {
    extern __shared__ __nv_bfloat16 sm[];
    constexpr int AW = 128 * 72;
    constexpr int BW = 128 * 72;
    __nv_bfloat16* As = sm;
    __nv_bfloat16* Bs = sm + 2 * AW;
    uint32_t sA = (uint32_t)__cvta_generic_to_shared(As);
    uint32_t sB = (uint32_t)__cvta_generic_to_shared(Bs);

    int tid = threadIdx.x;
    int warp = tid >> 5, lane = tid & 31;
    int g = lane >> 2, t = lane & 3;
    int wm = warp >> 1, wn = warp & 1;
    int bm = blockIdx.x * 128, bn = blockIdx.y * 128;
    int lrow = tid >> 3, lq = tid & 7;

    float acc[2][8][4];
#pragma unroll
    for (int mt = 0; mt < 2; mt++)
#pragma unroll
        for (int nt = 0; nt < 8; nt++)
#pragma unroll
            for (int j = 0; j < 4; j++) acc[mt][nt][j] = 0.f;

    const int T = K >> 6;

    auto load_tile = [&](int stage, int kt) {
#pragma unroll
        for (int i = 0; i < 4; i++) {
            int row = lrow + i * 32;
            int gm = bm + row;
            cp16(sA + (uint32_t)(stage * AW + row * 72 + lq * 8) * 2,
                 A + (size_t)gm * K + kt + lq * 8, (gm < M) ? 16 : 0);
        }
#pragma unroll
        for (int i = 0; i < 4; i++) {
            int row = lrow + i * 32;
            cp16(sB + (uint32_t)(stage * BW + row * 72 + lq * 8) * 2,
                 WT + (size_t)(bn + row) * K + kt + lq * 8, 16);
        }
    };

    load_tile(0, 0);
    CP_COMMIT();

    for (int ti = 0; ti < T; ti++) {
        if (ti + 1 < T) {
            load_tile((ti + 1) & 1, (ti + 1) * 64);
            CP_COMMIT();
            asm volatile("cp.async.wait_group 1;" ::: "memory");
        } else {
            asm volatile("cp.async.wait_group 0;" ::: "memory");
        }
        __syncthreads();

        const uint32_t* Asu = (const uint32_t*)(As + (ti & 1) * AW);
        const uint32_t* Bsu = (const uint32_t*)(Bs + (ti & 1) * BW);
#pragma unroll
        for (int k16 = 0; k16 < 4; k16++) {
            int kw = k16 * 8;
            uint32_t a[2][4];
#pragma unroll
            for (int mt = 0; mt < 2; mt++) {
                int r0 = (wm * 32 + mt * 16 + g) * 36 + kw + t;
                a[mt][0] = Asu[r0];
                a[mt][1] = Asu[r0 + 8 * 36];
                a[mt][2] = Asu[r0 + 4];
                a[mt][3] = Asu[r0 + 8 * 36 + 4];
            }
            uint32_t b[8][2];
#pragma unroll
            for (int nt = 0; nt < 8; nt++) {
                int r0 = (wn * 64 + nt * 8 + g) * 36 + kw + t;
                b[nt][0] = Bsu[r0];
                b[nt][1] = Bsu[r0 + 4];
            }
#pragma unroll
            for (int mt = 0; mt < 2; mt++)
#pragma unroll
                for (int nt = 0; nt < 8; nt++)
                    mma_bf16(acc[mt][nt], a[mt], b[nt]);
        }
        __syncthreads();
    }

    // ---- epilogue ----
    float2 bv[8];
#pragma unroll
    for (int nt = 0; nt < 8; nt++) {
        if (bias) bv[nt] = *(const float2*)(bias + bn + wn * 64 + nt * 8 + 2 * t);
        else bv[nt] = make_float2(0.f, 0.f);
    }

    if (ACT == 2) {
        // fused row softmax (N == 128, full row in CTA)
        float* red = (float*)sm;
        float Mx[2][2];
        // pass 1: transform in place + row max
#pragma unroll
        for (int mt = 0; mt < 2; mt++) {
#pragma unroll
            for (int h = 0; h < 2; h++) {
                int gm = bm + wm * 32 + mt * 16 + h * 8 + g;
                float pre = (prescale && gm < M) ? prescale[gm] : 1.f;
                float lm = -1e30f;
#pragma unroll
                for (int nt = 0; nt < 8; nt++) {
                    float ox = acc[mt][nt][2 * h]     * pre + bv[nt].x;
                    float oy = acc[mt][nt][2 * h + 1] * pre + bv[nt].y;
                    acc[mt][nt][2 * h] = ox; acc[mt][nt][2 * h + 1] = oy;
                    lm = fmaxf(lm, fmaxf(ox, oy));
                }
                lm = fmaxf(lm, __shfl_xor_sync(0xffffffffu, lm, 1));
                lm = fmaxf(lm, __shfl_xor_sync(0xffffffffu, lm, 2));
                int r = wm * 32 + mt * 16 + h * 8 + g;
                if (t == 0) red[r * 2 + wn] = lm;
            }
        }
        __syncthreads();
#pragma unroll
        for (int mt = 0; mt < 2; mt++)
#pragma unroll
            for (int h = 0; h < 2; h++) {
                int r = wm * 32 + mt * 16 + h * 8 + g;
                Mx[mt][h] = fmaxf(red[r * 2], red[r * 2 + 1]);
            }
        __syncthreads();
        // pass 2: exp + row sum
#pragma unroll
        for (int mt = 0; mt < 2; mt++) {
#pragma unroll
            for (int h = 0; h < 2; h++) {
                float ls = 0.f;
#pragma unroll
                for (int nt = 0; nt < 8; nt++) {
                    float ex = expf(acc[mt][nt][2 * h]     - Mx[mt][h]);
                    float ey = expf(acc[mt][nt][2 * h + 1] - Mx[mt][h]);
                    acc[mt][nt][2 * h] = ex; acc[mt][nt][2 * h + 1] = ey;
                    ls += ex + ey;
                }
                ls += __shfl_xor_sync(0xffffffffu, ls, 1);
                ls += __shfl_xor_sync(0xffffffffu, ls, 2);
                int r = wm * 32 + mt * 16 + h * 8 + g;
                if (t == 0) red[r * 2 + wn] = ls;
            }
        }
        __syncthreads();
#pragma unroll
        for (int mt = 0; mt < 2; mt++) {
#pragma unroll
            for (int h = 0; h < 2; h++) {
                int r = wm * 32 + mt * 16 + h * 8 + g;
                float inv = 1.f / (red[r * 2] + red[r * 2 + 1]);
                int gm = bm + wm * 32 + mt * 16 + h * 8 + g;
                if (gm >= M) continue;
#pragma unroll
                for (int nt = 0; nt < 8; nt++) {
                    float2 o = make_float2(acc[mt][nt][2 * h] * inv, acc[mt][nt][2 * h + 1] * inv);
                    *(float2*)((float*)Cout + (size_t)gm * N + bn + wn * 64 + nt * 8 + 2 * t) = o;
                }
            }
        }
        return;
    }

#pragma unroll
    for (int mt = 0; mt < 2; mt++) {
#pragma unroll
        for (int h = 0; h < 2; h++) {
            int gm = bm + wm * 32 + mt * 16 + h * 8 + g;
            if (gm >= M) continue;
            float pre = prescale ? prescale[gm] : 1.f;
            float post = postscale ? postscale[gm] : 1.f;
#pragma unroll
            for (int nt = 0; nt < 8; nt++) {
                float ox = acc[mt][nt][2 * h]     * pre + bv[nt].x;
                float oy = acc[mt][nt][2 * h + 1] * pre + bv[nt].y;
                if (ACT == 1) { ox = tanhf(ox); oy = tanhf(oy); }
                ox *= post; oy *= post;
                size_t off = (size_t)gm * N + bn + wn * 64 + nt * 8 + 2 * t;
                if (OUTB) {
                    __nv_bfloat162 p = __float22bfloat162_rn(make_float2(ox, oy));
                    *(uint32_t*)((__nv_bfloat16*)Cout + off) = *(uint32_t*)&p;
                } else {
                    *(float2*)((float*)Cout + off) = make_float2(ox, oy);
                }
            }
        }
    }
}

// ---------------- launcher ----------------
extern "C" void kernel_launch(void* const* d_in, const int* in_sizes, int n_in,
                              void* d_out, int out_size) {
    const float* in_feat = (const float*)d_in[0];
    const int*   src     = (const int*)d_in[1];
    const int*   dst     = (const int*)d_in[2];
    const float* Wc0 = (const float*)d_in[3];
    const float* bc0 = (const float*)d_in[4];
    const float* Wc1 = (const float*)d_in[5];
    const float* bc1 = (const float*)d_in[6];
    const float* Wc2 = (const float*)d_in[7];
    const float* bc2 = (const float*)d_in[8];
    const float* Wr0 = (const float*)d_in[9];
    const float* br0 = (const float*)d_in[10];
    const float* Wr1 = (const float*)d_in[11];
    const float* br1 = (const float*)d_in[12];
    const float* Wr2 = (const float*)d_in[13];
    const float* br2 = (const float*)d_in[14];
    float* out = (float*)d_out;

    float *bufA, *bufB, *bufC, *sout, *sin, *wt;
    cudaGetSymbolAddress((void**)&bufA, g_bufA);
    cudaGetSymbolAddress((void**)&bufB, g_bufB);
    cudaGetSymbolAddress((void**)&bufC, g_bufC);
    cudaGetSymbolAddress((void**)&sout, g_sout);
    cudaGetSymbolAddress((void**)&sin,  g_sin);
    cudaGetSymbolAddress((void**)&wt,   g_wt);

    __nv_bfloat16* bA16 = (__nv_bfloat16*)bufA;
    __nv_bfloat16* bB16 = (__nv_bfloat16*)bufB;
    __nv_bfloat16* WTc0 = (__nv_bfloat16*)(wt + 0 * 65536);
    __nv_bfloat16* WTc1 = (__nv_bfloat16*)(wt + 1 * 65536);
    __nv_bfloat16* WTc2 = (__nv_bfloat16*)(wt + 2 * 65536);
    __nv_bfloat16* WTr0 = (__nv_bfloat16*)(wt + 3 * 65536);
    __nv_bfloat16* WTr1 = (__nv_bfloat16*)(wt + 4 * 65536);
    __nv_bfloat16* WTr2 = (__nv_bfloat16*)(wt + 5 * 65536);

    const int M = NN;
    dim3 g_n((NN + 255) / 256);
    dim3 g_e(4096);
    dim3 g_w((NN * 32 + 255) / 256);
    const int GT = (M + 127) / 128;

    const int SMEM_GEMM = (2 * 128 * 72 + 2 * 128 * 72) * 2;   // 73728 B
    static int attr_done = 0;
    if (!attr_done) {
        cudaFuncSetAttribute(k_gemm_bf16<1, 1>, cudaFuncAttributeMaxDynamicSharedMemorySize, SMEM_GEMM);
        cudaFuncSetAttribute(k_gemm_bf16<0, 1>, cudaFuncAttributeMaxDynamicSharedMemorySize, SMEM_GEMM);
        cudaFuncSetAttribute(k_gemm_bf16<2, 0>, cudaFuncAttributeMaxDynamicSharedMemorySize, SMEM_GEMM);
        attr_done = 1;
    }

    // graph preprocessing
    k_zero_counts<<<g_n, 256>>>();
    k_hist<<<g_e, 256>>>(src, dst);
    k_scan<<<1, 1024>>>();
    k_fill<<<g_e, 256>>>(src, dst);
    k_scales<<<g_n, 256>>>();

    // weights: transpose + bf16, one launch
    k_transpose_all<<<dim3(8, 8, 6), dim3(32, 8)>>>(Wc0, Wc1, Wc2, Wr0, Wr1, Wr2,
                                                    WTc0, WTc1, WTc2, WTr0, WTr1, WTr2);

    // x_b16 = bf16(in_feat * sout)
    k_prescale<<<g_w, 256>>>(in_feat, bA16);

    // conv1: agg(128) -> GEMM 128->256: tanh(acc*sin + bc0) * sout -> bf16
    k_agg_b16<128, 1><<<g_w, 256>>>(bA16, bB16);
    k_gemm_bf16<1, 1><<<dim3(GT, 2), 256, SMEM_GEMM>>>(bB16, WTc0, bA16, M, 128, 256, sin, bc0, sout);

    // conv2: agg(256) -> GEMM 256->256: tanh(acc*sin + bc1) * sout -> bf16
    k_agg_b16<256, 1><<<g_w, 256>>>(bA16, bB16);
    k_gemm_bf16<1, 1><<<dim3(GT, 2), 256, SMEM_GEMM>>>(bB16, WTc1, bA16, M, 256, 256, sin, bc1, sout);

    // conv3: GEMM 256->128 -> bf16, then agg(128) + fused scale/bias/softmax -> out + bf16
    k_gemm_bf16<0, 1><<<dim3(GT, 1), 256, SMEM_GEMM>>>(bA16, WTc2, bB16, M, 256, 128, nullptr, nullptr, nullptr);
    k_agg_smax128<<<g_w, 256>>>(bB16, out, bA16, sin, bc2);

    // MLP on h (bf16 copy in bA16)
    k_gemm_bf16<1, 1><<<dim3(GT, 2), 256, SMEM_GEMM>>>(bA16, WTr0, bB16, M, 128, 256, nullptr, br0, nullptr);
    k_gemm_bf16<1, 1><<<dim3(GT, 2), 256, SMEM_GEMM>>>(bB16, WTr1, bA16, M, 256, 256, nullptr, br1, nullptr);
    k_gemm_bf16<2, 0><<<dim3(GT, 1), 256, SMEM_GEMM>>>(bA16, WTr2, out + (size_t)M * 128, M, 256, 128, nullptr, br2, nullptr);
}

// round 10
// speedup vs baseline: 3.0618x; 1.0480x over previous
#include <cuda_runtime.h>
#include <cuda_bf16.h>
#include <math.h>
#include <stdint.h>

#define NN 100000
#define EE 1600000
#define CH0 50048
#define CH1 (NN - CH0)

// ---------------- static scratch ----------------
__device__ float g_bufA[(size_t)NN * 256];
__device__ float g_bufB[(size_t)NN * 256];
__device__ float g_bufC[(size_t)NN * 256];
__device__ float g_sout[NN];
__device__ float g_sin[NN];
__device__ int   g_cnt_out[NN];
__device__ int   g_cnt_in[NN];
__device__ int   g_cursor[NN];
__device__ int   g_row_ptr[NN + 1];
__device__ int   g_csr[EE];
__device__ float g_wt[6][65536];

// ---------------- graph preprocessing ----------------
__global__ void k_zero_counts() {
    int i = blockIdx.x * blockDim.x + threadIdx.x;
    if (i < NN) { g_cnt_out[i] = 0; g_cnt_in[i] = 0; g_cursor[i] = 0; }
}
__global__ void k_hist(const int* __restrict__ src, const int* __restrict__ dst) {
    int stride = gridDim.x * blockDim.x;
    for (int i = blockIdx.x * blockDim.x + threadIdx.x; i < EE; i += stride) {
        atomicAdd(&g_cnt_out[src[i]], 1);
        atomicAdd(&g_cnt_in[dst[i]], 1);
    }
}
__global__ void k_scan() {
    __shared__ int wsum[32];
    __shared__ int carry_s;
    int t = threadIdx.x, lane = t & 31, w = t >> 5;
    if (t == 0) carry_s = 0;
    __syncthreads();
    for (int base = 0; base < NN; base += 1024) {
        int idx = base + t;
        int x = (idx < NN) ? g_cnt_in[idx] : 0;
#pragma unroll
        for (int off = 1; off < 32; off <<= 1) {
            int y = __shfl_up_sync(0xffffffffu, x, off);
            if (lane >= off) x += y;
        }
        if (lane == 31) wsum[w] = x;
        __syncthreads();
        if (w == 0) {
            int s = wsum[lane];
#pragma unroll
            for (int off = 1; off < 32; off <<= 1) {
                int y = __shfl_up_sync(0xffffffffu, s, off);
                if (lane >= off) s += y;
            }
            wsum[lane] = s;
        }
        __syncthreads();
        int res = carry_s + ((w > 0) ? wsum[w - 1] : 0) + x;
        if (idx < NN) g_row_ptr[idx + 1] = res;
        __syncthreads();
        if (t == 1023) carry_s = res;
        __syncthreads();
    }
    if (t == 0) g_row_ptr[0] = 0;
}
__global__ void k_fill(const int* __restrict__ src, const int* __restrict__ dst) {
    int stride = gridDim.x * blockDim.x;
    for (int i = blockIdx.x * blockDim.x + threadIdx.x; i < EE; i += stride) {
        int d = dst[i];
        int pos = g_row_ptr[d] + atomicAdd(&g_cursor[d], 1);
        g_csr[pos] = src[i];
    }
}
__global__ void k_scales() {
    int i = blockIdx.x * blockDim.x + threadIdx.x;
    if (i < NN) {
        g_sout[i] = rsqrtf(fmaxf((float)g_cnt_out[i], 1.f));
        g_sin[i]  = rsqrtf(fmaxf((float)g_cnt_in[i], 1.f));
    }
}

// all 6 weight transposes in one launch
__global__ void k_transpose_all(
    const float* W0, const float* W1, const float* W2,
    const float* W3, const float* W4, const float* W5,
    __nv_bfloat16* T0, __nv_bfloat16* T1, __nv_bfloat16* T2,
    __nv_bfloat16* T3, __nv_bfloat16* T4, __nv_bfloat16* T5) {
    __shared__ float t[32][33];
    const float* W; __nv_bfloat16* WT; int K, N;
    switch (blockIdx.z) {
        case 0: W = W0; WT = T0; K = 128; N = 256; break;
        case 1: W = W1; WT = T1; K = 256; N = 256; break;
        case 2: W = W2; WT = T2; K = 256; N = 128; break;
        case 3: W = W3; WT = T3; K = 128; N = 256; break;
        case 4: W = W4; WT = T4; K = 256; N = 256; break;
        default: W = W5; WT = T5; K = 256; N = 128; break;
    }
    int k0 = blockIdx.x * 32, n0 = blockIdx.y * 32;
    if (k0 >= K || n0 >= N) return;
    int x = threadIdx.x, y = threadIdx.y;
    for (int i = 0; i < 32; i += 8) {
        int k = k0 + y + i, n = n0 + x;
        t[y + i][x] = (k < K && n < N) ? W[(size_t)k * N + n] : 0.f;
    }
    __syncthreads();
    for (int i = 0; i < 32; i += 8) {
        int n = n0 + y + i, k = k0 + x;
        if (n < N && k < K) WT[(size_t)n * K + k] = __float2bfloat16(t[x][y + i]);
    }
}

// prescale in_feat by sout -> bf16
__global__ void k_prescale(const float* __restrict__ x, __nv_bfloat16* __restrict__ o) {
    int i = blockIdx.x * blockDim.x + threadIdx.x;
    if (i >= NN * 32) return;
    int m = i >> 5;
    float s = g_sout[m];
    float4 v = ((const float4*)x)[i];
    uint2 r;
    __nv_bfloat162 p0 = __float22bfloat162_rn(make_float2(v.x * s, v.y * s));
    __nv_bfloat162 p1 = __float22bfloat162_rn(make_float2(v.z * s, v.w * s));
    r.x = *(uint32_t*)&p0; r.y = *(uint32_t*)&p1;
    ((uint2*)o)[i] = r;
}

// ---------------- aggregation (bf16 gather, fp32 accumulate), node range [n0, n0+cnt) ----------------
template <int D, int OUTB>
__global__ void k_agg_b16(const __nv_bfloat16* __restrict__ x, void* __restrict__ out,
                          int n0, int ncnt) {
    int wloc = (blockIdx.x * blockDim.x + threadIdx.x) >> 5;
    int lane = threadIdx.x & 31;
    if (wloc >= ncnt) return;
    int node = n0 + wloc;
    int s0 = g_row_ptr[node], s1 = g_row_ptr[node + 1];

    if (D == 128) {
        float4 a0 = make_float4(0.f, 0.f, 0.f, 0.f);
        float4 a1 = make_float4(0.f, 0.f, 0.f, 0.f);
        for (int base = s0; base < s1; base += 32) {
            int cnt = min(32, s1 - base);
            int myidx = (lane < cnt) ? g_csr[base + lane] : 0;
            int e = 0;
            for (; e + 2 <= cnt; e += 2) {
                int sa = __shfl_sync(0xffffffffu, myidx, e);
                int sb = __shfl_sync(0xffffffffu, myidx, e + 1);
                uint2 va = ((const uint2*)(x + (size_t)sa * 128))[lane];
                uint2 vb = ((const uint2*)(x + (size_t)sb * 128))[lane];
                __nv_bfloat162 p0 = *(__nv_bfloat162*)&va.x;
                __nv_bfloat162 p1 = *(__nv_bfloat162*)&va.y;
                a0.x += __low2float(p0); a0.y += __high2float(p0);
                a0.z += __low2float(p1); a0.w += __high2float(p1);
                __nv_bfloat162 q0 = *(__nv_bfloat162*)&vb.x;
                __nv_bfloat162 q1 = *(__nv_bfloat162*)&vb.y;
                a1.x += __low2float(q0); a1.y += __high2float(q0);
                a1.z += __low2float(q1); a1.w += __high2float(q1);
            }
            if (e < cnt) {
                int sa = __shfl_sync(0xffffffffu, myidx, e);
                uint2 va = ((const uint2*)(x + (size_t)sa * 128))[lane];
                __nv_bfloat162 p0 = *(__nv_bfloat162*)&va.x;
                __nv_bfloat162 p1 = *(__nv_bfloat162*)&va.y;
                a0.x += __low2float(p0); a0.y += __high2float(p0);
                a0.z += __low2float(p1); a0.w += __high2float(p1);
            }
        }
        float4 acc = make_float4(a0.x + a1.x, a0.y + a1.y, a0.z + a1.z, a0.w + a1.w);
        if (OUTB) {
            uint2 r;
            __nv_bfloat162 p0 = __float22bfloat162_rn(make_float2(acc.x, acc.y));
            __nv_bfloat162 p1 = __float22bfloat162_rn(make_float2(acc.z, acc.w));
            r.x = *(uint32_t*)&p0; r.y = *(uint32_t*)&p1;
            ((uint2*)out)[(size_t)node * 32 + lane] = r;
        } else {
            ((float4*)out)[(size_t)node * 32 + lane] = acc;
        }
    } else {  // D == 256
        float a0[8], a1[8];
#pragma unroll
        for (int j = 0; j < 8; j++) { a0[j] = 0.f; a1[j] = 0.f; }
        for (int base = s0; base < s1; base += 32) {
            int cnt = min(32, s1 - base);
            int myidx = (lane < cnt) ? g_csr[base + lane] : 0;
            int e = 0;
            for (; e + 2 <= cnt; e += 2) {
                int sa = __shfl_sync(0xffffffffu, myidx, e);
                int sb = __shfl_sync(0xffffffffu, myidx, e + 1);
                uint4 va = ((const uint4*)(x + (size_t)sa * 256))[lane];
                uint4 vb = ((const uint4*)(x + (size_t)sb * 256))[lane];
                {
                    __nv_bfloat162 p0 = *(__nv_bfloat162*)&va.x, p1 = *(__nv_bfloat162*)&va.y;
                    __nv_bfloat162 p2 = *(__nv_bfloat162*)&va.z, p3 = *(__nv_bfloat162*)&va.w;
                    a0[0] += __low2float(p0); a0[1] += __high2float(p0);
                    a0[2] += __low2float(p1); a0[3] += __high2float(p1);
                    a0[4] += __low2float(p2); a0[5] += __high2float(p2);
                    a0[6] += __low2float(p3); a0[7] += __high2float(p3);
                }
                {
                    __nv_bfloat162 p0 = *(__nv_bfloat162*)&vb.x, p1 = *(__nv_bfloat162*)&vb.y;
                    __nv_bfloat162 p2 = *(__nv_bfloat162*)&vb.z, p3 = *(__nv_bfloat162*)&vb.w;
                    a1[0] += __low2float(p0); a1[1] += __high2float(p0);
                    a1[2] += __low2float(p1); a1[3] += __high2float(p1);
                    a1[4] += __low2float(p2); a1[5] += __high2float(p2);
                    a1[6] += __low2float(p3); a1[7] += __high2float(p3);
                }
            }
            if (e < cnt) {
                int sa = __shfl_sync(0xffffffffu, myidx, e);
                uint4 va = ((const uint4*)(x + (size_t)sa * 256))[lane];
                __nv_bfloat162 p0 = *(__nv_bfloat162*)&va.x, p1 = *(__nv_bfloat162*)&va.y;
                __nv_bfloat162 p2 = *(__nv_bfloat162*)&va.z, p3 = *(__nv_bfloat162*)&va.w;
                a0[0] += __low2float(p0); a0[1] += __high2float(p0);
                a0[2] += __low2float(p1); a0[3] += __high2float(p1);
                a0[4] += __low2float(p2); a0[5] += __high2float(p2);
                a0[6] += __low2float(p3); a0[7] += __high2float(p3);
            }
        }
        uint4 r;
        __nv_bfloat162 q0 = __float22bfloat162_rn(make_float2(a0[0] + a1[0], a0[1] + a1[1]));
        __nv_bfloat162 q1 = __float22bfloat162_rn(make_float2(a0[2] + a1[2], a0[3] + a1[3]));
        __nv_bfloat162 q2 = __float22bfloat162_rn(make_float2(a0[4] + a1[4], a0[5] + a1[5]));
        __nv_bfloat162 q3 = __float22bfloat162_rn(make_float2(a0[6] + a1[6], a0[7] + a1[7]));
        r.x = *(uint32_t*)&q0; r.y = *(uint32_t*)&q1;
        r.z = *(uint32_t*)&q2; r.w = *(uint32_t*)&q3;
        ((uint4*)out)[(size_t)node * 32 + lane] = r;
    }
}

// conv3: aggregate(D=128) + fused scale+bias+softmax, dual fp32 + bf16 output; node range
__global__ void k_agg_smax128(const __nv_bfloat16* __restrict__ x,
                              float* __restrict__ out, __nv_bfloat16* __restrict__ outb,
                              const float* __restrict__ rowscale, const float* __restrict__ bias,
                              int n0, int ncnt) {
    int wloc = (blockIdx.x * blockDim.x + threadIdx.x) >> 5;
    int lane = threadIdx.x & 31;
    if (wloc >= ncnt) return;
    int node = n0 + wloc;
    int s0 = g_row_ptr[node], s1 = g_row_ptr[node + 1];
    float4 a0 = make_float4(0.f, 0.f, 0.f, 0.f);
    float4 a1 = make_float4(0.f, 0.f, 0.f, 0.f);
    for (int base = s0; base < s1; base += 32) {
        int cnt = min(32, s1 - base);
        int myidx = (lane < cnt) ? g_csr[base + lane] : 0;
        int e = 0;
        for (; e + 2 <= cnt; e += 2) {
            int sa = __shfl_sync(0xffffffffu, myidx, e);
            int sb = __shfl_sync(0xffffffffu, myidx, e + 1);
            uint2 va = ((const uint2*)(x + (size_t)sa * 128))[lane];
            uint2 vb = ((const uint2*)(x + (size_t)sb * 128))[lane];
            __nv_bfloat162 p0 = *(__nv_bfloat162*)&va.x;
            __nv_bfloat162 p1 = *(__nv_bfloat162*)&va.y;
            a0.x += __low2float(p0); a0.y += __high2float(p0);
            a0.z += __low2float(p1); a0.w += __high2float(p1);
            __nv_bfloat162 q0 = *(__nv_bfloat162*)&vb.x;
            __nv_bfloat162 q1 = *(__nv_bfloat162*)&vb.y;
            a1.x += __low2float(q0); a1.y += __high2float(q0);
            a1.z += __low2float(q1); a1.w += __high2float(q1);
        }
        if (e < cnt) {
            int sa = __shfl_sync(0xffffffffu, myidx, e);
            uint2 va = ((const uint2*)(x + (size_t)sa * 128))[lane];
            __nv_bfloat162 p0 = *(__nv_bfloat162*)&va.x;
            __nv_bfloat162 p1 = *(__nv_bfloat162*)&va.y;
            a0.x += __low2float(p0); a0.y += __high2float(p0);
            a0.z += __low2float(p1); a0.w += __high2float(p1);
        }
    }
    float4 v = make_float4(a0.x + a1.x, a0.y + a1.y, a0.z + a1.z, a0.w + a1.w);
    float rs = rowscale[node];
    float4 b = ((const float4*)bias)[lane];
    v.x = v.x * rs + b.x; v.y = v.y * rs + b.y;
    v.z = v.z * rs + b.z; v.w = v.w * rs + b.w;
    float m = fmaxf(fmaxf(v.x, v.y), fmaxf(v.z, v.w));
#pragma unroll
    for (int off = 16; off > 0; off >>= 1) m = fmaxf(m, __shfl_xor_sync(0xffffffffu, m, off));
    v.x = expf(v.x - m); v.y = expf(v.y - m);
    v.z = expf(v.z - m); v.w = expf(v.w - m);
    float s = v.x + v.y + v.z + v.w;
#pragma unroll
    for (int off = 16; off > 0; off >>= 1) s += __shfl_xor_sync(0xffffffffu, s, off);
    float inv = 1.f / s;
    v.x *= inv; v.y *= inv; v.z *= inv; v.w *= inv;
    ((float4*)out)[(size_t)node * 32 + lane] = v;
    uint2 r;
    __nv_bfloat162 p0 = __float22bfloat162_rn(make_float2(v.x, v.y));
    __nv_bfloat162 p1 = __float22bfloat162_rn(make_float2(v.z, v.w));
    r.x = *(uint32_t*)&p0; r.y = *(uint32_t*)&p1;
    ((uint2*)outb)[(size_t)node * 32 + lane] = r;
}

// ---------------- bf16 tensor-core GEMM, BN=128, cp.async 2-stage ----------------
__device__ __forceinline__ void mma_bf16(float* d, const uint32_t* a, const uint32_t* b) {
    asm volatile(
        "mma.sync.aligned.m16n8k16.row.col.f32.bf16.bf16.f32 "
        "{%0,%1,%2,%3}, {%4,%5,%6,%7}, {%8,%9}, {%0,%1,%2,%3};"
        : "+f"(d[0]), "+f"(d[1]), "+f"(d[2]), "+f"(d[3])
        : "r"(a[0]), "r"(a[1]), "r"(a[2]), "r"(a[3]), "r"(b[0]), "r"(b[1]));
}
__device__ __forceinline__ void cp16(uint32_t dst, const void* src, int sz) {
    asm volatile("cp.async.cg.shared.global [%0], [%1], 16, %2;" :: "r"(dst), "l"(src), "r"(sz) : "memory");
}
#define CP_COMMIT() asm volatile("cp.async.commit_group;" ::: "memory")

// CTA tile 128x128; 8 warps (4 wm x 2 wn); warp tile 32x64.
// ACT: 0 none, 1 tanh, 2 row-softmax (N==128, gridDim.y==1, OUTB=0)
template <int ACT, int OUTB>
__global__ void __launch_bounds__(256)
k_gemm_bf16(const __nv_bfloat16* __restrict__ A, const __nv_bfloat16* __restrict__ WT,
            void* __restrict__ Cout, int M, int K, int N,
            const float* __restrict__ prescale, const float* __restrict__ bias,
            const float* __restrict__ postscale) {
    extern __shared__ __nv_bfloat16 sm[];
    constexpr int AW = 128 * 72;
    constexpr int BW = 128 * 72;
    __nv_bfloat16* As = sm;
    __nv_bfloat16* Bs = sm + 2 * AW;
    uint32_t sA = (uint32_t)__cvta_generic_to_shared(As);
    uint32_t sB = (uint32_t)__cvta_generic_to_shared(Bs);

    int tid = threadIdx.x;
    int warp = tid >> 5, lane = tid & 31;
    int g = lane >> 2, t = lane & 3;
    int wm = warp >> 1, wn = warp & 1;
    int bm = blockIdx.x * 128, bn = blockIdx.y * 128;
    int lrow = tid >> 3, lq = tid & 7;

    float acc[2][8][4];
#pragma unroll
    for (int mt = 0; mt < 2; mt++)
#pragma unroll
        for (int nt = 0; nt < 8; nt++)
#pragma unroll
            for (int j = 0; j < 4; j++) acc[mt][nt][j] = 0.f;

    const int T = K >> 6;

    auto load_tile = [&](int stage, int kt) {
#pragma unroll
        for (int i = 0; i < 4; i++) {
            int row = lrow + i * 32;
            int gm = bm + row;
            cp16(sA + (uint32_t)(stage * AW + row * 72 + lq * 8) * 2,
                 A + (size_t)gm * K + kt + lq * 8, (gm < M) ? 16 : 0);
        }
#pragma unroll
        for (int i = 0; i < 4; i++) {
            int row = lrow + i * 32;
            cp16(sB + (uint32_t)(stage * BW + row * 72 + lq * 8) * 2,
                 WT + (size_t)(bn + row) * K + kt + lq * 8, 16);
        }
    };

    load_tile(0, 0);
    CP_COMMIT();

    for (int ti = 0; ti < T; ti++) {
        if (ti + 1 < T) {
            load_tile((ti + 1) & 1, (ti + 1) * 64);
            CP_COMMIT();
            asm volatile("cp.async.wait_group 1;" ::: "memory");
        } else {
            asm volatile("cp.async.wait_group 0;" ::: "memory");
        }
        __syncthreads();

        const uint32_t* Asu = (const uint32_t*)(As + (ti & 1) * AW);
        const uint32_t* Bsu = (const uint32_t*)(Bs + (ti & 1) * BW);
#pragma unroll
        for (int k16 = 0; k16 < 4; k16++) {
            int kw = k16 * 8;
            uint32_t a[2][4];
#pragma unroll
            for (int mt = 0; mt < 2; mt++) {
                int r0 = (wm * 32 + mt * 16 + g) * 36 + kw + t;
                a[mt][0] = Asu[r0];
                a[mt][1] = Asu[r0 + 8 * 36];
                a[mt][2] = Asu[r0 + 4];
                a[mt][3] = Asu[r0 + 8 * 36 + 4];
            }
            uint32_t b[8][2];
#pragma unroll
            for (int nt = 0; nt < 8; nt++) {
                int r0 = (wn * 64 + nt * 8 + g) * 36 + kw + t;
                b[nt][0] = Bsu[r0];
                b[nt][1] = Bsu[r0 + 4];
            }
#pragma unroll
            for (int mt = 0; mt < 2; mt++)
#pragma unroll
                for (int nt = 0; nt < 8; nt++)
                    mma_bf16(acc[mt][nt], a[mt], b[nt]);
        }
        __syncthreads();
    }

    // ---- epilogue ----
    float2 bv[8];
#pragma unroll
    for (int nt = 0; nt < 8; nt++) {
        if (bias) bv[nt] = *(const float2*)(bias + bn + wn * 64 + nt * 8 + 2 * t);
        else bv[nt] = make_float2(0.f, 0.f);
    }

    if (ACT == 2) {
        float* red = (float*)sm;
        float Mx[2][2];
#pragma unroll
        for (int mt = 0; mt < 2; mt++) {
#pragma unroll
            for (int h = 0; h < 2; h++) {
                int gm = bm + wm * 32 + mt * 16 + h * 8 + g;
                float pre = (prescale && gm < M) ? prescale[gm] : 1.f;
                float lm = -1e30f;
#pragma unroll
                for (int nt = 0; nt < 8; nt++) {
                    float ox = acc[mt][nt][2 * h]     * pre + bv[nt].x;
                    float oy = acc[mt][nt][2 * h + 1] * pre + bv[nt].y;
                    acc[mt][nt][2 * h] = ox; acc[mt][nt][2 * h + 1] = oy;
                    lm = fmaxf(lm, fmaxf(ox, oy));
                }
                lm = fmaxf(lm, __shfl_xor_sync(0xffffffffu, lm, 1));
                lm = fmaxf(lm, __shfl_xor_sync(0xffffffffu, lm, 2));
                int r = wm * 32 + mt * 16 + h * 8 + g;
                if (t == 0) red[r * 2 + wn] = lm;
            }
        }
        __syncthreads();
#pragma unroll
        for (int mt = 0; mt < 2; mt++)
#pragma unroll
            for (int h = 0; h < 2; h++) {
                int r = wm * 32 + mt * 16 + h * 8 + g;
                Mx[mt][h] = fmaxf(red[r * 2], red[r * 2 + 1]);
            }
        __syncthreads();
#pragma unroll
        for (int mt = 0; mt < 2; mt++) {
#pragma unroll
            for (int h = 0; h < 2; h++) {
                float ls = 0.f;
#pragma unroll
                for (int nt = 0; nt < 8; nt++) {
                    float ex = expf(acc[mt][nt][2 * h]     - Mx[mt][h]);
                    float ey = expf(acc[mt][nt][2 * h + 1] - Mx[mt][h]);
                    acc[mt][nt][2 * h] = ex; acc[mt][nt][2 * h + 1] = ey;
                    ls += ex + ey;
                }
                ls += __shfl_xor_sync(0xffffffffu, ls, 1);
                ls += __shfl_xor_sync(0xffffffffu, ls, 2);
                int r = wm * 32 + mt * 16 + h * 8 + g;
                if (t == 0) red[r * 2 + wn] = ls;
            }
        }
        __syncthreads();
#pragma unroll
        for (int mt = 0; mt < 2; mt++) {
#pragma unroll
            for (int h = 0; h < 2; h++) {
                int r = wm * 32 + mt * 16 + h * 8 + g;
                float inv = 1.f / (red[r * 2] + red[r * 2 + 1]);
                int gm = bm + wm * 32 + mt * 16 + h * 8 + g;
                if (gm >= M) continue;
#pragma unroll
                for (int nt = 0; nt < 8; nt++) {
                    float2 o = make_float2(acc[mt][nt][2 * h] * inv, acc[mt][nt][2 * h + 1] * inv);
                    *(float2*)((float*)Cout + (size_t)gm * N + bn + wn * 64 + nt * 8 + 2 * t) = o;
                }
            }
        }
        return;
    }

#pragma unroll
    for (int mt = 0; mt < 2; mt++) {
#pragma unroll
        for (int h = 0; h < 2; h++) {
            int gm = bm + wm * 32 + mt * 16 + h * 8 + g;
            if (gm >= M) continue;
            float pre = prescale ? prescale[gm] : 1.f;
            float post = postscale ? postscale[gm] : 1.f;
#pragma unroll
            for (int nt = 0; nt < 8; nt++) {
                float ox = acc[mt][nt][2 * h]     * pre + bv[nt].x;
                float oy = acc[mt][nt][2 * h + 1] * pre + bv[nt].y;
                if (ACT == 1) { ox = tanhf(ox); oy = tanhf(oy); }
                ox *= post; oy *= post;
                size_t off = (size_t)gm * N + bn + wn * 64 + nt * 8 + 2 * t;
                if (OUTB) {
                    __nv_bfloat162 p = __float22bfloat162_rn(make_float2(ox, oy));
                    *(uint32_t*)((__nv_bfloat16*)Cout + off) = *(uint32_t*)&p;
                } else {
                    *(float2*)((float*)Cout + off) = make_float2(ox, oy);
                }
            }
        }
    }
}

// ---------------- launcher: fork-join dual-stream schedule ----------------
extern "C" void kernel_launch(void* const* d_in, const int* in_sizes, int n_in,
                              void* d_out, int out_size) {
    const float* in_feat = (const float*)d_in[0];
    const int*   src     = (const int*)d_in[1];
    const int*   dst     = (const int*)d_in[2];
    const float* Wc0 = (const float*)d_in[3];
    const float* bc0 = (const float*)d_in[4];
    const float* Wc1 = (const float*)d_in[5];
    const float* bc1 = (const float*)d_in[6];
    const float* Wc2 = (const float*)d_in[7];
    const float* bc2 = (const float*)d_in[8];
    const float* Wr0 = (const float*)d_in[9];
    const float* br0 = (const float*)d_in[10];
    const float* Wr1 = (const float*)d_in[11];
    const float* br1 = (const float*)d_in[12];
    const float* Wr2 = (const float*)d_in[13];
    const float* br2 = (const float*)d_in[14];
    float* out = (float*)d_out;

    float *bufA, *bufB, *bufC, *sout, *sin, *wt;
    cudaGetSymbolAddress((void**)&bufA, g_bufA);
    cudaGetSymbolAddress((void**)&bufB, g_bufB);
    cudaGetSymbolAddress((void**)&bufC, g_bufC);
    cudaGetSymbolAddress((void**)&sout, g_sout);
    cudaGetSymbolAddress((void**)&sin,  g_sin);
    cudaGetSymbolAddress((void**)&wt,   g_wt);

    __nv_bfloat16* bA16 = (__nv_bfloat16*)bufA;                   // x / conv2-gemm out / r0 out
    __nv_bfloat16* bB16 = (__nv_bfloat16*)bufB;                   // agg out / conv3 V
    __nv_bfloat16* bC16 = (__nv_bfloat16*)bufC;                   // conv1-gemm out, then h16
    __nv_bfloat16* t116 = (__nv_bfloat16*)bufC + (size_t)NN * 128; // r1 out
    __nv_bfloat16* WTc0 = (__nv_bfloat16*)(wt + 0 * 65536);
    __nv_bfloat16* WTc1 = (__nv_bfloat16*)(wt + 1 * 65536);
    __nv_bfloat16* WTc2 = (__nv_bfloat16*)(wt + 2 * 65536);
    __nv_bfloat16* WTr0 = (__nv_bfloat16*)(wt + 3 * 65536);
    __nv_bfloat16* WTr1 = (__nv_bfloat16*)(wt + 4 * 65536);
    __nv_bfloat16* WTr2 = (__nv_bfloat16*)(wt + 5 * 65536);

    const int M = NN;
    dim3 g_n((NN + 255) / 256);
    dim3 g_e(4096);
    dim3 g_w((NN * 32 + 255) / 256);
    dim3 gw0((CH0 * 32 + 255) / 256), gw1((CH1 * 32 + 255) / 256);
    const int GT  = (M + 127) / 128;
    const int GT0 = (CH0 + 127) / 128;
    const int GT1 = (CH1 + 127) / 128;

    const int SMEM_GEMM = (2 * 128 * 72 + 2 * 128 * 72) * 2;
    static cudaStream_t s1 = nullptr;
    static cudaEvent_t evRoot, evHist, evPre, evA1, evG1, evA2, evG2, evS0, evR0;
    if (!s1) {
        cudaFuncSetAttribute(k_gemm_bf16<1, 1>, cudaFuncAttributeMaxDynamicSharedMemorySize, SMEM_GEMM);
        cudaFuncSetAttribute(k_gemm_bf16<0, 1>, cudaFuncAttributeMaxDynamicSharedMemorySize, SMEM_GEMM);
        cudaFuncSetAttribute(k_gemm_bf16<2, 0>, cudaFuncAttributeMaxDynamicSharedMemorySize, SMEM_GEMM);
        cudaStreamCreateWithFlags(&s1, cudaStreamNonBlocking);
        cudaEventCreateWithFlags(&evRoot, cudaEventDisableTiming);
        cudaEventCreateWithFlags(&evHist, cudaEventDisableTiming);
        cudaEventCreateWithFlags(&evPre,  cudaEventDisableTiming);
        cudaEventCreateWithFlags(&evA1,   cudaEventDisableTiming);
        cudaEventCreateWithFlags(&evG1,   cudaEventDisableTiming);
        cudaEventCreateWithFlags(&evA2,   cudaEventDisableTiming);
        cudaEventCreateWithFlags(&evG2,   cudaEventDisableTiming);
        cudaEventCreateWithFlags(&evS0,   cudaEventDisableTiming);
        cudaEventCreateWithFlags(&evR0,   cudaEventDisableTiming);
    }

    // ---- fork: side stream does transposes (indep) then scales+prescale (after hist) ----
    cudaEventRecord(evRoot, 0);
    cudaStreamWaitEvent(s1, evRoot, 0);
    k_transpose_all<<<dim3(8, 8, 6), dim3(32, 8), 0, s1>>>(Wc0, Wc1, Wc2, Wr0, Wr1, Wr2,
                                                           WTc0, WTc1, WTc2, WTr0, WTr1, WTr2);
    // main: CSR chain
    k_zero_counts<<<g_n, 256>>>();
    k_hist<<<g_e, 256>>>(src, dst);
    cudaEventRecord(evHist, 0);
    k_scan<<<1, 1024>>>();
    k_fill<<<g_e, 256>>>(src, dst);
    // side: scales + prescale
    cudaStreamWaitEvent(s1, evHist, 0);
    k_scales<<<g_n, 256, 0, s1>>>();
    k_prescale<<<g_w, 256, 0, s1>>>(in_feat, bA16);
    cudaEventRecord(evPre, s1);
    cudaStreamWaitEvent(0, evPre, 0);

    // ---- conv1: agg(x)->bB16 ; gemm(bB16)->bC16, chunk-pipelined ----
    k_agg_b16<128, 1><<<gw0, 256>>>(bA16, bB16, 0, CH0);
    cudaEventRecord(evA1, 0);
    k_agg_b16<128, 1><<<gw1, 256>>>(bA16, bB16, CH0, CH1);
    cudaStreamWaitEvent(s1, evA1, 0);
    k_gemm_bf16<1, 1><<<dim3(GT0, 2), 256, SMEM_GEMM, s1>>>(bB16, WTc0, bC16, CH0, 128, 256, sin, bc0, sout);
    k_gemm_bf16<1, 1><<<dim3(GT1, 2), 256, SMEM_GEMM>>>(bB16 + (size_t)CH0 * 128, WTc0,
                                                        bC16 + (size_t)CH0 * 256, CH1, 128, 256,
                                                        sin + CH0, bc0, sout + CH0);
    cudaEventRecord(evG1, s1);
    cudaStreamWaitEvent(0, evG1, 0);

    // ---- conv2: agg(bC16)->bB16 ; gemm(bB16)->bA16 ----
    k_agg_b16<256, 1><<<gw0, 256>>>(bC16, bB16, 0, CH0);
    cudaEventRecord(evA2, 0);
    k_agg_b16<256, 1><<<gw1, 256>>>(bC16, bB16, CH0, CH1);
    cudaStreamWaitEvent(s1, evA2, 0);
    k_gemm_bf16<1, 1><<<dim3(GT0, 2), 256, SMEM_GEMM, s1>>>(bB16, WTc1, bA16, CH0, 256, 256, sin, bc1, sout);
    k_gemm_bf16<1, 1><<<dim3(GT1, 2), 256, SMEM_GEMM>>>(bB16 + (size_t)CH0 * 256, WTc1,
                                                        bA16 + (size_t)CH0 * 256, CH1, 256, 256,
                                                        sin + CH0, bc1, sout + CH0);
    cudaEventRecord(evG2, s1);
    cudaStreamWaitEvent(0, evG2, 0);

    // ---- conv3: gemm(bA16)->bB16 (full), agg+softmax -> out & h16(bC16), chunked ----
    k_gemm_bf16<0, 1><<<dim3(GT, 1), 256, SMEM_GEMM>>>(bA16, WTc2, bB16, M, 256, 128, nullptr, nullptr, nullptr);
    k_agg_smax128<<<gw0, 256>>>(bB16, out, bC16, sin, bc2, 0, CH0);
    cudaEventRecord(evS0, 0);
    k_agg_smax128<<<gw1, 256>>>(bB16, out, bC16, sin, bc2, CH0, CH1);

    // ---- MLP: two row-chunk chains; h16=bC16, r0->bA16, r1->t116, r2->out ----
    cudaStreamWaitEvent(s1, evS0, 0);
    k_gemm_bf16<1, 1><<<dim3(GT0, 2), 256, SMEM_GEMM, s1>>>(bC16, WTr0, bA16, CH0, 128, 256, nullptr, br0, nullptr);
    k_gemm_bf16<1, 1><<<dim3(GT0, 2), 256, SMEM_GEMM, s1>>>(bA16, WTr1, t116, CH0, 256, 256, nullptr, br1, nullptr);
    k_gemm_bf16<2, 0><<<dim3(GT0, 1), 256, SMEM_GEMM, s1>>>(t116, WTr2, out + (size_t)M * 128, CH0, 256, 128, nullptr, br2, nullptr);
    cudaEventRecord(evR0, s1);

    k_gemm_bf16<1, 1><<<dim3(GT1, 2), 256, SMEM_GEMM>>>(bC16 + (size_t)CH0 * 128, WTr0,
                                                        bA16 + (size_t)CH0 * 256, CH1, 128, 256, nullptr, br0, nullptr);
    k_gemm_bf16<1, 1><<<dim3(GT1, 2), 256, SMEM_GEMM>>>(bA16 + (size_t)CH0 * 256, WTr1,
                                                        t116 + (size_t)CH0 * 256, CH1, 256, 256, nullptr, br1, nullptr);
    k_gemm_bf16<2, 0><<<dim3(GT1, 1), 256, SMEM_GEMM>>>(t116 + (size_t)CH0 * 256, WTr2,
                                                        out + (size_t)M * 128 + (size_t)CH0 * 128, CH1, 256, 128, nullptr, br2, nullptr);
    cudaStreamWaitEvent(0, evR0, 0);
}

// round 11
// speedup vs baseline: 3.3402x; 1.0910x over previous
#include <cuda_runtime.h>
#include <cuda_bf16.h>
#include <math.h>
#include <stdint.h>

#define NN 100000
#define EE 1600000
#define CH0 50048
#define CH1 (NN - CH0)
#define SCAN_NB ((NN + 1023) / 1024)

// ---------------- static scratch ----------------
__device__ float g_bufA[(size_t)NN * 256];
__device__ float g_bufB[(size_t)NN * 256];
__device__ float g_bufC[(size_t)NN * 256];
__device__ float g_sout[NN];
__device__ float g_sin[NN];
__device__ int   g_cnt_out[NN];
__device__ int   g_cnt_in[NN];
__device__ int   g_cursor[NN];
__device__ int   g_row_ptr[NN + 1];
__device__ int   g_csr[EE];
__device__ int   g_blocksum[128];
__device__ float g_wt[6][65536];

// ---------------- graph preprocessing ----------------
__global__ void k_zero_counts() {
    int i = blockIdx.x * blockDim.x + threadIdx.x;
    if (i < NN) { g_cnt_out[i] = 0; g_cnt_in[i] = 0; g_cursor[i] = 0; }
}
__global__ void k_hist(const int* __restrict__ src, const int* __restrict__ dst) {
    int stride = gridDim.x * blockDim.x;
    for (int i = blockIdx.x * blockDim.x + threadIdx.x; i < EE; i += stride) {
        atomicAdd(&g_cnt_out[src[i]], 1);
        atomicAdd(&g_cnt_in[dst[i]], 1);
    }
}

// ---- multi-block scan: phase 1 (block-local inclusive scan + block sums) ----
__global__ void k_scan1() {
    __shared__ int wsum[32];
    int b = blockIdx.x, t = threadIdx.x, lane = t & 31, w = t >> 5;
    int idx = b * 1024 + t;
    int x = (idx < NN) ? g_cnt_in[idx] : 0;
#pragma unroll
    for (int off = 1; off < 32; off <<= 1) {
        int y = __shfl_up_sync(0xffffffffu, x, off);
        if (lane >= off) x += y;
    }
    if (lane == 31) wsum[w] = x;
    __syncthreads();
    if (w == 0) {
        int s = wsum[lane];
#pragma unroll
        for (int off = 1; off < 32; off <<= 1) {
            int y = __shfl_up_sync(0xffffffffu, s, off);
            if (lane >= off) s += y;
        }
        wsum[lane] = s;
    }
    __syncthreads();
    int res = ((w > 0) ? wsum[w - 1] : 0) + x;
    if (idx < NN) g_row_ptr[idx + 1] = res;
    if (t == 1023) g_blocksum[b] = res;
}
// ---- phase 2: exclusive scan of 98 block sums (1 block, 128 threads) ----
__global__ void k_scan2() {
    __shared__ int wsum[4];
    int t = threadIdx.x, lane = t & 31, w = t >> 5;
    int v = (t < SCAN_NB) ? g_blocksum[t] : 0;
    int x = v;
#pragma unroll
    for (int off = 1; off < 32; off <<= 1) {
        int y = __shfl_up_sync(0xffffffffu, x, off);
        if (lane >= off) x += y;
    }
    if (lane == 31) wsum[w] = x;
    __syncthreads();
    if (t == 0) {
        int c = 0;
        for (int i = 0; i < 4; i++) { int tmp = wsum[i]; wsum[i] = c; c += tmp; }
    }
    __syncthreads();
    if (t < SCAN_NB) g_blocksum[t] = wsum[w] + x - v;   // exclusive
}
// ---- phase 3: add block offsets ----
__global__ void k_scan3() {
    int b = blockIdx.x, t = threadIdx.x;
    int idx = b * 1024 + t;
    if (idx == 0) g_row_ptr[0] = 0;
    if (idx < NN && b > 0) g_row_ptr[idx + 1] += g_blocksum[b];
}

__global__ void k_fill(const int* __restrict__ src, const int* __restrict__ dst) {
    int stride = gridDim.x * blockDim.x;
    for (int i = blockIdx.x * blockDim.x + threadIdx.x; i < EE; i += stride) {
        int d = dst[i];
        int pos = g_row_ptr[d] + atomicAdd(&g_cursor[d], 1);
        g_csr[pos] = src[i];
    }
}
__global__ void k_scales() {
    int i = blockIdx.x * blockDim.x + threadIdx.x;
    if (i < NN) {
        g_sout[i] = rsqrtf(fmaxf((float)g_cnt_out[i], 1.f));
        g_sin[i]  = rsqrtf(fmaxf((float)g_cnt_in[i], 1.f));
    }
}

// all 6 weight transposes in one launch
__global__ void k_transpose_all(
    const float* W0, const float* W1, const float* W2,
    const float* W3, const float* W4, const float* W5,
    __nv_bfloat16* T0, __nv_bfloat16* T1, __nv_bfloat16* T2,
    __nv_bfloat16* T3, __nv_bfloat16* T4, __nv_bfloat16* T5) {
    __shared__ float t[32][33];
    const float* W; __nv_bfloat16* WT; int K, N;
    switch (blockIdx.z) {
        case 0: W = W0; WT = T0; K = 128; N = 256; break;
        case 1: W = W1; WT = T1; K = 256; N = 256; break;
        case 2: W = W2; WT = T2; K = 256; N = 128; break;
        case 3: W = W3; WT = T3; K = 128; N = 256; break;
        case 4: W = W4; WT = T4; K = 256; N = 256; break;
        default: W = W5; WT = T5; K = 256; N = 128; break;
    }
    int k0 = blockIdx.x * 32, n0 = blockIdx.y * 32;
    if (k0 >= K || n0 >= N) return;
    int x = threadIdx.x, y = threadIdx.y;
    for (int i = 0; i < 32; i += 8) {
        int k = k0 + y + i, n = n0 + x;
        t[y + i][x] = (k < K && n < N) ? W[(size_t)k * N + n] : 0.f;
    }
    __syncthreads();
    for (int i = 0; i < 32; i += 8) {
        int n = n0 + y + i, k = k0 + x;
        if (n < N && k < K) WT[(size_t)n * K + k] = __float2bfloat16(t[x][y + i]);
    }
}

// prescale in_feat by sout -> bf16
__global__ void k_prescale(const float* __restrict__ x, __nv_bfloat16* __restrict__ o) {
    int i = blockIdx.x * blockDim.x + threadIdx.x;
    if (i >= NN * 32) return;
    int m = i >> 5;
    float s = g_sout[m];
    float4 v = ((const float4*)x)[i];
    uint2 r;
    __nv_bfloat162 p0 = __float22bfloat162_rn(make_float2(v.x * s, v.y * s));
    __nv_bfloat162 p1 = __float22bfloat162_rn(make_float2(v.z * s, v.w * s));
    r.x = *(uint32_t*)&p0; r.y = *(uint32_t*)&p1;
    ((uint2*)o)[i] = r;
}

// ---------------- aggregation (bf16 gather, fp32 accumulate), node range ----------------
template <int D, int OUTB>
__global__ void k_agg_b16(const __nv_bfloat16* __restrict__ x, void* __restrict__ out,
                          int n0, int ncnt) {
    int wloc = (blockIdx.x * blockDim.x + threadIdx.x) >> 5;
    int lane = threadIdx.x & 31;
    if (wloc >= ncnt) return;
    int node = n0 + wloc;
    int s0 = g_row_ptr[node], s1 = g_row_ptr[node + 1];

    if (D == 128) {
        float4 a0 = make_float4(0.f, 0.f, 0.f, 0.f);
        float4 a1 = make_float4(0.f, 0.f, 0.f, 0.f);
        for (int base = s0; base < s1; base += 32) {
            int cnt = min(32, s1 - base);
            int myidx = (lane < cnt) ? g_csr[base + lane] : 0;
            int e = 0;
            for (; e + 2 <= cnt; e += 2) {
                int sa = __shfl_sync(0xffffffffu, myidx, e);
                int sb = __shfl_sync(0xffffffffu, myidx, e + 1);
                uint2 va = ((const uint2*)(x + (size_t)sa * 128))[lane];
                uint2 vb = ((const uint2*)(x + (size_t)sb * 128))[lane];
                __nv_bfloat162 p0 = *(__nv_bfloat162*)&va.x;
                __nv_bfloat162 p1 = *(__nv_bfloat162*)&va.y;
                a0.x += __low2float(p0); a0.y += __high2float(p0);
                a0.z += __low2float(p1); a0.w += __high2float(p1);
                __nv_bfloat162 q0 = *(__nv_bfloat162*)&vb.x;
                __nv_bfloat162 q1 = *(__nv_bfloat162*)&vb.y;
                a1.x += __low2float(q0); a1.y += __high2float(q0);
                a1.z += __low2float(q1); a1.w += __high2float(q1);
            }
            if (e < cnt) {
                int sa = __shfl_sync(0xffffffffu, myidx, e);
                uint2 va = ((const uint2*)(x + (size_t)sa * 128))[lane];
                __nv_bfloat162 p0 = *(__nv_bfloat162*)&va.x;
                __nv_bfloat162 p1 = *(__nv_bfloat162*)&va.y;
                a0.x += __low2float(p0); a0.y += __high2float(p0);
                a0.z += __low2float(p1); a0.w += __high2float(p1);
            }
        }
        float4 acc = make_float4(a0.x + a1.x, a0.y + a1.y, a0.z + a1.z, a0.w + a1.w);
        if (OUTB) {
            uint2 r;
            __nv_bfloat162 p0 = __float22bfloat162_rn(make_float2(acc.x, acc.y));
            __nv_bfloat162 p1 = __float22bfloat162_rn(make_float2(acc.z, acc.w));
            r.x = *(uint32_t*)&p0; r.y = *(uint32_t*)&p1;
            ((uint2*)out)[(size_t)node * 32 + lane] = r;
        } else {
            ((float4*)out)[(size_t)node * 32 + lane] = acc;
        }
    } else {  // D == 256
        float a0[8], a1[8];
#pragma unroll
        for (int j = 0; j < 8; j++) { a0[j] = 0.f; a1[j] = 0.f; }
        for (int base = s0; base < s1; base += 32) {
            int cnt = min(32, s1 - base);
            int myidx = (lane < cnt) ? g_csr[base + lane] : 0;
            int e = 0;
            for (; e + 2 <= cnt; e += 2) {
                int sa = __shfl_sync(0xffffffffu, myidx, e);
                int sb = __shfl_sync(0xffffffffu, myidx, e + 1);
                uint4 va = ((const uint4*)(x + (size_t)sa * 256))[lane];
                uint4 vb = ((const uint4*)(x + (size_t)sb * 256))[lane];
                {
                    __nv_bfloat162 p0 = *(__nv_bfloat162*)&va.x, p1 = *(__nv_bfloat162*)&va.y;
                    __nv_bfloat162 p2 = *(__nv_bfloat162*)&va.z, p3 = *(__nv_bfloat162*)&va.w;
                    a0[0] += __low2float(p0); a0[1] += __high2float(p0);
                    a0[2] += __low2float(p1); a0[3] += __high2float(p1);
                    a0[4] += __low2float(p2); a0[5] += __high2float(p2);
                    a0[6] += __low2float(p3); a0[7] += __high2float(p3);
                }
                {
                    __nv_bfloat162 p0 = *(__nv_bfloat162*)&vb.x, p1 = *(__nv_bfloat162*)&vb.y;
                    __nv_bfloat162 p2 = *(__nv_bfloat162*)&vb.z, p3 = *(__nv_bfloat162*)&vb.w;
                    a1[0] += __low2float(p0); a1[1] += __high2float(p0);
                    a1[2] += __low2float(p1); a1[3] += __high2float(p1);
                    a1[4] += __low2float(p2); a1[5] += __high2float(p2);
                    a1[6] += __low2float(p3); a1[7] += __high2float(p3);
                }
            }
            if (e < cnt) {
                int sa = __shfl_sync(0xffffffffu, myidx, e);
                uint4 va = ((const uint4*)(x + (size_t)sa * 256))[lane];
                __nv_bfloat162 p0 = *(__nv_bfloat162*)&va.x, p1 = *(__nv_bfloat162*)&va.y;
                __nv_bfloat162 p2 = *(__nv_bfloat162*)&va.z, p3 = *(__nv_bfloat162*)&va.w;
                a0[0] += __low2float(p0); a0[1] += __high2float(p0);
                a0[2] += __low2float(p1); a0[3] += __high2float(p1);
                a0[4] += __low2float(p2); a0[5] += __high2float(p2);
                a0[6] += __low2float(p3); a0[7] += __high2float(p3);
            }
        }
        uint4 r;
        __nv_bfloat162 q0 = __float22bfloat162_rn(make_float2(a0[0] + a1[0], a0[1] + a1[1]));
        __nv_bfloat162 q1 = __float22bfloat162_rn(make_float2(a0[2] + a1[2], a0[3] + a1[3]));
        __nv_bfloat162 q2 = __float22bfloat162_rn(make_float2(a0[4] + a1[4], a0[5] + a1[5]));
        __nv_bfloat162 q3 = __float22bfloat162_rn(make_float2(a0[6] + a1[6], a0[7] + a1[7]));
        r.x = *(uint32_t*)&q0; r.y = *(uint32_t*)&q1;
        r.z = *(uint32_t*)&q2; r.w = *(uint32_t*)&q3;
        ((uint4*)out)[(size_t)node * 32 + lane] = r;
    }
}

// conv3: aggregate(D=128) + fused scale+bias+softmax, dual fp32 + bf16 output
__global__ void k_agg_smax128(const __nv_bfloat16* __restrict__ x,
                              float* __restrict__ out, __nv_bfloat16* __restrict__ outb,
                              const float* __restrict__ rowscale, const float* __restrict__ bias,
                              int n0, int ncnt) {
    int wloc = (blockIdx.x * blockDim.x + threadIdx.x) >> 5;
    int lane = threadIdx.x & 31;
    if (wloc >= ncnt) return;
    int node = n0 + wloc;
    int s0 = g_row_ptr[node], s1 = g_row_ptr[node + 1];
    float4 a0 = make_float4(0.f, 0.f, 0.f, 0.f);
    float4 a1 = make_float4(0.f, 0.f, 0.f, 0.f);
    for (int base = s0; base < s1; base += 32) {
        int cnt = min(32, s1 - base);
        int myidx = (lane < cnt) ? g_csr[base + lane] : 0;
        int e = 0;
        for (; e + 2 <= cnt; e += 2) {
            int sa = __shfl_sync(0xffffffffu, myidx, e);
            int sb = __shfl_sync(0xffffffffu, myidx, e + 1);
            uint2 va = ((const uint2*)(x + (size_t)sa * 128))[lane];
            uint2 vb = ((const uint2*)(x + (size_t)sb * 128))[lane];
            __nv_bfloat162 p0 = *(__nv_bfloat162*)&va.x;
            __nv_bfloat162 p1 = *(__nv_bfloat162*)&va.y;
            a0.x += __low2float(p0); a0.y += __high2float(p0);
            a0.z += __low2float(p1); a0.w += __high2float(p1);
            __nv_bfloat162 q0 = *(__nv_bfloat162*)&vb.x;
            __nv_bfloat162 q1 = *(__nv_bfloat162*)&vb.y;
            a1.x += __low2float(q0); a1.y += __high2float(q0);
            a1.z += __low2float(q1); a1.w += __high2float(q1);
        }
        if (e < cnt) {
            int sa = __shfl_sync(0xffffffffu, myidx, e);
            uint2 va = ((const uint2*)(x + (size_t)sa * 128))[lane];
            __nv_bfloat162 p0 = *(__nv_bfloat162*)&va.x;
            __nv_bfloat162 p1 = *(__nv_bfloat162*)&va.y;
            a0.x += __low2float(p0); a0.y += __high2float(p0);
            a0.z += __low2float(p1); a0.w += __high2float(p1);
        }
    }
    float4 v = make_float4(a0.x + a1.x, a0.y + a1.y, a0.z + a1.z, a0.w + a1.w);
    float rs = rowscale[node];
    float4 b = ((const float4*)bias)[lane];
    v.x = v.x * rs + b.x; v.y = v.y * rs + b.y;
    v.z = v.z * rs + b.z; v.w = v.w * rs + b.w;
    float m = fmaxf(fmaxf(v.x, v.y), fmaxf(v.z, v.w));
#pragma unroll
    for (int off = 16; off > 0; off >>= 1) m = fmaxf(m, __shfl_xor_sync(0xffffffffu, m, off));
    v.x = expf(v.x - m); v.y = expf(v.y - m);
    v.z = expf(v.z - m); v.w = expf(v.w - m);
    float s = v.x + v.y + v.z + v.w;
#pragma unroll
    for (int off = 16; off > 0; off >>= 1) s += __shfl_xor_sync(0xffffffffu, s, off);
    float inv = 1.f / s;
    v.x *= inv; v.y *= inv; v.z *= inv; v.w *= inv;
    ((float4*)out)[(size_t)node * 32 + lane] = v;
    uint2 r;
    __nv_bfloat162 p0 = __float22bfloat162_rn(make_float2(v.x, v.y));
    __nv_bfloat162 p1 = __float22bfloat162_rn(make_float2(v.z, v.w));
    r.x = *(uint32_t*)&p0; r.y = *(uint32_t*)&p1;
    ((uint2*)outb)[(size_t)node * 32 + lane] = r;
}

// ---------------- bf16 tensor-core GEMM, BN=128, cp.async 2-stage ----------------
__device__ __forceinline__ void mma_bf16(float* d, const uint32_t* a, const uint32_t* b) {
    asm volatile(
        "mma.sync.aligned.m16n8k16.row.col.f32.bf16.bf16.f32 "
        "{%0,%1,%2,%3}, {%4,%5,%6,%7}, {%8,%9}, {%0,%1,%2,%3};"
        : "+f"(d[0]), "+f"(d[1]), "+f"(d[2]), "+f"(d[3])
        : "r"(a[0]), "r"(a[1]), "r"(a[2]), "r"(a[3]), "r"(b[0]), "r"(b[1]));
}
__device__ __forceinline__ void cp16(uint32_t dst, const void* src, int sz) {
    asm volatile("cp.async.cg.shared.global [%0], [%1], 16, %2;" :: "r"(dst), "l"(src), "r"(sz) : "memory");
}
#define CP_COMMIT() asm volatile("cp.async.commit_group;" ::: "memory")

template <int ACT, int OUTB>
__global__ void __launch_bounds__(256)
k_gemm_bf16(const __nv_bfloat16* __restrict__ A, const __nv_bfloat16* __restrict__ WT,
            void* __restrict__ Cout, int M, int K, int N,
            const float* __restrict__ prescale, const float* __restrict__ bias,
            const float* __restrict__ postscale) {
    extern __shared__ __nv_bfloat16 sm[];
    constexpr int AW = 128 * 72;
    constexpr int BW = 128 * 72;
    __nv_bfloat16* As = sm;
    __nv_bfloat16* Bs = sm + 2 * AW;
    uint32_t sA = (uint32_t)__cvta_generic_to_shared(As);
    uint32_t sB = (uint32_t)__cvta_generic_to_shared(Bs);

    int tid = threadIdx.x;
    int warp = tid >> 5, lane = tid & 31;
    int g = lane >> 2, t = lane & 3;
    int wm = warp >> 1, wn = warp & 1;
    int bm = blockIdx.x * 128, bn = blockIdx.y * 128;
    int lrow = tid >> 3, lq = tid & 7;

    float acc[2][8][4];
#pragma unroll
    for (int mt = 0; mt < 2; mt++)
#pragma unroll
        for (int nt = 0; nt < 8; nt++)
#pragma unroll
            for (int j = 0; j < 4; j++) acc[mt][nt][j] = 0.f;

    const int T = K >> 6;

    auto load_tile = [&](int stage, int kt) {
#pragma unroll
        for (int i = 0; i < 4; i++) {
            int row = lrow + i * 32;
            int gm = bm + row;
            cp16(sA + (uint32_t)(stage * AW + row * 72 + lq * 8) * 2,
                 A + (size_t)gm * K + kt + lq * 8, (gm < M) ? 16 : 0);
        }
#pragma unroll
        for (int i = 0; i < 4; i++) {
            int row = lrow + i * 32;
            cp16(sB + (uint32_t)(stage * BW + row * 72 + lq * 8) * 2,
                 WT + (size_t)(bn + row) * K + kt + lq * 8, 16);
        }
    };

    load_tile(0, 0);
    CP_COMMIT();

    for (int ti = 0; ti < T; ti++) {
        if (ti + 1 < T) {
            load_tile((ti + 1) & 1, (ti + 1) * 64);
            CP_COMMIT();
            asm volatile("cp.async.wait_group 1;" ::: "memory");
        } else {
            asm volatile("cp.async.wait_group 0;" ::: "memory");
        }
        __syncthreads();

        const uint32_t* Asu = (const uint32_t*)(As + (ti & 1) * AW);
        const uint32_t* Bsu = (const uint32_t*)(Bs + (ti & 1) * BW);
#pragma unroll
        for (int k16 = 0; k16 < 4; k16++) {
            int kw = k16 * 8;
            uint32_t a[2][4];
#pragma unroll
            for (int mt = 0; mt < 2; mt++) {
                int r0 = (wm * 32 + mt * 16 + g) * 36 + kw + t;
                a[mt][0] = Asu[r0];
                a[mt][1] = Asu[r0 + 8 * 36];
                a[mt][2] = Asu[r0 + 4];
                a[mt][3] = Asu[r0 + 8 * 36 + 4];
            }
            uint32_t b[8][2];
#pragma unroll
            for (int nt = 0; nt < 8; nt++) {
                int r0 = (wn * 64 + nt * 8 + g) * 36 + kw + t;
                b[nt][0] = Bsu[r0];
                b[nt][1] = Bsu[r0 + 4];
            }
#pragma unroll
            for (int mt = 0; mt < 2; mt++)
#pragma unroll
                for (int nt = 0; nt < 8; nt++)
                    mma_bf16(acc[mt][nt], a[mt], b[nt]);
        }
        __syncthreads();
    }

    float2 bv[8];
#pragma unroll
    for (int nt = 0; nt < 8; nt++) {
        if (bias) bv[nt] = *(const float2*)(bias + bn + wn * 64 + nt * 8 + 2 * t);
        else bv[nt] = make_float2(0.f, 0.f);
    }

    if (ACT == 2) {
        float* red = (float*)sm;
        float Mx[2][2];
#pragma unroll
        for (int mt = 0; mt < 2; mt++) {
#pragma unroll
            for (int h = 0; h < 2; h++) {
                int gm = bm + wm * 32 + mt * 16 + h * 8 + g;
                float pre = (prescale && gm < M) ? prescale[gm] : 1.f;
                float lm = -1e30f;
#pragma unroll
                for (int nt = 0; nt < 8; nt++) {
                    float ox = acc[mt][nt][2 * h]     * pre + bv[nt].x;
                    float oy = acc[mt][nt][2 * h + 1] * pre + bv[nt].y;
                    acc[mt][nt][2 * h] = ox; acc[mt][nt][2 * h + 1] = oy;
                    lm = fmaxf(lm, fmaxf(ox, oy));
                }
                lm = fmaxf(lm, __shfl_xor_sync(0xffffffffu, lm, 1));
                lm = fmaxf(lm, __shfl_xor_sync(0xffffffffu, lm, 2));
                int r = wm * 32 + mt * 16 + h * 8 + g;
                if (t == 0) red[r * 2 + wn] = lm;
            }
        }
        __syncthreads();
#pragma unroll
        for (int mt = 0; mt < 2; mt++)
#pragma unroll
            for (int h = 0; h < 2; h++) {
                int r = wm * 32 + mt * 16 + h * 8 + g;
                Mx[mt][h] = fmaxf(red[r * 2], red[r * 2 + 1]);
            }
        __syncthreads();
#pragma unroll
        for (int mt = 0; mt < 2; mt++) {
#pragma unroll
            for (int h = 0; h < 2; h++) {
                float ls = 0.f;
#pragma unroll
                for (int nt = 0; nt < 8; nt++) {
                    float ex = expf(acc[mt][nt][2 * h]     - Mx[mt][h]);
                    float ey = expf(acc[mt][nt][2 * h + 1] - Mx[mt][h]);
                    acc[mt][nt][2 * h] = ex; acc[mt][nt][2 * h + 1] = ey;
                    ls += ex + ey;
                }
                ls += __shfl_xor_sync(0xffffffffu, ls, 1);
                ls += __shfl_xor_sync(0xffffffffu, ls, 2);
                int r = wm * 32 + mt * 16 + h * 8 + g;
                if (t == 0) red[r * 2 + wn] = ls;
            }
        }
        __syncthreads();
#pragma unroll
        for (int mt = 0; mt < 2; mt++) {
#pragma unroll
            for (int h = 0; h < 2; h++) {
                int r = wm * 32 + mt * 16 + h * 8 + g;
                float inv = 1.f / (red[r * 2] + red[r * 2 + 1]);
                int gm = bm + wm * 32 + mt * 16 + h * 8 + g;
                if (gm >= M) continue;
#pragma unroll
                for (int nt = 0; nt < 8; nt++) {
                    float2 o = make_float2(acc[mt][nt][2 * h] * inv, acc[mt][nt][2 * h + 1] * inv);
                    *(float2*)((float*)Cout + (size_t)gm * N + bn + wn * 64 + nt * 8 + 2 * t) = o;
                }
            }
        }
        return;
    }

#pragma unroll
    for (int mt = 0; mt < 2; mt++) {
#pragma unroll
        for (int h = 0; h < 2; h++) {
            int gm = bm + wm * 32 + mt * 16 + h * 8 + g;
            if (gm >= M) continue;
            float pre = prescale ? prescale[gm] : 1.f;
            float post = postscale ? postscale[gm] : 1.f;
#pragma unroll
            for (int nt = 0; nt < 8; nt++) {
                float ox = acc[mt][nt][2 * h]     * pre + bv[nt].x;
                float oy = acc[mt][nt][2 * h + 1] * pre + bv[nt].y;
                if (ACT == 1) { ox = tanhf(ox); oy = tanhf(oy); }
                ox *= post; oy *= post;
                size_t off = (size_t)gm * N + bn + wn * 64 + nt * 8 + 2 * t;
                if (OUTB) {
                    __nv_bfloat162 p = __float22bfloat162_rn(make_float2(ox, oy));
                    *(uint32_t*)((__nv_bfloat16*)Cout + off) = *(uint32_t*)&p;
                } else {
                    *(float2*)((float*)Cout + off) = make_float2(ox, oy);
                }
            }
        }
    }
}

// ---------------- launcher: fork-join dual-stream schedule ----------------
extern "C" void kernel_launch(void* const* d_in, const int* in_sizes, int n_in,
                              void* d_out, int out_size) {
    const float* in_feat = (const float*)d_in[0];
    const int*   src     = (const int*)d_in[1];
    const int*   dst     = (const int*)d_in[2];
    const float* Wc0 = (const float*)d_in[3];
    const float* bc0 = (const float*)d_in[4];
    const float* Wc1 = (const float*)d_in[5];
    const float* bc1 = (const float*)d_in[6];
    const float* Wc2 = (const float*)d_in[7];
    const float* bc2 = (const float*)d_in[8];
    const float* Wr0 = (const float*)d_in[9];
    const float* br0 = (const float*)d_in[10];
    const float* Wr1 = (const float*)d_in[11];
    const float* br1 = (const float*)d_in[12];
    const float* Wr2 = (const float*)d_in[13];
    const float* br2 = (const float*)d_in[14];
    float* out = (float*)d_out;

    float *bufA, *bufB, *bufC, *sout, *sin, *wt;
    cudaGetSymbolAddress((void**)&bufA, g_bufA);
    cudaGetSymbolAddress((void**)&bufB, g_bufB);
    cudaGetSymbolAddress((void**)&bufC, g_bufC);
    cudaGetSymbolAddress((void**)&sout, g_sout);
    cudaGetSymbolAddress((void**)&sin,  g_sin);
    cudaGetSymbolAddress((void**)&wt,   g_wt);

    __nv_bfloat16* bA16 = (__nv_bfloat16*)bufA;
    __nv_bfloat16* bB16 = (__nv_bfloat16*)bufB;
    __nv_bfloat16* bC16 = (__nv_bfloat16*)bufC;
    __nv_bfloat16* t116 = (__nv_bfloat16*)bufC + (size_t)NN * 128;
    __nv_bfloat16* WTc0 = (__nv_bfloat16*)(wt + 0 * 65536);
    __nv_bfloat16* WTc1 = (__nv_bfloat16*)(wt + 1 * 65536);
    __nv_bfloat16* WTc2 = (__nv_bfloat16*)(wt + 2 * 65536);
    __nv_bfloat16* WTr0 = (__nv_bfloat16*)(wt + 3 * 65536);
    __nv_bfloat16* WTr1 = (__nv_bfloat16*)(wt + 4 * 65536);
    __nv_bfloat16* WTr2 = (__nv_bfloat16*)(wt + 5 * 65536);

    const int M = NN;
    dim3 g_n((NN + 255) / 256);
    dim3 g_e(4096);
    dim3 g_w((NN * 32 + 255) / 256);
    dim3 gw0((CH0 * 32 + 255) / 256), gw1((CH1 * 32 + 255) / 256);
    const int GT0 = (CH0 + 127) / 128;
    const int GT1 = (CH1 + 127) / 128;

    const int SMEM_GEMM = (2 * 128 * 72 + 2 * 128 * 72) * 2;
    static cudaStream_t s1 = nullptr;
    static cudaEvent_t evRoot, evHist, evPre, evA1, evG1, evA2, evG2, evG3, evS0, evR0;
    if (!s1) {
        cudaFuncSetAttribute(k_gemm_bf16<1, 1>, cudaFuncAttributeMaxDynamicSharedMemorySize, SMEM_GEMM);
        cudaFuncSetAttribute(k_gemm_bf16<0, 1>, cudaFuncAttributeMaxDynamicSharedMemorySize, SMEM_GEMM);
        cudaFuncSetAttribute(k_gemm_bf16<2, 0>, cudaFuncAttributeMaxDynamicSharedMemorySize, SMEM_GEMM);
        cudaStreamCreateWithFlags(&s1, cudaStreamNonBlocking);
        cudaEventCreateWithFlags(&evRoot, cudaEventDisableTiming);
        cudaEventCreateWithFlags(&evHist, cudaEventDisableTiming);
        cudaEventCreateWithFlags(&evPre,  cudaEventDisableTiming);
        cudaEventCreateWithFlags(&evA1,   cudaEventDisableTiming);
        cudaEventCreateWithFlags(&evG1,   cudaEventDisableTiming);
        cudaEventCreateWithFlags(&evA2,   cudaEventDisableTiming);
        cudaEventCreateWithFlags(&evG2,   cudaEventDisableTiming);
        cudaEventCreateWithFlags(&evG3,   cudaEventDisableTiming);
        cudaEventCreateWithFlags(&evS0,   cudaEventDisableTiming);
        cudaEventCreateWithFlags(&evR0,   cudaEventDisableTiming);
    }

    // ---- fork: side stream transposes; scales+prescale after hist ----
    cudaEventRecord(evRoot, 0);
    cudaStreamWaitEvent(s1, evRoot, 0);
    k_transpose_all<<<dim3(8, 8, 6), dim3(32, 8), 0, s1>>>(Wc0, Wc1, Wc2, Wr0, Wr1, Wr2,
                                                           WTc0, WTc1, WTc2, WTr0, WTr1, WTr2);
    // main: CSR chain (multi-block scan)
    k_zero_counts<<<g_n, 256>>>();
    k_hist<<<g_e, 256>>>(src, dst);
    cudaEventRecord(evHist, 0);
    k_scan1<<<SCAN_NB, 1024>>>();
    k_scan2<<<1, 128>>>();
    k_scan3<<<SCAN_NB, 1024>>>();
    k_fill<<<g_e, 256>>>(src, dst);
    // side: scales + prescale
    cudaStreamWaitEvent(s1, evHist, 0);
    k_scales<<<g_n, 256, 0, s1>>>();
    k_prescale<<<g_w, 256, 0, s1>>>(in_feat, bA16);
    cudaEventRecord(evPre, s1);
    cudaStreamWaitEvent(0, evPre, 0);

    // ---- conv1: agg(x)->bB16 ; gemm->bC16, chunk-pipelined ----
    k_agg_b16<128, 1><<<gw0, 256>>>(bA16, bB16, 0, CH0);
    cudaEventRecord(evA1, 0);
    k_agg_b16<128, 1><<<gw1, 256>>>(bA16, bB16, CH0, CH1);
    cudaStreamWaitEvent(s1, evA1, 0);
    k_gemm_bf16<1, 1><<<dim3(GT0, 2), 256, SMEM_GEMM, s1>>>(bB16, WTc0, bC16, CH0, 128, 256, sin, bc0, sout);
    k_gemm_bf16<1, 1><<<dim3(GT1, 2), 256, SMEM_GEMM>>>(bB16 + (size_t)CH0 * 128, WTc0,
                                                        bC16 + (size_t)CH0 * 256, CH1, 128, 256,
                                                        sin + CH0, bc0, sout + CH0);
    cudaEventRecord(evG1, s1);
    cudaStreamWaitEvent(0, evG1, 0);

    // ---- conv2: agg(bC16)->bB16 ; gemm->bA16 ; conv3 gemm chunked right behind ----
    k_agg_b16<256, 1><<<gw0, 256>>>(bC16, bB16, 0, CH0);
    cudaEventRecord(evA2, 0);
    k_agg_b16<256, 1><<<gw1, 256>>>(bC16, bB16, CH0, CH1);
    cudaStreamWaitEvent(s1, evA2, 0);
    // s1: conv2 gemm ch0, then conv3 gemm ch0 (reads bA16 ch0 only)
    k_gemm_bf16<1, 1><<<dim3(GT0, 2), 256, SMEM_GEMM, s1>>>(bB16, WTc1, bA16, CH0, 256, 256, sin, bc1, sout);
    k_gemm_bf16<0, 1><<<dim3(GT0, 1), 256, SMEM_GEMM, s1>>>(bA16, WTc2, bB16, CH0, 256, 128, nullptr, nullptr, nullptr);
    cudaEventRecord(evG3, s1);
    // main: conv2 gemm ch1, then conv3 gemm ch1
    k_gemm_bf16<1, 1><<<dim3(GT1, 2), 256, SMEM_GEMM>>>(bB16 + (size_t)CH0 * 256, WTc1,
                                                        bA16 + (size_t)CH0 * 256, CH1, 256, 256,
                                                        sin + CH0, bc1, sout + CH0);
    k_gemm_bf16<0, 1><<<dim3(GT1, 1), 256, SMEM_GEMM>>>(bA16 + (size_t)CH0 * 256, WTc2,
                                                        bB16 + (size_t)CH0 * 128, CH1, 256, 128, nullptr, nullptr, nullptr);
    cudaStreamWaitEvent(0, evG3, 0);

    // ---- conv3 agg+softmax -> out & h16(bC16), chunked; MLP dual-chain ----
    k_agg_smax128<<<gw0, 256>>>(bB16, out, bC16, sin, bc2, 0, CH0);
    cudaEventRecord(evS0, 0);
    k_agg_smax128<<<gw1, 256>>>(bB16, out, bC16, sin, bc2, CH0, CH1);

    cudaStreamWaitEvent(s1, evS0, 0);
    k_gemm_bf16<1, 1><<<dim3(GT0, 2), 256, SMEM_GEMM, s1>>>(bC16, WTr0, bA16, CH0, 128, 256, nullptr, br0, nullptr);
    k_gemm_bf16<1, 1><<<dim3(GT0, 2), 256, SMEM_GEMM, s1>>>(bA16, WTr1, t116, CH0, 256, 256, nullptr, br1, nullptr);
    k_gemm_bf16<2, 0><<<dim3(GT0, 1), 256, SMEM_GEMM, s1>>>(t116, WTr2, out + (size_t)M * 128, CH0, 256, 128, nullptr, br2, nullptr);
    cudaEventRecord(evR0, s1);

    k_gemm_bf16<1, 1><<<dim3(GT1, 2), 256, SMEM_GEMM>>>(bC16 + (size_t)CH0 * 128, WTr0,
                                                        bA16 + (size_t)CH0 * 256, CH1, 128, 256, nullptr, br0, nullptr);
    k_gemm_bf16<1, 1><<<dim3(GT1, 2), 256, SMEM_GEMM>>>(bA16 + (size_t)CH0 * 256, WTr1,
                                                        t116 + (size_t)CH0 * 256, CH1, 256, 256, nullptr, br1, nullptr);
    k_gemm_bf16<2, 0><<<dim3(GT1, 1), 256, SMEM_GEMM>>>(t116 + (size_t)CH0 * 256, WTr2,
                                                        out + (size_t)M * 128 + (size_t)CH0 * 128, CH1, 256, 128, nullptr, br2, nullptr);
    cudaStreamWaitEvent(0, evR0, 0);
}

// round 12
// speedup vs baseline: 3.3535x; 1.0040x over previous
#include <cuda_runtime.h>
#include <cuda_bf16.h>
#include <math.h>
#include <stdint.h>

#define NN 100000
#define EE 1600000
#define CH0 50048
#define CH1 (NN - CH0)
#define SCAN_NB ((NN + 1023) / 1024)

// ---------------- static scratch ----------------
__device__ float g_bufA[(size_t)NN * 256];
__device__ float g_bufB[(size_t)NN * 256];
__device__ float g_bufC[(size_t)NN * 256];
__device__ float g_sout[NN];
__device__ float g_sin[NN];
__device__ int   g_cnt_out[NN];
__device__ int   g_cnt_in[NN];
__device__ int   g_cursor[NN];
__device__ int   g_row_ptr[NN + 1];
__device__ int   g_csr[EE];
__device__ int   g_blocksum[128];
__device__ float g_wt[6][65536];

// ---------------- graph preprocessing ----------------
__global__ void k_zero_counts() {
    int i = blockIdx.x * blockDim.x + threadIdx.x;
    if (i < NN) { g_cnt_out[i] = 0; g_cnt_in[i] = 0; g_cursor[i] = 0; }
}
__global__ void k_hist(const int* __restrict__ src, const int* __restrict__ dst) {
    int stride = gridDim.x * blockDim.x;
    for (int i = blockIdx.x * blockDim.x + threadIdx.x; i < EE; i += stride) {
        atomicAdd(&g_cnt_out[src[i]], 1);
        atomicAdd(&g_cnt_in[dst[i]], 1);
    }
}
__global__ void k_scan1() {
    __shared__ int wsum[32];
    int b = blockIdx.x, t = threadIdx.x, lane = t & 31, w = t >> 5;
    int idx = b * 1024 + t;
    int x = (idx < NN) ? g_cnt_in[idx] : 0;
#pragma unroll
    for (int off = 1; off < 32; off <<= 1) {
        int y = __shfl_up_sync(0xffffffffu, x, off);
        if (lane >= off) x += y;
    }
    if (lane == 31) wsum[w] = x;
    __syncthreads();
    if (w == 0) {
        int s = wsum[lane];
#pragma unroll
        for (int off = 1; off < 32; off <<= 1) {
            int y = __shfl_up_sync(0xffffffffu, s, off);
            if (lane >= off) s += y;
        }
        wsum[lane] = s;
    }
    __syncthreads();
    int res = ((w > 0) ? wsum[w - 1] : 0) + x;
    if (idx < NN) g_row_ptr[idx + 1] = res;
    if (t == 1023) g_blocksum[b] = res;
}
__global__ void k_scan2() {
    __shared__ int wsum[4];
    int t = threadIdx.x, lane = t & 31, w = t >> 5;
    int v = (t < SCAN_NB) ? g_blocksum[t] : 0;
    int x = v;
#pragma unroll
    for (int off = 1; off < 32; off <<= 1) {
        int y = __shfl_up_sync(0xffffffffu, x, off);
        if (lane >= off) x += y;
    }
    if (lane == 31) wsum[w] = x;
    __syncthreads();
    if (t == 0) {
        int c = 0;
        for (int i = 0; i < 4; i++) { int tmp = wsum[i]; wsum[i] = c; c += tmp; }
    }
    __syncthreads();
    if (t < SCAN_NB) g_blocksum[t] = wsum[w] + x - v;
}
__global__ void k_scan3() {
    int b = blockIdx.x, t = threadIdx.x;
    int idx = b * 1024 + t;
    if (idx == 0) g_row_ptr[0] = 0;
    if (idx < NN && b > 0) g_row_ptr[idx + 1] += g_blocksum[b];
}
__global__ void k_fill(const int* __restrict__ src, const int* __restrict__ dst) {
    int stride = gridDim.x * blockDim.x;
    for (int i = blockIdx.x * blockDim.x + threadIdx.x; i < EE; i += stride) {
        int d = dst[i];
        int pos = g_row_ptr[d] + atomicAdd(&g_cursor[d], 1);
        g_csr[pos] = src[i];
    }
}
__global__ void k_scales() {
    int i = blockIdx.x * blockDim.x + threadIdx.x;
    if (i < NN) {
        g_sout[i] = rsqrtf(fmaxf((float)g_cnt_out[i], 1.f));
        g_sin[i]  = rsqrtf(fmaxf((float)g_cnt_in[i], 1.f));
    }
}

__global__ void k_transpose_all(
    const float* W0, const float* W1, const float* W2,
    const float* W3, const float* W4, const float* W5,
    __nv_bfloat16* T0, __nv_bfloat16* T1, __nv_bfloat16* T2,
    __nv_bfloat16* T3, __nv_bfloat16* T4, __nv_bfloat16* T5) {
    __shared__ float t[32][33];
    const float* W; __nv_bfloat16* WT; int K, N;
    switch (blockIdx.z) {
        case 0: W = W0; WT = T0; K = 128; N = 256; break;
        case 1: W = W1; WT = T1; K = 256; N = 256; break;
        case 2: W = W2; WT = T2; K = 256; N = 128; break;
        case 3: W = W3; WT = T3; K = 128; N = 256; break;
        case 4: W = W4; WT = T4; K = 256; N = 256; break;
        default: W = W5; WT = T5; K = 256; N = 128; break;
    }
    int k0 = blockIdx.x * 32, n0 = blockIdx.y * 32;
    if (k0 >= K || n0 >= N) return;
    int x = threadIdx.x, y = threadIdx.y;
    for (int i = 0; i < 32; i += 8) {
        int k = k0 + y + i, n = n0 + x;
        t[y + i][x] = (k < K && n < N) ? W[(size_t)k * N + n] : 0.f;
    }
    __syncthreads();
    for (int i = 0; i < 32; i += 8) {
        int n = n0 + y + i, k = k0 + x;
        if (n < N && k < K) WT[(size_t)n * K + k] = __float2bfloat16(t[x][y + i]);
    }
}

__global__ void k_prescale(const float* __restrict__ x, __nv_bfloat16* __restrict__ o) {
    int i = blockIdx.x * blockDim.x + threadIdx.x;
    if (i >= NN * 32) return;
    int m = i >> 5;
    float s = g_sout[m];
    float4 v = ((const float4*)x)[i];
    uint2 r;
    __nv_bfloat162 p0 = __float22bfloat162_rn(make_float2(v.x * s, v.y * s));
    __nv_bfloat162 p1 = __float22bfloat162_rn(make_float2(v.z * s, v.w * s));
    r.x = *(uint32_t*)&p0; r.y = *(uint32_t*)&p1;
    ((uint2*)o)[i] = r;
}

// ---------------- aggregation helpers ----------------
__device__ __forceinline__ void acc_add2(float4& a, uint2 v) {
    __nv_bfloat162 p0 = *(__nv_bfloat162*)&v.x;
    __nv_bfloat162 p1 = *(__nv_bfloat162*)&v.y;
    a.x += __low2float(p0); a.y += __high2float(p0);
    a.z += __low2float(p1); a.w += __high2float(p1);
}

// D=128 agg core: 4 gathers in flight
__device__ __forceinline__ float4 agg128_core(const __nv_bfloat16* __restrict__ x,
                                              int s0, int s1, int lane) {
    float4 a0 = make_float4(0.f, 0.f, 0.f, 0.f);
    float4 a1 = make_float4(0.f, 0.f, 0.f, 0.f);
    float4 a2 = make_float4(0.f, 0.f, 0.f, 0.f);
    float4 a3 = make_float4(0.f, 0.f, 0.f, 0.f);
    for (int base = s0; base < s1; base += 32) {
        int cnt = min(32, s1 - base);
        int myidx = (lane < cnt) ? g_csr[base + lane] : 0;
        int e = 0;
        for (; e + 4 <= cnt; e += 4) {
            int sa = __shfl_sync(0xffffffffu, myidx, e);
            int sb = __shfl_sync(0xffffffffu, myidx, e + 1);
            int sc = __shfl_sync(0xffffffffu, myidx, e + 2);
            int sd = __shfl_sync(0xffffffffu, myidx, e + 3);
            uint2 va = ((const uint2*)(x + (size_t)sa * 128))[lane];
            uint2 vb = ((const uint2*)(x + (size_t)sb * 128))[lane];
            uint2 vc = ((const uint2*)(x + (size_t)sc * 128))[lane];
            uint2 vd = ((const uint2*)(x + (size_t)sd * 128))[lane];
            acc_add2(a0, va); acc_add2(a1, vb); acc_add2(a2, vc); acc_add2(a3, vd);
        }
        for (; e < cnt; e++) {
            int sa = __shfl_sync(0xffffffffu, myidx, e);
            uint2 va = ((const uint2*)(x + (size_t)sa * 128))[lane];
            acc_add2(a0, va);
        }
    }
    return make_float4(a0.x + a1.x + a2.x + a3.x, a0.y + a1.y + a2.y + a3.y,
                       a0.z + a1.z + a2.z + a3.z, a0.w + a1.w + a2.w + a3.w);
}

template <int D, int OUTB>
__global__ void k_agg_b16(const __nv_bfloat16* __restrict__ x, void* __restrict__ out,
                          int n0, int ncnt) {
    int wloc = (blockIdx.x * blockDim.x + threadIdx.x) >> 5;
    int lane = threadIdx.x & 31;
    if (wloc >= ncnt) return;
    int node = n0 + wloc;
    int s0 = g_row_ptr[node], s1 = g_row_ptr[node + 1];

    if (D == 128) {
        float4 acc = agg128_core(x, s0, s1, lane);
        if (OUTB) {
            uint2 r;
            __nv_bfloat162 p0 = __float22bfloat162_rn(make_float2(acc.x, acc.y));
            __nv_bfloat162 p1 = __float22bfloat162_rn(make_float2(acc.z, acc.w));
            r.x = *(uint32_t*)&p0; r.y = *(uint32_t*)&p1;
            ((uint2*)out)[(size_t)node * 32 + lane] = r;
        } else {
            ((float4*)out)[(size_t)node * 32 + lane] = acc;
        }
    } else {  // D == 256, 2 gathers in flight (uint4 per lane)
        float a0[8], a1[8];
#pragma unroll
        for (int j = 0; j < 8; j++) { a0[j] = 0.f; a1[j] = 0.f; }
        for (int base = s0; base < s1; base += 32) {
            int cnt = min(32, s1 - base);
            int myidx = (lane < cnt) ? g_csr[base + lane] : 0;
            int e = 0;
            for (; e + 2 <= cnt; e += 2) {
                int sa = __shfl_sync(0xffffffffu, myidx, e);
                int sb = __shfl_sync(0xffffffffu, myidx, e + 1);
                uint4 va = ((const uint4*)(x + (size_t)sa * 256))[lane];
                uint4 vb = ((const uint4*)(x + (size_t)sb * 256))[lane];
                {
                    __nv_bfloat162 p0 = *(__nv_bfloat162*)&va.x, p1 = *(__nv_bfloat162*)&va.y;
                    __nv_bfloat162 p2 = *(__nv_bfloat162*)&va.z, p3 = *(__nv_bfloat162*)&va.w;
                    a0[0] += __low2float(p0); a0[1] += __high2float(p0);
                    a0[2] += __low2float(p1); a0[3] += __high2float(p1);
                    a0[4] += __low2float(p2); a0[5] += __high2float(p2);
                    a0[6] += __low2float(p3); a0[7] += __high2float(p3);
                }
                {
                    __nv_bfloat162 p0 = *(__nv_bfloat162*)&vb.x, p1 = *(__nv_bfloat162*)&vb.y;
                    __nv_bfloat162 p2 = *(__nv_bfloat162*)&vb.z, p3 = *(__nv_bfloat162*)&vb.w;
                    a1[0] += __low2float(p0); a1[1] += __high2float(p0);
                    a1[2] += __low2float(p1); a1[3] += __high2float(p1);
                    a1[4] += __low2float(p2); a1[5] += __high2float(p2);
                    a1[6] += __low2float(p3); a1[7] += __high2float(p3);
                }
            }
            if (e < cnt) {
                int sa = __shfl_sync(0xffffffffu, myidx, e);
                uint4 va = ((const uint4*)(x + (size_t)sa * 256))[lane];
                __nv_bfloat162 p0 = *(__nv_bfloat162*)&va.x, p1 = *(__nv_bfloat162*)&va.y;
                __nv_bfloat162 p2 = *(__nv_bfloat162*)&va.z, p3 = *(__nv_bfloat162*)&va.w;
                a0[0] += __low2float(p0); a0[1] += __high2float(p0);
                a0[2] += __low2float(p1); a0[3] += __high2float(p1);
                a0[4] += __low2float(p2); a0[5] += __high2float(p2);
                a0[6] += __low2float(p3); a0[7] += __high2float(p3);
            }
        }
        uint4 r;
        __nv_bfloat162 q0 = __float22bfloat162_rn(make_float2(a0[0] + a1[0], a0[1] + a1[1]));
        __nv_bfloat162 q1 = __float22bfloat162_rn(make_float2(a0[2] + a1[2], a0[3] + a1[3]));
        __nv_bfloat162 q2 = __float22bfloat162_rn(make_float2(a0[4] + a1[4], a0[5] + a1[5]));
        __nv_bfloat162 q3 = __float22bfloat162_rn(make_float2(a0[6] + a1[6], a0[7] + a1[7]));
        r.x = *(uint32_t*)&q0; r.y = *(uint32_t*)&q1;
        r.z = *(uint32_t*)&q2; r.w = *(uint32_t*)&q3;
        ((uint4*)out)[(size_t)node * 32 + lane] = r;
    }
}

// conv3: agg(D=128) + fused scale+bias+softmax
__global__ void k_agg_smax128(const __nv_bfloat16* __restrict__ x,
                              float* __restrict__ out, __nv_bfloat16* __restrict__ outb,
                              const float* __restrict__ rowscale, const float* __restrict__ bias,
                              int n0, int ncnt) {
    int wloc = (blockIdx.x * blockDim.x + threadIdx.x) >> 5;
    int lane = threadIdx.x & 31;
    if (wloc >= ncnt) return;
    int node = n0 + wloc;
    int s0 = g_row_ptr[node], s1 = g_row_ptr[node + 1];
    float4 v = agg128_core(x, s0, s1, lane);
    float rs = rowscale[node];
    float4 b = ((const float4*)bias)[lane];
    v.x = v.x * rs + b.x; v.y = v.y * rs + b.y;
    v.z = v.z * rs + b.z; v.w = v.w * rs + b.w;
    float m = fmaxf(fmaxf(v.x, v.y), fmaxf(v.z, v.w));
#pragma unroll
    for (int off = 16; off > 0; off >>= 1) m = fmaxf(m, __shfl_xor_sync(0xffffffffu, m, off));
    v.x = expf(v.x - m); v.y = expf(v.y - m);
    v.z = expf(v.z - m); v.w = expf(v.w - m);
    float s = v.x + v.y + v.z + v.w;
#pragma unroll
    for (int off = 16; off > 0; off >>= 1) s += __shfl_xor_sync(0xffffffffu, s, off);
    float inv = 1.f / s;
    v.x *= inv; v.y *= inv; v.z *= inv; v.w *= inv;
    ((float4*)out)[(size_t)node * 32 + lane] = v;
    uint2 r;
    __nv_bfloat162 p0 = __float22bfloat162_rn(make_float2(v.x, v.y));
    __nv_bfloat162 p1 = __float22bfloat162_rn(make_float2(v.z, v.w));
    r.x = *(uint32_t*)&p0; r.y = *(uint32_t*)&p1;
    ((uint2*)outb)[(size_t)node * 32 + lane] = r;
}

// ---------------- bf16 tensor-core GEMM, BN=128, cp.async 2-stage, 2 CTAs/SM ----------------
__device__ __forceinline__ void mma_bf16(float* d, const uint32_t* a, const uint32_t* b) {
    asm volatile(
        "mma.sync.aligned.m16n8k16.row.col.f32.bf16.bf16.f32 "
        "{%0,%1,%2,%3}, {%4,%5,%6,%7}, {%8,%9}, {%0,%1,%2,%3};"
        : "+f"(d[0]), "+f"(d[1]), "+f"(d[2]), "+f"(d[3])
        : "r"(a[0]), "r"(a[1]), "r"(a[2]), "r"(a[3]), "r"(b[0]), "r"(b[1]));
}
__device__ __forceinline__ void cp16(uint32_t dst, const void* src, int sz) {
    asm volatile("cp.async.cg.shared.global [%0], [%1], 16, %2;" :: "r"(dst), "l"(src), "r"(sz) : "memory");
}
#define CP_COMMIT() asm volatile("cp.async.commit_group;" ::: "memory")

template <int ACT, int OUTB>
__global__ void __launch_bounds__(256, 2)
k_gemm_bf16(const __nv_bfloat16* __restrict__ A, const __nv_bfloat16* __restrict__ WT,
            void* __restrict__ Cout, int M, int K, int N,
            const float* __restrict__ prescale, const float* __restrict__ bias,
            const float* __restrict__ postscale) {
    extern __shared__ __nv_bfloat16 sm[];
    constexpr int AW = 128 * 72;
    constexpr int BW = 128 * 72;
    __nv_bfloat16* As = sm;
    __nv_bfloat16* Bs = sm + 2 * AW;
    uint32_t sA = (uint32_t)__cvta_generic_to_shared(As);
    uint32_t sB = (uint32_t)__cvta_generic_to_shared(Bs);

    int tid = threadIdx.x;
    int warp = tid >> 5, lane = tid & 31;
    int g = lane >> 2, t = lane & 3;
    int wm = warp >> 1, wn = warp & 1;
    int bm = blockIdx.x * 128, bn = blockIdx.y * 128;
    int lrow = tid >> 3, lq = tid & 7;

    float acc[2][8][4];
#pragma unroll
    for (int mt = 0; mt < 2; mt++)
#pragma unroll
        for (int nt = 0; nt < 8; nt++)
#pragma unroll
            for (int j = 0; j < 4; j++) acc[mt][nt][j] = 0.f;

    const int T = K >> 6;

    auto load_tile = [&](int stage, int kt) {
#pragma unroll
        for (int i = 0; i < 4; i++) {
            int row = lrow + i * 32;
            int gm = bm + row;
            cp16(sA + (uint32_t)(stage * AW + row * 72 + lq * 8) * 2,
                 A + (size_t)gm * K + kt + lq * 8, (gm < M) ? 16 : 0);
        }
#pragma unroll
        for (int i = 0; i < 4; i++) {
            int row = lrow + i * 32;
            cp16(sB + (uint32_t)(stage * BW + row * 72 + lq * 8) * 2,
                 WT + (size_t)(bn + row) * K + kt + lq * 8, 16);
        }
    };

    load_tile(0, 0);
    CP_COMMIT();

    for (int ti = 0; ti < T; ti++) {
        if (ti + 1 < T) {
            load_tile((ti + 1) & 1, (ti + 1) * 64);
            CP_COMMIT();
            asm volatile("cp.async.wait_group 1;" ::: "memory");
        } else {
            asm volatile("cp.async.wait_group 0;" ::: "memory");
        }
        __syncthreads();

        const uint32_t* Asu = (const uint32_t*)(As + (ti & 1) * AW);
        const uint32_t* Bsu = (const uint32_t*)(Bs + (ti & 1) * BW);
#pragma unroll
        for (int k16 = 0; k16 < 4; k16++) {
            int kw = k16 * 8;
            uint32_t a[2][4];
#pragma unroll
            for (int mt = 0; mt < 2; mt++) {
                int r0 = (wm * 32 + mt * 16 + g) * 36 + kw + t;
                a[mt][0] = Asu[r0];
                a[mt][1] = Asu[r0 + 8 * 36];
                a[mt][2] = Asu[r0 + 4];
                a[mt][3] = Asu[r0 + 8 * 36 + 4];
            }
            uint32_t b[8][2];
#pragma unroll
            for (int nt = 0; nt < 8; nt++) {
                int r0 = (wn * 64 + nt * 8 + g) * 36 + kw + t;
                b[nt][0] = Bsu[r0];
                b[nt][1] = Bsu[r0 + 4];
            }
#pragma unroll
            for (int mt = 0; mt < 2; mt++)
#pragma unroll
                for (int nt = 0; nt < 8; nt++)
                    mma_bf16(acc[mt][nt], a[mt], b[nt]);
        }
        __syncthreads();
    }

    float2 bv[8];
#pragma unroll
    for (int nt = 0; nt < 8; nt++) {
        if (bias) bv[nt] = *(const float2*)(bias + bn + wn * 64 + nt * 8 + 2 * t);
        else bv[nt] = make_float2(0.f, 0.f);
    }

    if (ACT == 2) {
        float* red = (float*)sm;
        float Mx[2][2];
#pragma unroll
        for (int mt = 0; mt < 2; mt++) {
#pragma unroll
            for (int h = 0; h < 2; h++) {
                int gm = bm + wm * 32 + mt * 16 + h * 8 + g;
                float pre = (prescale && gm < M) ? prescale[gm] : 1.f;
                float lm = -1e30f;
#pragma unroll
                for (int nt = 0; nt < 8; nt++) {
                    float ox = acc[mt][nt][2 * h]     * pre + bv[nt].x;
                    float oy = acc[mt][nt][2 * h + 1] * pre + bv[nt].y;
                    acc[mt][nt][2 * h] = ox; acc[mt][nt][2 * h + 1] = oy;
                    lm = fmaxf(lm, fmaxf(ox, oy));
                }
                lm = fmaxf(lm, __shfl_xor_sync(0xffffffffu, lm, 1));
                lm = fmaxf(lm, __shfl_xor_sync(0xffffffffu, lm, 2));
                int r = wm * 32 + mt * 16 + h * 8 + g;
                if (t == 0) red[r * 2 + wn] = lm;
            }
        }
        __syncthreads();
#pragma unroll
        for (int mt = 0; mt < 2; mt++)
#pragma unroll
            for (int h = 0; h < 2; h++) {
                int r = wm * 32 + mt * 16 + h * 8 + g;
                Mx[mt][h] = fmaxf(red[r * 2], red[r * 2 + 1]);
            }
        __syncthreads();
#pragma unroll
        for (int mt = 0; mt < 2; mt++) {
#pragma unroll
            for (int h = 0; h < 2; h++) {
                float ls = 0.f;
#pragma unroll
                for (int nt = 0; nt < 8; nt++) {
                    float ex = expf(acc[mt][nt][2 * h]     - Mx[mt][h]);
                    float ey = expf(acc[mt][nt][2 * h + 1] - Mx[mt][h]);
                    acc[mt][nt][2 * h] = ex; acc[mt][nt][2 * h + 1] = ey;
                    ls += ex + ey;
                }
                ls += __shfl_xor_sync(0xffffffffu, ls, 1);
                ls += __shfl_xor_sync(0xffffffffu, ls, 2);
                int r = wm * 32 + mt * 16 + h * 8 + g;
                if (t == 0) red[r * 2 + wn] = ls;
            }
        }
        __syncthreads();
#pragma unroll
        for (int mt = 0; mt < 2; mt++) {
#pragma unroll
            for (int h = 0; h < 2; h++) {
                int r = wm * 32 + mt * 16 + h * 8 + g;
                float inv = 1.f / (red[r * 2] + red[r * 2 + 1]);
                int gm = bm + wm * 32 + mt * 16 + h * 8 + g;
                if (gm >= M) continue;
#pragma unroll
                for (int nt = 0; nt < 8; nt++) {
                    float2 o = make_float2(acc[mt][nt][2 * h] * inv, acc[mt][nt][2 * h + 1] * inv);
                    *(float2*)((float*)Cout + (size_t)gm * N + bn + wn * 64 + nt * 8 + 2 * t) = o;
                }
            }
        }
        return;
    }

#pragma unroll
    for (int mt = 0; mt < 2; mt++) {
#pragma unroll
        for (int h = 0; h < 2; h++) {
            int gm = bm + wm * 32 + mt * 16 + h * 8 + g;
            if (gm >= M) continue;
            float pre = prescale ? prescale[gm] : 1.f;
            float post = postscale ? postscale[gm] : 1.f;
#pragma unroll
            for (int nt = 0; nt < 8; nt++) {
                float ox = acc[mt][nt][2 * h]     * pre + bv[nt].x;
                float oy = acc[mt][nt][2 * h + 1] * pre + bv[nt].y;
                if (ACT == 1) { ox = tanhf(ox); oy = tanhf(oy); }
                ox *= post; oy *= post;
                size_t off = (size_t)gm * N + bn + wn * 64 + nt * 8 + 2 * t;
                if (OUTB) {
                    __nv_bfloat162 p = __float22bfloat162_rn(make_float2(ox, oy));
                    *(uint32_t*)((__nv_bfloat16*)Cout + off) = *(uint32_t*)&p;
                } else {
                    *(float2*)((float*)Cout + off) = make_float2(ox, oy);
                }
            }
        }
    }
}

// ---------------- launcher: fork-join dual-stream schedule ----------------
extern "C" void kernel_launch(void* const* d_in, const int* in_sizes, int n_in,
                              void* d_out, int out_size) {
    const float* in_feat = (const float*)d_in[0];
    const int*   src     = (const int*)d_in[1];
    const int*   dst     = (const int*)d_in[2];
    const float* Wc0 = (const float*)d_in[3];
    const float* bc0 = (const float*)d_in[4];
    const float* Wc1 = (const float*)d_in[5];
    const float* bc1 = (const float*)d_in[6];
    const float* Wc2 = (const float*)d_in[7];
    const float* bc2 = (const float*)d_in[8];
    const float* Wr0 = (const float*)d_in[9];
    const float* br0 = (const float*)d_in[10];
    const float* Wr1 = (const float*)d_in[11];
    const float* br1 = (const float*)d_in[12];
    const float* Wr2 = (const float*)d_in[13];
    const float* br2 = (const float*)d_in[14];
    float* out = (float*)d_out;

    float *bufA, *bufB, *bufC, *sout, *sin, *wt;
    cudaGetSymbolAddress((void**)&bufA, g_bufA);
    cudaGetSymbolAddress((void**)&bufB, g_bufB);
    cudaGetSymbolAddress((void**)&bufC, g_bufC);
    cudaGetSymbolAddress((void**)&sout, g_sout);
    cudaGetSymbolAddress((void**)&sin,  g_sin);
    cudaGetSymbolAddress((void**)&wt,   g_wt);

    __nv_bfloat16* bA16 = (__nv_bfloat16*)bufA;
    __nv_bfloat16* bB16 = (__nv_bfloat16*)bufB;
    __nv_bfloat16* bC16 = (__nv_bfloat16*)bufC;
    __nv_bfloat16* t116 = (__nv_bfloat16*)bufC + (size_t)NN * 128;
    __nv_bfloat16* WTc0 = (__nv_bfloat16*)(wt + 0 * 65536);
    __nv_bfloat16* WTc1 = (__nv_bfloat16*)(wt + 1 * 65536);
    __nv_bfloat16* WTc2 = (__nv_bfloat16*)(wt + 2 * 65536);
    __nv_bfloat16* WTr0 = (__nv_bfloat16*)(wt + 3 * 65536);
    __nv_bfloat16* WTr1 = (__nv_bfloat16*)(wt + 4 * 65536);
    __nv_bfloat16* WTr2 = (__nv_bfloat16*)(wt + 5 * 65536);

    const int M = NN;
    dim3 g_n((NN + 255) / 256);
    dim3 g_e(4096);
    dim3 g_w((NN * 32 + 255) / 256);
    dim3 gw0((CH0 * 32 + 255) / 256), gw1((CH1 * 32 + 255) / 256);
    const int GT0 = (CH0 + 127) / 128;
    const int GT1 = (CH1 + 127) / 128;

    const int SMEM_GEMM = (2 * 128 * 72 + 2 * 128 * 72) * 2;
    static cudaStream_t s1 = nullptr;
    static cudaEvent_t evRoot, evHist, evPre, evA1, evG1, evA2, evG3, evS0, evR0;
    if (!s1) {
        cudaFuncSetAttribute(k_gemm_bf16<1, 1>, cudaFuncAttributeMaxDynamicSharedMemorySize, SMEM_GEMM);
        cudaFuncSetAttribute(k_gemm_bf16<0, 1>, cudaFuncAttributeMaxDynamicSharedMemorySize, SMEM_GEMM);
        cudaFuncSetAttribute(k_gemm_bf16<2, 0>, cudaFuncAttributeMaxDynamicSharedMemorySize, SMEM_GEMM);
        cudaStreamCreateWithFlags(&s1, cudaStreamNonBlocking);
        cudaEventCreateWithFlags(&evRoot, cudaEventDisableTiming);
        cudaEventCreateWithFlags(&evHist, cudaEventDisableTiming);
        cudaEventCreateWithFlags(&evPre,  cudaEventDisableTiming);
        cudaEventCreateWithFlags(&evA1,   cudaEventDisableTiming);
        cudaEventCreateWithFlags(&evG1,   cudaEventDisableTiming);
        cudaEventCreateWithFlags(&evA2,   cudaEventDisableTiming);
        cudaEventCreateWithFlags(&evG3,   cudaEventDisableTiming);
        cudaEventCreateWithFlags(&evS0,   cudaEventDisableTiming);
        cudaEventCreateWithFlags(&evR0,   cudaEventDisableTiming);
    }

    // ---- fork: side stream transposes; scales+prescale after hist ----
    cudaEventRecord(evRoot, 0);
    cudaStreamWaitEvent(s1, evRoot, 0);
    k_transpose_all<<<dim3(8, 8, 6), dim3(32, 8), 0, s1>>>(Wc0, Wc1, Wc2, Wr0, Wr1, Wr2,
                                                           WTc0, WTc1, WTc2, WTr0, WTr1, WTr2);
    // main: CSR chain
    k_zero_counts<<<g_n, 256>>>();
    k_hist<<<g_e, 256>>>(src, dst);
    cudaEventRecord(evHist, 0);
    k_scan1<<<SCAN_NB, 1024>>>();
    k_scan2<<<1, 128>>>();
    k_scan3<<<SCAN_NB, 1024>>>();
    k_fill<<<g_e, 256>>>(src, dst);
    // side: scales + prescale
    cudaStreamWaitEvent(s1, evHist, 0);
    k_scales<<<g_n, 256, 0, s1>>>();
    k_prescale<<<g_w, 256, 0, s1>>>(in_feat, bA16);
    cudaEventRecord(evPre, s1);
    cudaStreamWaitEvent(0, evPre, 0);

    // ---- conv1 ----
    k_agg_b16<128, 1><<<gw0, 256>>>(bA16, bB16, 0, CH0);
    cudaEventRecord(evA1, 0);
    k_agg_b16<128, 1><<<gw1, 256>>>(bA16, bB16, CH0, CH1);
    cudaStreamWaitEvent(s1, evA1, 0);
    k_gemm_bf16<1, 1><<<dim3(GT0, 2), 256, SMEM_GEMM, s1>>>(bB16, WTc0, bC16, CH0, 128, 256, sin, bc0, sout);
    k_gemm_bf16<1, 1><<<dim3(GT1, 2), 256, SMEM_GEMM>>>(bB16 + (size_t)CH0 * 128, WTc0,
                                                        bC16 + (size_t)CH0 * 256, CH1, 128, 256,
                                                        sin + CH0, bc0, sout + CH0);
    cudaEventRecord(evG1, s1);
    cudaStreamWaitEvent(0, evG1, 0);

    // ---- conv2 + conv3 gemm ----
    k_agg_b16<256, 1><<<gw0, 256>>>(bC16, bB16, 0, CH0);
    cudaEventRecord(evA2, 0);
    k_agg_b16<256, 1><<<gw1, 256>>>(bC16, bB16, CH0, CH1);
    cudaStreamWaitEvent(s1, evA2, 0);
    k_gemm_bf16<1, 1><<<dim3(GT0, 2), 256, SMEM_GEMM, s1>>>(bB16, WTc1, bA16, CH0, 256, 256, sin, bc1, sout);
    k_gemm_bf16<0, 1><<<dim3(GT0, 1), 256, SMEM_GEMM, s1>>>(bA16, WTc2, bB16, CH0, 256, 128, nullptr, nullptr, nullptr);
    cudaEventRecord(evG3, s1);
    k_gemm_bf16<1, 1><<<dim3(GT1, 2), 256, SMEM_GEMM>>>(bB16 + (size_t)CH0 * 256, WTc1,
                                                        bA16 + (size_t)CH0 * 256, CH1, 256, 256,
                                                        sin + CH0, bc1, sout + CH0);
    k_gemm_bf16<0, 1><<<dim3(GT1, 1), 256, SMEM_GEMM>>>(bA16 + (size_t)CH0 * 256, WTc2,
                                                        bB16 + (size_t)CH0 * 128, CH1, 256, 128, nullptr, nullptr, nullptr);
    cudaStreamWaitEvent(0, evG3, 0);

    // ---- conv3 agg+softmax; MLP dual-chain ----
    k_agg_smax128<<<gw0, 256>>>(bB16, out, bC16, sin, bc2, 0, CH0);
    cudaEventRecord(evS0, 0);
    k_agg_smax128<<<gw1, 256>>>(bB16, out, bC16, sin, bc2, CH0, CH1);

    cudaStreamWaitEvent(s1, evS0, 0);
    k_gemm_bf16<1, 1><<<dim3(GT0, 2), 256, SMEM_GEMM, s1>>>(bC16, WTr0, bA16, CH0, 128, 256, nullptr, br0, nullptr);
    k_gemm_bf16<1, 1><<<dim3(GT0, 2), 256, SMEM_GEMM, s1>>>(bA16, WTr1, t116, CH0, 256, 256, nullptr, br1, nullptr);
    k_gemm_bf16<2, 0><<<dim3(GT0, 1), 256, SMEM_GEMM, s1>>>(t116, WTr2, out + (size_t)M * 128, CH0, 256, 128, nullptr, br2, nullptr);
    cudaEventRecord(evR0, s1);

    k_gemm_bf16<1, 1><<<dim3(GT1, 2), 256, SMEM_GEMM>>>(bC16 + (size_t)CH0 * 128, WTr0,
                                                        bA16 + (size_t)CH0 * 256, CH1, 128, 256, nullptr, br0, nullptr);
    k_gemm_bf16<1, 1><<<dim3(GT1, 2), 256, SMEM_GEMM>>>(bA16 + (size_t)CH0 * 256, WTr1,
                                                        t116 + (size_t)CH0 * 256, CH1, 256, 256, nullptr, br1, nullptr);
    k_gemm_bf16<2, 0><<<dim3(GT1, 1), 256, SMEM_GEMM>>>(t116 + (size_t)CH0 * 256, WTr2,
                                                        out + (size_t)M * 128 + (size_t)CH0 * 128, CH1, 256, 128, nullptr, br2, nullptr);
    cudaStreamWaitEvent(0, evR0, 0);
}